// round 11
// baseline (speedup 1.0000x reference)
#include <cuda_runtime.h>
#include <cuda_fp16.h>
#include <math.h>
#include <stdint.h>

#define B_  4
#define S_  1024
#define D_  768
#define H_  12
#define L_  6
#define DF_ 3072
#define DH_ 64
#define NT_ (B_*S_)        // 4096
#define D3_ (3*D_)         // 2304

// ---------------- scratch (static device globals) ----------------------------
static __device__ float g_h[NT_*D_];
static __device__ __half g_ah[NT_*D_],  g_al[NT_*D_];
static __device__ __half g_mh[NT_*DF_], g_ml[NT_*DF_];
static __device__ __half g_oh[NT_*D_],  g_ol[NT_*D_];
static __device__ __half g_qh[NT_*D_],  g_ql[NT_*D_];
static __device__ __half g_kh[NT_*D_];
static __device__ __half g_vh[NT_*D_];
static __device__ __half t_attn_h[(size_t)L_*D3_*D_];
static __device__ __half t_proj_h[(size_t)L_*D_*D_];
static __device__ __half t_fc_h[(size_t)L_*DF_*D_];
static __device__ __half t_fc2_h[(size_t)L_*D_*DF_];

// ---------------- helpers ----------------------------------------------------
__device__ __forceinline__ uint32_t smem_u32(const void* p) {
    uint32_t a;
    asm("{ .reg .u64 t; cvta.to.shared.u64 t, %1; cvt.u32.u64 %0, t; }" : "=r"(a) : "l"(p));
    return a;
}
__device__ __forceinline__ float gelu_f(float x) {
    const float c = 0.7978845608028654f;
    return 0.5f * x * (1.0f + tanhf(c * (x + 0.044715f * x * x * x)));
}
__device__ __forceinline__ void split_h(float v, __half& hi, __half& lo) {
    hi = __float2half_rn(v);
    lo = __float2half_rn(v - __half2float(hi));
}
__device__ __forceinline__ uint32_t pack2h(float x, float y) {
    __half2 p; p.x = __float2half_rn(x); p.y = __float2half_rn(y);
    return *(uint32_t*)&p;
}
__device__ __forceinline__ void pack_split_h(float x, float y, uint32_t& hp, uint32_t& lp) {
    __half hx, lx, hy, ly;
    split_h(x, hx, lx); split_h(y, hy, ly);
    __half2 h2; h2.x = hx; h2.y = hy;
    __half2 l2; l2.x = lx; l2.y = ly;
    hp = *(uint32_t*)&h2; lp = *(uint32_t*)&l2;
}
__device__ __forceinline__ float warp_sum(float v) {
    #pragma unroll
    for (int o = 16; o > 0; o >>= 1) v += __shfl_xor_sync(0xffffffffu, v, o);
    return v;
}

#define CP16(dst, src) \
    asm volatile("cp.async.cg.shared.global [%0], [%1], 16;" :: "r"(dst), "l"(src))
#define CP_COMMIT() asm volatile("cp.async.commit_group;")
#define CP_WAIT(n)  asm volatile("cp.async.wait_group %0;" :: "n"(n))

#define LDSM_X4(r0, r1, r2, r3, a) \
    asm volatile("ldmatrix.sync.aligned.m8n8.x4.shared.b16 {%0,%1,%2,%3}, [%4];" \
                 : "=r"(r0), "=r"(r1), "=r"(r2), "=r"(r3) : "r"(a))
#define LDSM_X2(r0, r1, a) \
    asm volatile("ldmatrix.sync.aligned.m8n8.x2.shared.b16 {%0,%1}, [%2];" \
                 : "=r"(r0), "=r"(r1) : "r"(a))
#define LDSM_X2_T(r0, r1, a) \
    asm volatile("ldmatrix.sync.aligned.m8n8.x2.trans.shared.b16 {%0,%1}, [%2];" \
                 : "=r"(r0), "=r"(r1) : "r"(a))
#define MMA16816(d, a0, a1, a2, a3, b0, b1) \
    asm volatile("mma.sync.aligned.m16n8k16.row.col.f32.f16.f16.f32 " \
                 "{%0,%1,%2,%3},{%4,%5,%6,%7},{%8,%9},{%0,%1,%2,%3};" \
                 : "+f"((d)[0]), "+f"((d)[1]), "+f"((d)[2]), "+f"((d)[3]) \
                 : "r"(a0), "r"(a1), "r"(a2), "r"(a3), "r"(b0), "r"(b1))

// gemm smem: 128 rows x 64 fp16 (128B) padded to 144B; 3 matrices per stage
#define TSTRIDE 144
#define MATBYTES 18432
#define STAGEBYTES 55296
#define SMEM_GEMM (2*STAGEBYTES)

// flash smem: rows of 64 fp16 (128B) padded to 144B
#define FSTR 144
#define QOFF_H 0
#define QOFF_L 9216
#define KOFF   18432
#define VOFF   36864
#define SMEM_FLASH 55296

// ---------------- fused weight transpose + fp16 convert ----------------------
#define TILES_PER_LAYER 6912
__global__ void wsplit_all_kernel(const float* __restrict__ attn_w, const float* __restrict__ proj_w,
                                  const float* __restrict__ fc_w,   const float* __restrict__ fc2_w,
                                  __half* __restrict__ tah, __half* __restrict__ tph,
                                  __half* __restrict__ tfh, __half* __restrict__ t2h) {
    __shared__ float t[32][33];
    int bid = blockIdx.x;
    int l = bid / TILES_PER_LAYER;
    int r = bid % TILES_PER_LAYER;
    const float* W; __half* Oh; int K, N, tile;
    if (r < 1728)      { W = attn_w; Oh = tah; K = D_;  N = D3_; tile = r; }
    else if (r < 2304) { W = proj_w; Oh = tph; K = D_;  N = D_;  tile = r - 1728; }
    else if (r < 4608) { W = fc_w;   Oh = tfh; K = D_;  N = DF_; tile = r - 2304; }
    else               { W = fc2_w;  Oh = t2h; K = DF_; N = D_;  tile = r - 4608; }
    int nx = N >> 5;
    int n0 = (tile % nx) << 5, k0 = (tile / nx) << 5;
    const float* Wl = W + (size_t)l * K * N;
    __half* OhL = Oh + (size_t)l * K * N;
    int tx = threadIdx.x, ty = threadIdx.y;    // (32,8)
    for (int i = ty; i < 32; i += 8)
        t[i][tx] = Wl[(size_t)(k0 + i) * N + n0 + tx];
    __syncthreads();
    for (int i = ty; i < 32; i += 8)
        OhL[(size_t)(n0 + i) * K + k0 + tx] = __float2half_rn(t[tx][i]);
}

// ---------------- warp-per-row layernorms -------------------------------------
#define LNROWS 8
__global__ void embed_ln_kernel(const int* __restrict__ ids, const int* __restrict__ rfi,
                                const float* __restrict__ wte, const float* __restrict__ wte_rf,
                                const float* __restrict__ wpe,
                                const float* __restrict__ g, const float* __restrict__ b,
                                float* __restrict__ h,
                                __half* __restrict__ yh, __half* __restrict__ yl) {
    int w = threadIdx.x >> 5, lane = threadIdx.x & 31;
    int row = blockIdx.x * LNROWS + w;
    int s = row & (S_ - 1);
    const float* e1 = wte    + (size_t)ids[row] * D_;
    const float* e2 = wte_rf + (size_t)rfi[row] * D_;
    const float* e3 = wpe    + (size_t)s * D_;
    float* hr = h + (size_t)row * D_;
    float v[24];
    float sum = 0.f;
    #pragma unroll
    for (int i = 0; i < 24; i++) {
        int c = lane + (i << 5);
        float x = e1[c] + e2[c] + e3[c];
        hr[c] = x;
        v[i] = x; sum += x;
    }
    sum = warp_sum(sum);
    float mu = sum * (1.0f / D_);
    float q = 0.f;
    #pragma unroll
    for (int i = 0; i < 24; i++) { v[i] -= mu; q += v[i] * v[i]; }
    q = warp_sum(q);
    float inv = rsqrtf(q * (1.0f / D_) + 1e-5f);
    size_t base = (size_t)row * D_;
    #pragma unroll
    for (int i = 0; i < 24; i++) {
        int c = lane + (i << 5);
        float r = v[i] * inv * g[c] + b[c];
        __half hi, lo; split_h(r, hi, lo);
        yh[base + c] = hi; yl[base + c] = lo;
    }
}

template<bool HF>
__global__ void ln_kernel(const float* __restrict__ x, const float* __restrict__ g,
                          const float* __restrict__ b, float* __restrict__ y,
                          __half* __restrict__ yh, __half* __restrict__ yl) {
    int w = threadIdx.x >> 5, lane = threadIdx.x & 31;
    int row = blockIdx.x * LNROWS + w;
    const float* xr = x + (size_t)row * D_;
    float v[24];
    float sum = 0.f;
    #pragma unroll
    for (int i = 0; i < 24; i++) { v[i] = xr[lane + (i << 5)]; sum += v[i]; }
    sum = warp_sum(sum);
    float mu = sum * (1.0f / D_);
    float q = 0.f;
    #pragma unroll
    for (int i = 0; i < 24; i++) { v[i] -= mu; q += v[i] * v[i]; }
    q = warp_sum(q);
    float inv = rsqrtf(q * (1.0f / D_) + 1e-5f);
    size_t base = (size_t)row * D_;
    #pragma unroll
    for (int i = 0; i < 24; i++) {
        int c = lane + (i << 5);
        float r = v[i] * inv * g[c] + b[c];
        if (HF) {
            __half hi, lo; split_h(r, hi, lo);
            yh[base + c] = hi; yl[base + c] = lo;
        } else {
            y[base + c] = r;
        }
    }
}

// ---------------- mma.sync GEMM (fp16 2-pass, K-chunk 64) ---------------------
template<int EPI>
__global__ void __launch_bounds__(256, 2)
gemm_mma(const __half* __restrict__ Ah, const __half* __restrict__ Al,
         const __half* __restrict__ Bh,
         const float* __restrict__ bias, const float* __restrict__ resid,
         float* __restrict__ Cf, __half* __restrict__ Ch, __half* __restrict__ Cl,
         __half* __restrict__ Qh_, __half* __restrict__ Ql_,
         __half* __restrict__ Kh_, __half* __restrict__ Vh_,
         int M, int N, int K) {
    extern __shared__ char smem[];
    uint32_t sbase = smem_u32(smem);
    int tid = threadIdx.x;
    int wid = tid >> 5, lane = tid & 31;
    int wm = wid >> 2, wn = wid & 3;
    int m0 = blockIdx.y << 7, n0 = blockIdx.x << 7;
    int ldb = K * 2;

    const char* srcs[3];
    srcs[0] = (const char*)(Ah + (size_t)m0 * K);
    srcs[1] = (const char*)(Al + (size_t)m0 * K);
    srcs[2] = (const char*)(Bh + (size_t)n0 * K);

    float acc[4][4][4] = {};
    int nk = K >> 6;

#define PREFETCH(c, s)                                                        \
    {                                                                         \
        size_t ko = (size_t)(c) << 7;                                         \
        uint32_t stb = sbase + (s) * STAGEBYTES;                              \
        _Pragma("unroll")                                                     \
        for (int j = 0; j < 12; j++) {                                        \
            int q = tid + j * 256;                                            \
            int mat = q >> 10, w = q & 1023, row = w >> 3, cc = w & 7;        \
            uint32_t dst = stb + mat * MATBYTES + row * TSTRIDE + cc * 16;    \
            const char* sp = srcs[mat] + (size_t)row * ldb + ko + cc * 16;    \
            CP16(dst, sp);                                                    \
        }                                                                     \
        CP_COMMIT();                                                          \
    }

    PREFETCH(0, 0);

    int aRow = wm * 64 + (lane & 7) + ((lane >> 3) & 1) * 8;
    uint32_t aKoff = ((lane >> 4) & 1) * 16;
    int lb = lane & 15;
    int bRow = wn * 32 + (lb & 7);
    uint32_t bKoff = ((lb >> 3) & 1) * 16;

    for (int c = 0; c < nk; c++) {
        int s = c & 1;
        if (c + 1 < nk) PREFETCH(c + 1, s ^ 1);
        if (c + 1 < nk) { CP_WAIT(1); } else { CP_WAIT(0); }
        __syncthreads();

        uint32_t stb = sbase + s * STAGEBYTES;
        #pragma unroll
        for (int kk = 0; kk < 4; kk++) {
            uint32_t bh[4][2];
            #pragma unroll
            for (int nj = 0; nj < 4; nj++) {
                uint32_t addr = stb + 2 * MATBYTES + (bRow + nj * 8) * TSTRIDE + kk * 32 + bKoff;
                LDSM_X2(bh[nj][0], bh[nj][1], addr);
            }
            uint32_t af[4][4];
            #pragma unroll
            for (int mi = 0; mi < 4; mi++) {
                uint32_t addr = stb + (aRow + mi * 16) * TSTRIDE + kk * 32 + aKoff;
                LDSM_X4(af[mi][0], af[mi][1], af[mi][2], af[mi][3], addr);
            }
            #pragma unroll
            for (int mi = 0; mi < 4; mi++)
                #pragma unroll
                for (int nj = 0; nj < 4; nj++)
                    MMA16816(acc[mi][nj], af[mi][0], af[mi][1], af[mi][2], af[mi][3],
                             bh[nj][0], bh[nj][1]);
            #pragma unroll
            for (int mi = 0; mi < 4; mi++) {
                uint32_t addr = stb + MATBYTES + (aRow + mi * 16) * TSTRIDE + kk * 32 + aKoff;
                LDSM_X4(af[mi][0], af[mi][1], af[mi][2], af[mi][3], addr);
            }
            #pragma unroll
            for (int mi = 0; mi < 4; mi++)
                #pragma unroll
                for (int nj = 0; nj < 4; nj++)
                    MMA16816(acc[mi][nj], af[mi][0], af[mi][1], af[mi][2], af[mi][3],
                             bh[nj][0], bh[nj][1]);
        }
        __syncthreads();
    }

    int rbase = m0 + wm * 64 + (lane >> 2);
    int cbase = n0 + wn * 32 + (lane & 3) * 2;
    #pragma unroll
    for (int mi = 0; mi < 4; mi++) {
        #pragma unroll
        for (int nj = 0; nj < 4; nj++) {
            int r = rbase + mi * 16;
            int col = cbase + nj * 8;
            float b0 = bias[col], b1 = bias[col + 1];
            float v00 = acc[mi][nj][0] + b0, v01 = acc[mi][nj][1] + b1;
            float v10 = acc[mi][nj][2] + b0, v11 = acc[mi][nj][3] + b1;
            size_t i0 = (size_t)r * N + col;
            size_t i1 = (size_t)(r + 8) * N + col;
            if (EPI == 0) {
                *(float2*)&Cf[i0] = make_float2(v00, v01);
                *(float2*)&Cf[i1] = make_float2(v10, v11);
            } else if (EPI == 1) {
                float2 r0 = *(const float2*)&resid[i0];
                float2 r1 = *(const float2*)&resid[i1];
                *(float2*)&Cf[i0] = make_float2(v00 + r0.x, v01 + r0.y);
                *(float2*)&Cf[i1] = make_float2(v10 + r1.x, v11 + r1.y);
            } else if (EPI == 2) {
                v00 = gelu_f(v00); v01 = gelu_f(v01);
                v10 = gelu_f(v10); v11 = gelu_f(v11);
                uint32_t hp, lp;
                pack_split_h(v00, v01, hp, lp);
                *(uint32_t*)&Ch[i0] = hp; *(uint32_t*)&Cl[i0] = lp;
                pack_split_h(v10, v11, hp, lp);
                *(uint32_t*)&Ch[i1] = hp; *(uint32_t*)&Cl[i1] = lp;
            } else {
                int which = col / D_;
                int hh = (col % D_) / DH_;
                int dd = col % DH_;
                int bi = r >> 10, si = r & 1023;
                size_t j0 = (((size_t)(bi * H_ + hh)) * S_ + si) * DH_ + dd;
                size_t j1 = j0 + 8 * DH_;
                if (which == 0) {
                    uint32_t hp, lp;
                    pack_split_h(v00, v01, hp, lp);
                    *(uint32_t*)&Qh_[j0] = hp; *(uint32_t*)&Ql_[j0] = lp;
                    pack_split_h(v10, v11, hp, lp);
                    *(uint32_t*)&Qh_[j1] = hp; *(uint32_t*)&Ql_[j1] = lp;
                } else {
                    __half* d_ = which == 1 ? Kh_ : Vh_;
                    *(uint32_t*)&d_[j0] = pack2h(v00, v01);
                    *(uint32_t*)&d_[j1] = pack2h(v10, v11);
                }
            }
        }
    }
#undef PREFETCH
}

// ---------------- fused flash attention (64-row Q, interleaved exp+PV) --------
// grid (S/64, B*H), 128 threads. Packed-P lives only 8 regs at a time ->
// lower register pressure -> 3 CTAs/SM.
__global__ void __launch_bounds__(128, 3)
flash_kernel(const __half* __restrict__ qh, const __half* __restrict__ ql,
             const __half* __restrict__ kh, const __half* __restrict__ vh,
             __half* __restrict__ oh, __half* __restrict__ ol) {
    extern __shared__ char fsm[];
    uint32_t sb = smem_u32(fsm);
    int bh = blockIdx.y;
    int q0 = (gridDim.x - 1 - blockIdx.x) << 6;   // long CTAs first
    int tid = threadIdx.x, wid = tid >> 5, lane = tid & 31;

    {   // Q tile load (64 rows x 128B), hi+lo
        const char* srcH = (const char*)(qh + ((size_t)bh * S_ + q0) * DH_);
        const char* srcL = (const char*)(ql + ((size_t)bh * S_ + q0) * DH_);
        #pragma unroll
        for (int i = tid; i < 512; i += 128) {
            int r = i >> 3, c = (i & 7) << 4;
            CP16(sb + QOFF_H + r * FSTR + c, srcH + r * 128 + c);
            CP16(sb + QOFF_L + r * FSTR + c, srcL + r * 128 + c);
        }
        CP_COMMIT();
    }

    float m0 = -1e30f, m1 = -1e30f, l0 = 0.f, l1 = 0.f;
    float oacc[8][4];
    #pragma unroll
    for (int d = 0; d < 8; d++)
        oacc[d][0] = oacc[d][1] = oacc[d][2] = oacc[d][3] = 0.f;

    int rA = q0 + wid * 16 + (lane >> 2);
    int nj = (q0 >> 7) + 1;

    uint32_t aAddrBase = sb + (wid * 16 + (lane & 15)) * FSTR + (((lane >> 4) & 1) << 4);
    uint32_t bRowOff = (uint32_t)((lane & 7) * FSTR) + (((lane >> 3) & 1) << 4);

    for (int j = 0; j < nj; j++) {
        __syncthreads();
        {   // K/V tile load (128 rows x 128B)
            const char* kH = (const char*)(kh + ((size_t)bh * S_ + (j << 7)) * DH_);
            const char* vH = (const char*)(vh + ((size_t)bh * S_ + (j << 7)) * DH_);
            #pragma unroll
            for (int i = tid; i < 1024; i += 128) {
                int r = i >> 3, c = (i & 7) << 4;
                uint32_t so = r * FSTR + c;
                size_t go = (size_t)r * 128 + c;
                CP16(sb + KOFF + so, kH + go);
                CP16(sb + VOFF + so, vH + go);
            }
            CP_COMMIT();
            CP_WAIT(0);
        }
        __syncthreads();

        float sf[16][4];
        #pragma unroll
        for (int nt = 0; nt < 16; nt++)
            sf[nt][0] = sf[nt][1] = sf[nt][2] = sf[nt][3] = 0.f;

        #pragma unroll
        for (int kc = 0; kc < 4; kc++) {
            uint32_t qa = aAddrBase + kc * 32;
            uint32_t q_h0,q_h1,q_h2,q_h3, q_l0,q_l1,q_l2,q_l3;
            LDSM_X4(q_h0,q_h1,q_h2,q_h3, qa + QOFF_H);
            LDSM_X4(q_l0,q_l1,q_l2,q_l3, qa + QOFF_L);
            #pragma unroll
            for (int nt = 0; nt < 16; nt++) {
                uint32_t ka = sb + KOFF + nt * 8 * FSTR + bRowOff + kc * 32;
                uint32_t k_h0,k_h1;
                LDSM_X2(k_h0,k_h1, ka);
                MMA16816(sf[nt], q_h0,q_h1,q_h2,q_h3, k_h0,k_h1);
                MMA16816(sf[nt], q_l0,q_l1,q_l2,q_l3, k_h0,k_h1);
            }
        }

        int cb = (j << 7) + (lane & 3) * 2;
        float mx0 = -1e30f, mx1 = -1e30f;
        #pragma unroll
        for (int nt = 0; nt < 16; nt++) {
            int c0 = cb + nt * 8;
            sf[nt][0] = (c0     <= rA)     ? sf[nt][0] * 0.125f : -1e30f;
            sf[nt][1] = (c0 + 1 <= rA)     ? sf[nt][1] * 0.125f : -1e30f;
            sf[nt][2] = (c0     <= rA + 8) ? sf[nt][2] * 0.125f : -1e30f;
            sf[nt][3] = (c0 + 1 <= rA + 8) ? sf[nt][3] * 0.125f : -1e30f;
            mx0 = fmaxf(mx0, fmaxf(sf[nt][0], sf[nt][1]));
            mx1 = fmaxf(mx1, fmaxf(sf[nt][2], sf[nt][3]));
        }
        mx0 = fmaxf(mx0, __shfl_xor_sync(0xffffffffu, mx0, 1));
        mx0 = fmaxf(mx0, __shfl_xor_sync(0xffffffffu, mx0, 2));
        mx1 = fmaxf(mx1, __shfl_xor_sync(0xffffffffu, mx1, 1));
        mx1 = fmaxf(mx1, __shfl_xor_sync(0xffffffffu, mx1, 2));
        float mn0 = fmaxf(m0, mx0), mn1 = fmaxf(m1, mx1);
        float sc0 = expf(m0 - mn0), sc1 = expf(m1 - mn1);
        m0 = mn0; m1 = mn1;
        l0 *= sc0; l1 *= sc1;
        #pragma unroll
        for (int d = 0; d < 8; d++) {
            oacc[d][0] *= sc0; oacc[d][1] *= sc0;
            oacc[d][2] *= sc1; oacc[d][3] *= sc1;
        }

        // --- interleaved: exp/pack nt-pair (2kc,2kc+1) then immediately PV ---
        float s0 = 0.f, s1 = 0.f;
        #pragma unroll
        for (int kc = 0; kc < 8; kc++) {
            uint32_t pA0, pA1, pB0, pB1, lA0, lA1, lB0, lB1;
            {
                int nt = 2 * kc;
                float p0 = expf(sf[nt][0] - m0), p1 = expf(sf[nt][1] - m0);
                float p2 = expf(sf[nt][2] - m1), p3 = expf(sf[nt][3] - m1);
                s0 += p0 + p1; s1 += p2 + p3;
                pack_split_h(p0, p1, pA0, lA0);
                pack_split_h(p2, p3, pA1, lA1);
            }
            {
                int nt = 2 * kc + 1;
                float p0 = expf(sf[nt][0] - m0), p1 = expf(sf[nt][1] - m0);
                float p2 = expf(sf[nt][2] - m1), p3 = expf(sf[nt][3] - m1);
                s0 += p0 + p1; s1 += p2 + p3;
                pack_split_h(p0, p1, pB0, lB0);
                pack_split_h(p2, p3, pB1, lB1);
            }
            uint32_t va = sb + VOFF + (kc * 16 + (lane & 15)) * FSTR;
            #pragma unroll
            for (int dt = 0; dt < 8; dt++) {
                uint32_t v_h0, v_h1;
                LDSM_X2_T(v_h0, v_h1, va + dt * 16);
                MMA16816(oacc[dt], pA0, pA1, pB0, pB1, v_h0, v_h1);
                MMA16816(oacc[dt], lA0, lA1, lB0, lB1, v_h0, v_h1);
            }
        }
        s0 += __shfl_xor_sync(0xffffffffu, s0, 1);
        s0 += __shfl_xor_sync(0xffffffffu, s0, 2);
        s1 += __shfl_xor_sync(0xffffffffu, s1, 1);
        s1 += __shfl_xor_sync(0xffffffffu, s1, 2);
        l0 += s0; l1 += s1;
    }

    float inv0 = 1.f / l0, inv1 = 1.f / l1;
    int bb = bh / H_, hH = bh % H_;
    size_t baseA = ((size_t)bb * S_ + rA) * D_ + hH * DH_;
    size_t baseB = baseA + 8 * D_;
    #pragma unroll
    for (int dt = 0; dt < 8; dt++) {
        int c = dt * 8 + (lane & 3) * 2;
        uint32_t hp, lp;
        pack_split_h(oacc[dt][0] * inv0, oacc[dt][1] * inv0, hp, lp);
        *(uint32_t*)&oh[baseA + c] = hp;
        *(uint32_t*)&ol[baseA + c] = lp;
        pack_split_h(oacc[dt][2] * inv1, oacc[dt][3] * inv1, hp, lp);
        *(uint32_t*)&oh[baseB + c] = hp;
        *(uint32_t*)&ol[baseB + c] = lp;
    }
}

// ---------------- host orchestration -----------------------------------------
extern "C" void kernel_launch(void* const* d_in, const int* in_sizes, int n_in,
                              void* d_out, int out_size) {
    const int*   ids    = (const int*)d_in[0];
    const int*   rfi    = (const int*)d_in[1];
    const float* wte    = (const float*)d_in[2];
    const float* wte_rf = (const float*)d_in[3];
    const float* wpe    = (const float*)d_in[4];
    const float* ln1_g  = (const float*)d_in[5];
    const float* ln1_b  = (const float*)d_in[6];
    const float* attn_w = (const float*)d_in[7];
    const float* attn_b = (const float*)d_in[8];
    const float* proj_w = (const float*)d_in[9];
    const float* proj_b = (const float*)d_in[10];
    const float* ln2_g  = (const float*)d_in[11];
    const float* ln2_b  = (const float*)d_in[12];
    const float* fc_w   = (const float*)d_in[13];
    const float* fc_b   = (const float*)d_in[14];
    const float* fc2_w  = (const float*)d_in[15];
    const float* fc2_b  = (const float*)d_in[16];
    const float* lnf_g  = (const float*)d_in[17];
    const float* lnf_b  = (const float*)d_in[18];
    float* out = (float*)d_out;

    float *h;
    __half *ah, *al, *mh, *ml, *oh, *ol;
    __half *qh, *ql, *kh, *vh;
    __half *tah, *tph, *tfh, *t2h;
    cudaGetSymbolAddress((void**)&h,   g_h);
    cudaGetSymbolAddress((void**)&ah,  g_ah);  cudaGetSymbolAddress((void**)&al,  g_al);
    cudaGetSymbolAddress((void**)&mh,  g_mh);  cudaGetSymbolAddress((void**)&ml,  g_ml);
    cudaGetSymbolAddress((void**)&oh,  g_oh);  cudaGetSymbolAddress((void**)&ol,  g_ol);
    cudaGetSymbolAddress((void**)&qh,  g_qh);  cudaGetSymbolAddress((void**)&ql,  g_ql);
    cudaGetSymbolAddress((void**)&kh,  g_kh);  cudaGetSymbolAddress((void**)&vh,  g_vh);
    cudaGetSymbolAddress((void**)&tah, t_attn_h);
    cudaGetSymbolAddress((void**)&tph, t_proj_h);
    cudaGetSymbolAddress((void**)&tfh, t_fc_h);
    cudaGetSymbolAddress((void**)&t2h, t_fc2_h);

    cudaFuncSetAttribute(gemm_mma<1>, cudaFuncAttributeMaxDynamicSharedMemorySize, SMEM_GEMM);
    cudaFuncSetAttribute(gemm_mma<2>, cudaFuncAttributeMaxDynamicSharedMemorySize, SMEM_GEMM);
    cudaFuncSetAttribute(gemm_mma<3>, cudaFuncAttributeMaxDynamicSharedMemorySize, SMEM_GEMM);
    cudaFuncSetAttribute(flash_kernel, cudaFuncAttributeMaxDynamicSharedMemorySize, SMEM_FLASH);

    wsplit_all_kernel<<<TILES_PER_LAYER * L_, dim3(32, 8)>>>(
        attn_w, proj_w, fc_w, fc2_w, tah, tph, tfh, t2h);
    embed_ln_kernel<<<NT_/LNROWS, 256>>>(ids, rfi, wte, wte_rf, wpe, ln1_g, ln1_b, h, ah, al);

    for (int l = 0; l < L_; l++) {
        if (l > 0)
            ln_kernel<true><<<NT_/LNROWS, 256>>>(h, ln1_g + l * D_, ln1_b + l * D_, nullptr, ah, al);
        gemm_mma<3><<<dim3(D3_/128, NT_/128), 256, SMEM_GEMM>>>(
            ah, al, tah + (size_t)l * D3_ * D_,
            attn_b + l * D3_, nullptr, nullptr, nullptr, nullptr,
            qh, ql, kh, vh, NT_, D3_, D_);
        flash_kernel<<<dim3(S_/64, B_*H_), 128, SMEM_FLASH>>>(qh, ql, kh, vh, oh, ol);
        gemm_mma<1><<<dim3(D_/128, NT_/128), 256, SMEM_GEMM>>>(
            oh, ol, tph + (size_t)l * D_ * D_,
            proj_b + l * D_, h, h, nullptr, nullptr,
            nullptr, nullptr, nullptr, nullptr, NT_, D_, D_);
        ln_kernel<true><<<NT_/LNROWS, 256>>>(h, ln2_g + l * D_, ln2_b + l * D_, nullptr, ah, al);
        gemm_mma<2><<<dim3(DF_/128, NT_/128), 256, SMEM_GEMM>>>(
            ah, al, tfh + (size_t)l * DF_ * D_,
            fc_b + l * DF_, nullptr, nullptr, mh, ml,
            nullptr, nullptr, nullptr, nullptr, NT_, DF_, D_);
        gemm_mma<1><<<dim3(D_/128, NT_/128), 256, SMEM_GEMM>>>(
            mh, ml, t2h + (size_t)l * D_ * DF_,
            fc2_b + l * D_, h, h, nullptr, nullptr,
            nullptr, nullptr, nullptr, nullptr, NT_, D_, DF_);
    }
    ln_kernel<false><<<NT_/LNROWS, 256>>>(h, lnf_g, lnf_b, out, nullptr, nullptr);
}

// round 12
// speedup vs baseline: 1.0921x; 1.0921x over previous
#include <cuda_runtime.h>
#include <cuda_fp16.h>
#include <math.h>
#include <stdint.h>

#define B_  4
#define S_  1024
#define D_  768
#define H_  12
#define L_  6
#define DF_ 3072
#define DH_ 64
#define NT_ (B_*S_)        // 4096
#define D3_ (3*D_)         // 2304

// ---------------- scratch (static device globals) ----------------------------
static __device__ float g_h[NT_*D_];
static __device__ float g_t[(size_t)2*NT_*D_];     // split-K partials
static __device__ __half g_ah[NT_*D_],  g_al[NT_*D_];
static __device__ __half g_mh[NT_*DF_], g_ml[NT_*DF_];
static __device__ __half g_oh[NT_*D_],  g_ol[NT_*D_];
static __device__ __half g_qh[NT_*D_],  g_ql[NT_*D_];
static __device__ __half g_kh[NT_*D_];
static __device__ __half g_vh[NT_*D_];
static __device__ __half t_attn_h[(size_t)L_*D3_*D_];
static __device__ __half t_proj_h[(size_t)L_*D_*D_];
static __device__ __half t_fc_h[(size_t)L_*DF_*D_];
static __device__ __half t_fc2_h[(size_t)L_*D_*DF_];

// ---------------- helpers ----------------------------------------------------
__device__ __forceinline__ uint32_t smem_u32(const void* p) {
    uint32_t a;
    asm("{ .reg .u64 t; cvta.to.shared.u64 t, %1; cvt.u32.u64 %0, t; }" : "=r"(a) : "l"(p));
    return a;
}
__device__ __forceinline__ float gelu_f(float x) {
    const float c = 0.7978845608028654f;
    return 0.5f * x * (1.0f + tanhf(c * (x + 0.044715f * x * x * x)));
}
__device__ __forceinline__ void split_h(float v, __half& hi, __half& lo) {
    hi = __float2half_rn(v);
    lo = __float2half_rn(v - __half2float(hi));
}
__device__ __forceinline__ uint32_t pack2h(float x, float y) {
    __half2 p; p.x = __float2half_rn(x); p.y = __float2half_rn(y);
    return *(uint32_t*)&p;
}
__device__ __forceinline__ void pack_split_h(float x, float y, uint32_t& hp, uint32_t& lp) {
    __half hx, lx, hy, ly;
    split_h(x, hx, lx); split_h(y, hy, ly);
    __half2 h2; h2.x = hx; h2.y = hy;
    __half2 l2; l2.x = lx; l2.y = ly;
    hp = *(uint32_t*)&h2; lp = *(uint32_t*)&l2;
}
__device__ __forceinline__ float warp_sum(float v) {
    #pragma unroll
    for (int o = 16; o > 0; o >>= 1) v += __shfl_xor_sync(0xffffffffu, v, o);
    return v;
}

#define CP16(dst, src) \
    asm volatile("cp.async.cg.shared.global [%0], [%1], 16;" :: "r"(dst), "l"(src))
#define CP_COMMIT() asm volatile("cp.async.commit_group;")
#define CP_WAIT(n)  asm volatile("cp.async.wait_group %0;" :: "n"(n))

#define LDSM_X4(r0, r1, r2, r3, a) \
    asm volatile("ldmatrix.sync.aligned.m8n8.x4.shared.b16 {%0,%1,%2,%3}, [%4];" \
                 : "=r"(r0), "=r"(r1), "=r"(r2), "=r"(r3) : "r"(a))
#define LDSM_X2(r0, r1, a) \
    asm volatile("ldmatrix.sync.aligned.m8n8.x2.shared.b16 {%0,%1}, [%2];" \
                 : "=r"(r0), "=r"(r1) : "r"(a))
#define LDSM_X2_T(r0, r1, a) \
    asm volatile("ldmatrix.sync.aligned.m8n8.x2.trans.shared.b16 {%0,%1}, [%2];" \
                 : "=r"(r0), "=r"(r1) : "r"(a))
#define MMA16816(d, a0, a1, a2, a3, b0, b1) \
    asm volatile("mma.sync.aligned.m16n8k16.row.col.f32.f16.f16.f32 " \
                 "{%0,%1,%2,%3},{%4,%5,%6,%7},{%8,%9},{%0,%1,%2,%3};" \
                 : "+f"((d)[0]), "+f"((d)[1]), "+f"((d)[2]), "+f"((d)[3]) \
                 : "r"(a0), "r"(a1), "r"(a2), "r"(a3), "r"(b0), "r"(b1))

// gemm smem: 128 rows x 64 fp16 (128B) padded to 144B; 3 matrices per stage
#define TSTRIDE 144
#define MATBYTES 18432
#define STAGEBYTES 55296
#define SMEM_GEMM (2*STAGEBYTES)

// flash smem: rows of 64 fp16 (128B) padded to 144B
#define FSTR 144
#define QOFF_H 0
#define QOFF_L 9216
#define KOFF   18432
#define VOFF   36864
#define SMEM_FLASH 55296

// ---------------- fused weight transpose + fp16 convert ----------------------
#define TILES_PER_LAYER 6912
__global__ void wsplit_all_kernel(const float* __restrict__ attn_w, const float* __restrict__ proj_w,
                                  const float* __restrict__ fc_w,   const float* __restrict__ fc2_w,
                                  __half* __restrict__ tah, __half* __restrict__ tph,
                                  __half* __restrict__ tfh, __half* __restrict__ t2h) {
    __shared__ float t[32][33];
    int bid = blockIdx.x;
    int l = bid / TILES_PER_LAYER;
    int r = bid % TILES_PER_LAYER;
    const float* W; __half* Oh; int K, N, tile;
    if (r < 1728)      { W = attn_w; Oh = tah; K = D_;  N = D3_; tile = r; }
    else if (r < 2304) { W = proj_w; Oh = tph; K = D_;  N = D_;  tile = r - 1728; }
    else if (r < 4608) { W = fc_w;   Oh = tfh; K = D_;  N = DF_; tile = r - 2304; }
    else               { W = fc2_w;  Oh = t2h; K = DF_; N = D_;  tile = r - 4608; }
    int nx = N >> 5;
    int n0 = (tile % nx) << 5, k0 = (tile / nx) << 5;
    const float* Wl = W + (size_t)l * K * N;
    __half* OhL = Oh + (size_t)l * K * N;
    int tx = threadIdx.x, ty = threadIdx.y;    // (32,8)
    for (int i = ty; i < 32; i += 8)
        t[i][tx] = Wl[(size_t)(k0 + i) * N + n0 + tx];
    __syncthreads();
    for (int i = ty; i < 32; i += 8)
        OhL[(size_t)(n0 + i) * K + k0 + tx] = __float2half_rn(t[tx][i]);
}

// ---------------- warp-per-row layernorms -------------------------------------
#define LNROWS 8
__global__ void embed_ln_kernel(const int* __restrict__ ids, const int* __restrict__ rfi,
                                const float* __restrict__ wte, const float* __restrict__ wte_rf,
                                const float* __restrict__ wpe,
                                const float* __restrict__ g, const float* __restrict__ b,
                                float* __restrict__ h,
                                __half* __restrict__ yh, __half* __restrict__ yl) {
    int w = threadIdx.x >> 5, lane = threadIdx.x & 31;
    int row = blockIdx.x * LNROWS + w;
    int s = row & (S_ - 1);
    const float* e1 = wte    + (size_t)ids[row] * D_;
    const float* e2 = wte_rf + (size_t)rfi[row] * D_;
    const float* e3 = wpe    + (size_t)s * D_;
    float* hr = h + (size_t)row * D_;
    float v[24];
    float sum = 0.f;
    #pragma unroll
    for (int i = 0; i < 24; i++) {
        int c = lane + (i << 5);
        float x = e1[c] + e2[c] + e3[c];
        hr[c] = x;
        v[i] = x; sum += x;
    }
    sum = warp_sum(sum);
    float mu = sum * (1.0f / D_);
    float q = 0.f;
    #pragma unroll
    for (int i = 0; i < 24; i++) { v[i] -= mu; q += v[i] * v[i]; }
    q = warp_sum(q);
    float inv = rsqrtf(q * (1.0f / D_) + 1e-5f);
    size_t base = (size_t)row * D_;
    #pragma unroll
    for (int i = 0; i < 24; i++) {
        int c = lane + (i << 5);
        float r = v[i] * inv * g[c] + b[c];
        __half hi, lo; split_h(r, hi, lo);
        yh[base + c] = hi; yl[base + c] = lo;
    }
}

// ln_sum: v = x + t0 + t1 + gbias; optionally write h; LN(v) -> (yh,yl) or y.
template<bool HF>
__global__ void ln_sum_kernel(const float* __restrict__ x, const float* __restrict__ t,
                              const float* __restrict__ gb,
                              const float* __restrict__ g, const float* __restrict__ b,
                              float* __restrict__ hout, float* __restrict__ y,
                              __half* __restrict__ yh, __half* __restrict__ yl) {
    int w = threadIdx.x >> 5, lane = threadIdx.x & 31;
    int row = blockIdx.x * LNROWS + w;
    size_t base = (size_t)row * D_;
    const float* t0 = t + base;
    const float* t1 = t + (size_t)NT_ * D_ + base;
    const float* xr = x + base;
    float v[24];
    float sum = 0.f;
    #pragma unroll
    for (int i = 0; i < 24; i++) {
        int c = lane + (i << 5);
        float val = xr[c] + t0[c] + t1[c] + gb[c];
        if (hout) hout[base + c] = val;
        v[i] = val; sum += val;
    }
    sum = warp_sum(sum);
    float mu = sum * (1.0f / D_);
    float q = 0.f;
    #pragma unroll
    for (int i = 0; i < 24; i++) { v[i] -= mu; q += v[i] * v[i]; }
    q = warp_sum(q);
    float inv = rsqrtf(q * (1.0f / D_) + 1e-5f);
    #pragma unroll
    for (int i = 0; i < 24; i++) {
        int c = lane + (i << 5);
        float r = v[i] * inv * g[c] + b[c];
        if (HF) {
            __half hi, lo; split_h(r, hi, lo);
            yh[base + c] = hi; yl[base + c] = lo;
        } else {
            y[base + c] = r;
        }
    }
}

// ---------------- mma.sync GEMM (fp16 2-pass, K-chunk 64) ---------------------
// EPI 2: Ch/Cl = split(gelu(acc+bias)).  EPI 3: head-major Q(hi/lo) K V.
// EPI 4: split-K partial: Cf[z] = acc (raw), z = blockIdx.z, koff = z*K.
template<int EPI>
__global__ void __launch_bounds__(256, 2)
gemm_mma(const __half* __restrict__ Ah, const __half* __restrict__ Al,
         const __half* __restrict__ Bh,
         const float* __restrict__ bias, const float* __restrict__ resid,
         float* __restrict__ Cf, __half* __restrict__ Ch, __half* __restrict__ Cl,
         __half* __restrict__ Qh_, __half* __restrict__ Ql_,
         __half* __restrict__ Kh_, __half* __restrict__ Vh_,
         int M, int N, int K, int Ktot) {
    extern __shared__ char smem[];
    uint32_t sbase = smem_u32(smem);
    int tid = threadIdx.x;
    int wid = tid >> 5, lane = tid & 31;
    int wm = wid >> 2, wn = wid & 3;
    int m0 = blockIdx.y << 7, n0 = blockIdx.x << 7;
    int ldb = Ktot * 2;
    int kz = (EPI == 4) ? blockIdx.z : 0;
    size_t koff0 = (size_t)kz * K;
    if (EPI == 4) Cf += (size_t)kz * ((size_t)M * N);

    const char* srcs[3];
    srcs[0] = (const char*)(Ah + (size_t)m0 * Ktot + koff0);
    srcs[1] = (const char*)(Al + (size_t)m0 * Ktot + koff0);
    srcs[2] = (const char*)(Bh + (size_t)n0 * Ktot + koff0);

    float acc[4][4][4] = {};
    int nk = K >> 6;

#define PREFETCH(c, s)                                                        \
    {                                                                         \
        size_t ko = (size_t)(c) << 7;                                         \
        uint32_t stb = sbase + (s) * STAGEBYTES;                              \
        _Pragma("unroll")                                                     \
        for (int j = 0; j < 12; j++) {                                        \
            int q = tid + j * 256;                                            \
            int mat = q >> 10, w = q & 1023, row = w >> 3, cc = w & 7;        \
            uint32_t dst = stb + mat * MATBYTES + row * TSTRIDE + cc * 16;    \
            const char* sp = srcs[mat] + (size_t)row * ldb + ko + cc * 16;    \
            CP16(dst, sp);                                                    \
        }                                                                     \
        CP_COMMIT();                                                          \
    }

    PREFETCH(0, 0);

    int aRow = wm * 64 + (lane & 7) + ((lane >> 3) & 1) * 8;
    uint32_t aKoff = ((lane >> 4) & 1) * 16;
    int lb = lane & 15;
    int bRow = wn * 32 + (lb & 7);
    uint32_t bKoff = ((lb >> 3) & 1) * 16;

    for (int c = 0; c < nk; c++) {
        int s = c & 1;
        if (c + 1 < nk) PREFETCH(c + 1, s ^ 1);
        if (c + 1 < nk) { CP_WAIT(1); } else { CP_WAIT(0); }
        __syncthreads();

        uint32_t stb = sbase + s * STAGEBYTES;
        #pragma unroll
        for (int kk = 0; kk < 4; kk++) {
            uint32_t bh[4][2];
            #pragma unroll
            for (int nj = 0; nj < 4; nj++) {
                uint32_t addr = stb + 2 * MATBYTES + (bRow + nj * 8) * TSTRIDE + kk * 32 + bKoff;
                LDSM_X2(bh[nj][0], bh[nj][1], addr);
            }
            uint32_t af[4][4];
            #pragma unroll
            for (int mi = 0; mi < 4; mi++) {
                uint32_t addr = stb + (aRow + mi * 16) * TSTRIDE + kk * 32 + aKoff;
                LDSM_X4(af[mi][0], af[mi][1], af[mi][2], af[mi][3], addr);
            }
            #pragma unroll
            for (int mi = 0; mi < 4; mi++)
                #pragma unroll
                for (int nj = 0; nj < 4; nj++)
                    MMA16816(acc[mi][nj], af[mi][0], af[mi][1], af[mi][2], af[mi][3],
                             bh[nj][0], bh[nj][1]);
            #pragma unroll
            for (int mi = 0; mi < 4; mi++) {
                uint32_t addr = stb + MATBYTES + (aRow + mi * 16) * TSTRIDE + kk * 32 + aKoff;
                LDSM_X4(af[mi][0], af[mi][1], af[mi][2], af[mi][3], addr);
            }
            #pragma unroll
            for (int mi = 0; mi < 4; mi++)
                #pragma unroll
                for (int nj = 0; nj < 4; nj++)
                    MMA16816(acc[mi][nj], af[mi][0], af[mi][1], af[mi][2], af[mi][3],
                             bh[nj][0], bh[nj][1]);
        }
        __syncthreads();
    }

    int rbase = m0 + wm * 64 + (lane >> 2);
    int cbase = n0 + wn * 32 + (lane & 3) * 2;
    #pragma unroll
    for (int mi = 0; mi < 4; mi++) {
        #pragma unroll
        for (int nj = 0; nj < 4; nj++) {
            int r = rbase + mi * 16;
            int col = cbase + nj * 8;
            float b0 = (EPI == 4) ? 0.f : bias[col];
            float b1 = (EPI == 4) ? 0.f : bias[col + 1];
            float v00 = acc[mi][nj][0] + b0, v01 = acc[mi][nj][1] + b1;
            float v10 = acc[mi][nj][2] + b0, v11 = acc[mi][nj][3] + b1;
            size_t i0 = (size_t)r * N + col;
            size_t i1 = (size_t)(r + 8) * N + col;
            if (EPI == 4) {
                *(float2*)&Cf[i0] = make_float2(v00, v01);
                *(float2*)&Cf[i1] = make_float2(v10, v11);
            } else if (EPI == 1) {
                float2 r0 = *(const float2*)&resid[i0];
                float2 r1 = *(const float2*)&resid[i1];
                *(float2*)&Cf[i0] = make_float2(v00 + r0.x, v01 + r0.y);
                *(float2*)&Cf[i1] = make_float2(v10 + r1.x, v11 + r1.y);
            } else if (EPI == 2) {
                v00 = gelu_f(v00); v01 = gelu_f(v01);
                v10 = gelu_f(v10); v11 = gelu_f(v11);
                uint32_t hp, lp;
                pack_split_h(v00, v01, hp, lp);
                *(uint32_t*)&Ch[i0] = hp; *(uint32_t*)&Cl[i0] = lp;
                pack_split_h(v10, v11, hp, lp);
                *(uint32_t*)&Ch[i1] = hp; *(uint32_t*)&Cl[i1] = lp;
            } else {
                int which = col / D_;
                int hh = (col % D_) / DH_;
                int dd = col % DH_;
                int bi = r >> 10, si = r & 1023;
                size_t j0 = (((size_t)(bi * H_ + hh)) * S_ + si) * DH_ + dd;
                size_t j1 = j0 + 8 * DH_;
                if (which == 0) {
                    uint32_t hp, lp;
                    pack_split_h(v00, v01, hp, lp);
                    *(uint32_t*)&Qh_[j0] = hp; *(uint32_t*)&Ql_[j0] = lp;
                    pack_split_h(v10, v11, hp, lp);
                    *(uint32_t*)&Qh_[j1] = hp; *(uint32_t*)&Ql_[j1] = lp;
                } else {
                    __half* d_ = which == 1 ? Kh_ : Vh_;
                    *(uint32_t*)&d_[j0] = pack2h(v00, v01);
                    *(uint32_t*)&d_[j1] = pack2h(v10, v11);
                }
            }
        }
    }
#undef PREFETCH
}

// ---------------- fused flash attention (R10-best: 64-row Q, single KV buffer) -
__global__ void __launch_bounds__(128)
flash_kernel(const __half* __restrict__ qh, const __half* __restrict__ ql,
             const __half* __restrict__ kh, const __half* __restrict__ vh,
             __half* __restrict__ oh, __half* __restrict__ ol) {
    extern __shared__ char fsm[];
    uint32_t sb = smem_u32(fsm);
    int bh = blockIdx.y;
    int q0 = (gridDim.x - 1 - blockIdx.x) << 6;   // long CTAs first
    int tid = threadIdx.x, wid = tid >> 5, lane = tid & 31;

    {   // Q tile load (64 rows x 128B), hi+lo
        const char* srcH = (const char*)(qh + ((size_t)bh * S_ + q0) * DH_);
        const char* srcL = (const char*)(ql + ((size_t)bh * S_ + q0) * DH_);
        #pragma unroll
        for (int i = tid; i < 512; i += 128) {
            int r = i >> 3, c = (i & 7) << 4;
            CP16(sb + QOFF_H + r * FSTR + c, srcH + r * 128 + c);
            CP16(sb + QOFF_L + r * FSTR + c, srcL + r * 128 + c);
        }
        CP_COMMIT();
    }

    float m0 = -1e30f, m1 = -1e30f, l0 = 0.f, l1 = 0.f;
    float oacc[8][4];
    #pragma unroll
    for (int d = 0; d < 8; d++)
        oacc[d][0] = oacc[d][1] = oacc[d][2] = oacc[d][3] = 0.f;

    int rA = q0 + wid * 16 + (lane >> 2);
    int nj = (q0 >> 7) + 1;

    uint32_t aAddrBase = sb + (wid * 16 + (lane & 15)) * FSTR + (((lane >> 4) & 1) << 4);
    uint32_t bRowOff = (uint32_t)((lane & 7) * FSTR) + (((lane >> 3) & 1) << 4);

    for (int j = 0; j < nj; j++) {
        __syncthreads();
        {   // K/V tile load (128 rows x 128B)
            const char* kH = (const char*)(kh + ((size_t)bh * S_ + (j << 7)) * DH_);
            const char* vH = (const char*)(vh + ((size_t)bh * S_ + (j << 7)) * DH_);
            #pragma unroll
            for (int i = tid; i < 1024; i += 128) {
                int r = i >> 3, c = (i & 7) << 4;
                uint32_t so = r * FSTR + c;
                size_t go = (size_t)r * 128 + c;
                CP16(sb + KOFF + so, kH + go);
                CP16(sb + VOFF + so, vH + go);
            }
            CP_COMMIT();
            CP_WAIT(0);
        }
        __syncthreads();

        float sf[16][4];
        #pragma unroll
        for (int nt = 0; nt < 16; nt++)
            sf[nt][0] = sf[nt][1] = sf[nt][2] = sf[nt][3] = 0.f;

        #pragma unroll
        for (int kc = 0; kc < 4; kc++) {
            uint32_t qa = aAddrBase + kc * 32;
            uint32_t q_h0,q_h1,q_h2,q_h3, q_l0,q_l1,q_l2,q_l3;
            LDSM_X4(q_h0,q_h1,q_h2,q_h3, qa + QOFF_H);
            LDSM_X4(q_l0,q_l1,q_l2,q_l3, qa + QOFF_L);
            #pragma unroll
            for (int nt = 0; nt < 16; nt++) {
                uint32_t ka = sb + KOFF + nt * 8 * FSTR + bRowOff + kc * 32;
                uint32_t k_h0,k_h1;
                LDSM_X2(k_h0,k_h1, ka);
                MMA16816(sf[nt], q_h0,q_h1,q_h2,q_h3, k_h0,k_h1);
                MMA16816(sf[nt], q_l0,q_l1,q_l2,q_l3, k_h0,k_h1);
            }
        }

        int cb = (j << 7) + (lane & 3) * 2;
        float mx0 = -1e30f, mx1 = -1e30f;
        #pragma unroll
        for (int nt = 0; nt < 16; nt++) {
            int c0 = cb + nt * 8;
            sf[nt][0] = (c0     <= rA)     ? sf[nt][0] * 0.125f : -1e30f;
            sf[nt][1] = (c0 + 1 <= rA)     ? sf[nt][1] * 0.125f : -1e30f;
            sf[nt][2] = (c0     <= rA + 8) ? sf[nt][2] * 0.125f : -1e30f;
            sf[nt][3] = (c0 + 1 <= rA + 8) ? sf[nt][3] * 0.125f : -1e30f;
            mx0 = fmaxf(mx0, fmaxf(sf[nt][0], sf[nt][1]));
            mx1 = fmaxf(mx1, fmaxf(sf[nt][2], sf[nt][3]));
        }
        mx0 = fmaxf(mx0, __shfl_xor_sync(0xffffffffu, mx0, 1));
        mx0 = fmaxf(mx0, __shfl_xor_sync(0xffffffffu, mx0, 2));
        mx1 = fmaxf(mx1, __shfl_xor_sync(0xffffffffu, mx1, 1));
        mx1 = fmaxf(mx1, __shfl_xor_sync(0xffffffffu, mx1, 2));
        float mn0 = fmaxf(m0, mx0), mn1 = fmaxf(m1, mx1);
        float sc0 = expf(m0 - mn0), sc1 = expf(m1 - mn1);
        m0 = mn0; m1 = mn1;
        l0 *= sc0; l1 *= sc1;
        #pragma unroll
        for (int d = 0; d < 8; d++) {
            oacc[d][0] *= sc0; oacc[d][1] *= sc0;
            oacc[d][2] *= sc1; oacc[d][3] *= sc1;
        }
        float s0 = 0.f, s1 = 0.f;
        uint32_t ph[16][2], pl[16][2];
        #pragma unroll
        for (int nt = 0; nt < 16; nt++) {
            float p0 = expf(sf[nt][0] - m0), p1 = expf(sf[nt][1] - m0);
            float p2 = expf(sf[nt][2] - m1), p3 = expf(sf[nt][3] - m1);
            s0 += p0 + p1; s1 += p2 + p3;
            pack_split_h(p0, p1, ph[nt][0], pl[nt][0]);
            pack_split_h(p2, p3, ph[nt][1], pl[nt][1]);
        }
        s0 += __shfl_xor_sync(0xffffffffu, s0, 1);
        s0 += __shfl_xor_sync(0xffffffffu, s0, 2);
        s1 += __shfl_xor_sync(0xffffffffu, s1, 1);
        s1 += __shfl_xor_sync(0xffffffffu, s1, 2);
        l0 += s0; l1 += s1;

        #pragma unroll
        for (int kc = 0; kc < 8; kc++) {
            uint32_t va = sb + VOFF + (kc * 16 + (lane & 15)) * FSTR;
            #pragma unroll
            for (int dt = 0; dt < 8; dt++) {
                uint32_t v_h0,v_h1;
                LDSM_X2_T(v_h0,v_h1, va + dt * 16);
                MMA16816(oacc[dt], ph[2*kc][0], ph[2*kc][1], ph[2*kc+1][0], ph[2*kc+1][1], v_h0, v_h1);
                MMA16816(oacc[dt], pl[2*kc][0], pl[2*kc][1], pl[2*kc+1][0], pl[2*kc+1][1], v_h0, v_h1);
            }
        }
    }

    float inv0 = 1.f / l0, inv1 = 1.f / l1;
    int bb = bh / H_, hH = bh % H_;
    size_t baseA = ((size_t)bb * S_ + rA) * D_ + hH * DH_;
    size_t baseB = baseA + 8 * D_;
    #pragma unroll
    for (int dt = 0; dt < 8; dt++) {
        int c = dt * 8 + (lane & 3) * 2;
        uint32_t hp, lp;
        pack_split_h(oacc[dt][0] * inv0, oacc[dt][1] * inv0, hp, lp);
        *(uint32_t*)&oh[baseA + c] = hp;
        *(uint32_t*)&ol[baseA + c] = lp;
        pack_split_h(oacc[dt][2] * inv1, oacc[dt][3] * inv1, hp, lp);
        *(uint32_t*)&oh[baseB + c] = hp;
        *(uint32_t*)&ol[baseB + c] = lp;
    }
}

// ---------------- host orchestration -----------------------------------------
extern "C" void kernel_launch(void* const* d_in, const int* in_sizes, int n_in,
                              void* d_out, int out_size) {
    const int*   ids    = (const int*)d_in[0];
    const int*   rfi    = (const int*)d_in[1];
    const float* wte    = (const float*)d_in[2];
    const float* wte_rf = (const float*)d_in[3];
    const float* wpe    = (const float*)d_in[4];
    const float* ln1_g  = (const float*)d_in[5];
    const float* ln1_b  = (const float*)d_in[6];
    const float* attn_w = (const float*)d_in[7];
    const float* attn_b = (const float*)d_in[8];
    const float* proj_w = (const float*)d_in[9];
    const float* proj_b = (const float*)d_in[10];
    const float* ln2_g  = (const float*)d_in[11];
    const float* ln2_b  = (const float*)d_in[12];
    const float* fc_w   = (const float*)d_in[13];
    const float* fc_b   = (const float*)d_in[14];
    const float* fc2_w  = (const float*)d_in[15];
    const float* fc2_b  = (const float*)d_in[16];
    const float* lnf_g  = (const float*)d_in[17];
    const float* lnf_b  = (const float*)d_in[18];
    float* out = (float*)d_out;

    float *h, *tp;
    __half *ah, *al, *mh, *ml, *oh, *ol;
    __half *qh, *ql, *kh, *vh;
    __half *tah, *tph, *tfh, *t2h;
    cudaGetSymbolAddress((void**)&h,   g_h);
    cudaGetSymbolAddress((void**)&tp,  g_t);
    cudaGetSymbolAddress((void**)&ah,  g_ah);  cudaGetSymbolAddress((void**)&al,  g_al);
    cudaGetSymbolAddress((void**)&mh,  g_mh);  cudaGetSymbolAddress((void**)&ml,  g_ml);
    cudaGetSymbolAddress((void**)&oh,  g_oh);  cudaGetSymbolAddress((void**)&ol,  g_ol);
    cudaGetSymbolAddress((void**)&qh,  g_qh);  cudaGetSymbolAddress((void**)&ql,  g_ql);
    cudaGetSymbolAddress((void**)&kh,  g_kh);  cudaGetSymbolAddress((void**)&vh,  g_vh);
    cudaGetSymbolAddress((void**)&tah, t_attn_h);
    cudaGetSymbolAddress((void**)&tph, t_proj_h);
    cudaGetSymbolAddress((void**)&tfh, t_fc_h);
    cudaGetSymbolAddress((void**)&t2h, t_fc2_h);

    cudaFuncSetAttribute(gemm_mma<2>, cudaFuncAttributeMaxDynamicSharedMemorySize, SMEM_GEMM);
    cudaFuncSetAttribute(gemm_mma<3>, cudaFuncAttributeMaxDynamicSharedMemorySize, SMEM_GEMM);
    cudaFuncSetAttribute(gemm_mma<4>, cudaFuncAttributeMaxDynamicSharedMemorySize, SMEM_GEMM);
    cudaFuncSetAttribute(flash_kernel, cudaFuncAttributeMaxDynamicSharedMemorySize, SMEM_FLASH);

    wsplit_all_kernel<<<TILES_PER_LAYER * L_, dim3(32, 8)>>>(
        attn_w, proj_w, fc_w, fc2_w, tah, tph, tfh, t2h);
    embed_ln_kernel<<<NT_/LNROWS, 256>>>(ids, rfi, wte, wte_rf, wpe, ln1_g, ln1_b, h, ah, al);

    for (int l = 0; l < L_; l++) {
        gemm_mma<3><<<dim3(D3_/128, NT_/128), 256, SMEM_GEMM>>>(
            ah, al, tah + (size_t)l * D3_ * D_,
            attn_b + l * D3_, nullptr, nullptr, nullptr, nullptr,
            qh, ql, kh, vh, NT_, D3_, D_, D_);
        flash_kernel<<<dim3(S_/64, B_*H_), 128, SMEM_FLASH>>>(qh, ql, kh, vh, oh, ol);
        // proj split-K=2 -> tmp partials
        gemm_mma<4><<<dim3(D_/128, NT_/128, 2), 256, SMEM_GEMM>>>(
            oh, ol, tph + (size_t)l * D_ * D_,
            nullptr, nullptr, tp, nullptr, nullptr,
            nullptr, nullptr, nullptr, nullptr, NT_, D_, D_/2, D_);
        // h = h + t0 + t1 + proj_b;  ah/al = split(ln2(h))
        ln_sum_kernel<true><<<NT_/LNROWS, 256>>>(
            h, tp, proj_b + l * D_, ln2_g + l * D_, ln2_b + l * D_, h, nullptr, ah, al);
        gemm_mma<2><<<dim3(DF_/128, NT_/128), 256, SMEM_GEMM>>>(
            ah, al, tfh + (size_t)l * DF_ * D_,
            fc_b + l * DF_, nullptr, nullptr, mh, ml,
            nullptr, nullptr, nullptr, nullptr, NT_, DF_, D_, D_);
        // fc2 split-K=2 -> tmp partials
        gemm_mma<4><<<dim3(D_/128, NT_/128, 2), 256, SMEM_GEMM>>>(
            mh, ml, t2h + (size_t)l * D_ * DF_,
            nullptr, nullptr, tp, nullptr, nullptr,
            nullptr, nullptr, nullptr, nullptr, NT_, D_, DF_/2, DF_);
        if (l < L_ - 1) {
            // h = h + t0 + t1 + fc2_b;  ah/al = split(ln1[l+1](h))
            ln_sum_kernel<true><<<NT_/LNROWS, 256>>>(
                h, tp, fc2_b + l * D_, ln1_g + (l + 1) * D_, ln1_b + (l + 1) * D_,
                h, nullptr, ah, al);
        } else {
            // out = lnf(h + t0 + t1 + fc2_b)
            ln_sum_kernel<false><<<NT_/LNROWS, 256>>>(
                h, tp, fc2_b + l * D_, lnf_g, lnf_b, nullptr, out, nullptr, nullptr);
        }
    }
}

// round 13
// speedup vs baseline: 1.1288x; 1.0335x over previous
#include <cuda_runtime.h>
#include <cuda_fp16.h>
#include <math.h>
#include <stdint.h>

#define B_  4
#define S_  1024
#define D_  768
#define H_  12
#define L_  6
#define DF_ 3072
#define DH_ 64
#define NT_ (B_*S_)        // 4096
#define D3_ (3*D_)         // 2304
#define SPLITK 3

// ---------------- scratch (static device globals) ----------------------------
static __device__ float g_h[NT_*D_];
static __device__ float g_t[(size_t)SPLITK*NT_*D_];     // split-K partials
static __device__ __half g_ah[NT_*D_],  g_al[NT_*D_];
static __device__ __half g_mh[NT_*DF_], g_ml[NT_*DF_];
static __device__ __half g_oh[NT_*D_],  g_ol[NT_*D_];
static __device__ __half g_qh[NT_*D_],  g_ql[NT_*D_];
static __device__ __half g_kh[NT_*D_];
static __device__ __half g_vh[NT_*D_];
static __device__ __half t_attn_h[(size_t)L_*D3_*D_];
static __device__ __half t_proj_h[(size_t)L_*D_*D_];
static __device__ __half t_fc_h[(size_t)L_*DF_*D_];
static __device__ __half t_fc2_h[(size_t)L_*D_*DF_];

// ---------------- helpers ----------------------------------------------------
__device__ __forceinline__ uint32_t smem_u32(const void* p) {
    uint32_t a;
    asm("{ .reg .u64 t; cvta.to.shared.u64 t, %1; cvt.u32.u64 %0, t; }" : "=r"(a) : "l"(p));
    return a;
}
__device__ __forceinline__ float gelu_f(float x) {
    const float c = 0.7978845608028654f;
    return 0.5f * x * (1.0f + tanhf(c * (x + 0.044715f * x * x * x)));
}
__device__ __forceinline__ void split_h(float v, __half& hi, __half& lo) {
    hi = __float2half_rn(v);
    lo = __float2half_rn(v - __half2float(hi));
}
__device__ __forceinline__ uint32_t pack2h(float x, float y) {
    __half2 p; p.x = __float2half_rn(x); p.y = __float2half_rn(y);
    return *(uint32_t*)&p;
}
__device__ __forceinline__ void pack_split_h(float x, float y, uint32_t& hp, uint32_t& lp) {
    __half hx, lx, hy, ly;
    split_h(x, hx, lx); split_h(y, hy, ly);
    __half2 h2; h2.x = hx; h2.y = hy;
    __half2 l2; l2.x = lx; l2.y = ly;
    hp = *(uint32_t*)&h2; lp = *(uint32_t*)&l2;
}
__device__ __forceinline__ float warp_sum(float v) {
    #pragma unroll
    for (int o = 16; o > 0; o >>= 1) v += __shfl_xor_sync(0xffffffffu, v, o);
    return v;
}

#define CP16(dst, src) \
    asm volatile("cp.async.cg.shared.global [%0], [%1], 16;" :: "r"(dst), "l"(src))
#define CP_COMMIT() asm volatile("cp.async.commit_group;")
#define CP_WAIT(n)  asm volatile("cp.async.wait_group %0;" :: "n"(n))

#define LDSM_X4(r0, r1, r2, r3, a) \
    asm volatile("ldmatrix.sync.aligned.m8n8.x4.shared.b16 {%0,%1,%2,%3}, [%4];" \
                 : "=r"(r0), "=r"(r1), "=r"(r2), "=r"(r3) : "r"(a))
#define LDSM_X2(r0, r1, a) \
    asm volatile("ldmatrix.sync.aligned.m8n8.x2.shared.b16 {%0,%1}, [%2];" \
                 : "=r"(r0), "=r"(r1) : "r"(a))
#define LDSM_X2_T(r0, r1, a) \
    asm volatile("ldmatrix.sync.aligned.m8n8.x2.trans.shared.b16 {%0,%1}, [%2];" \
                 : "=r"(r0), "=r"(r1) : "r"(a))
#define MMA16816(d, a0, a1, a2, a3, b0, b1) \
    asm volatile("mma.sync.aligned.m16n8k16.row.col.f32.f16.f16.f32 " \
                 "{%0,%1,%2,%3},{%4,%5,%6,%7},{%8,%9},{%0,%1,%2,%3};" \
                 : "+f"((d)[0]), "+f"((d)[1]), "+f"((d)[2]), "+f"((d)[3]) \
                 : "r"(a0), "r"(a1), "r"(a2), "r"(a3), "r"(b0), "r"(b1))

// gemm smem: 128 rows x 64 fp16 (128B) padded to 144B; 3 matrices per stage
#define TSTRIDE 144
#define MATBYTES 18432
#define STAGEBYTES 55296
#define SMEM_GEMM (2*STAGEBYTES)

// flash smem: rows of 64 fp16 (128B) padded to 144B
#define FSTR 144
#define QOFF_H 0
#define QOFF_L 9216
#define KOFF   18432
#define VOFF   36864
#define SMEM_FLASH 55296

// ---------------- fused weight transpose + fp16 convert ----------------------
#define TILES_PER_LAYER 6912
__global__ void wsplit_all_kernel(const float* __restrict__ attn_w, const float* __restrict__ proj_w,
                                  const float* __restrict__ fc_w,   const float* __restrict__ fc2_w,
                                  __half* __restrict__ tah, __half* __restrict__ tph,
                                  __half* __restrict__ tfh, __half* __restrict__ t2h) {
    __shared__ float t[32][33];
    int bid = blockIdx.x;
    int l = bid / TILES_PER_LAYER;
    int r = bid % TILES_PER_LAYER;
    const float* W; __half* Oh; int K, N, tile;
    if (r < 1728)      { W = attn_w; Oh = tah; K = D_;  N = D3_; tile = r; }
    else if (r < 2304) { W = proj_w; Oh = tph; K = D_;  N = D_;  tile = r - 1728; }
    else if (r < 4608) { W = fc_w;   Oh = tfh; K = D_;  N = DF_; tile = r - 2304; }
    else               { W = fc2_w;  Oh = t2h; K = DF_; N = D_;  tile = r - 4608; }
    int nx = N >> 5;
    int n0 = (tile % nx) << 5, k0 = (tile / nx) << 5;
    const float* Wl = W + (size_t)l * K * N;
    __half* OhL = Oh + (size_t)l * K * N;
    int tx = threadIdx.x, ty = threadIdx.y;    // (32,8)
    for (int i = ty; i < 32; i += 8)
        t[i][tx] = Wl[(size_t)(k0 + i) * N + n0 + tx];
    __syncthreads();
    for (int i = ty; i < 32; i += 8)
        OhL[(size_t)(n0 + i) * K + k0 + tx] = __float2half_rn(t[tx][i]);
}

// ---------------- warp-per-row layernorms -------------------------------------
#define LNROWS 8
__global__ void embed_ln_kernel(const int* __restrict__ ids, const int* __restrict__ rfi,
                                const float* __restrict__ wte, const float* __restrict__ wte_rf,
                                const float* __restrict__ wpe,
                                const float* __restrict__ g, const float* __restrict__ b,
                                float* __restrict__ h,
                                __half* __restrict__ yh, __half* __restrict__ yl) {
    int w = threadIdx.x >> 5, lane = threadIdx.x & 31;
    int row = blockIdx.x * LNROWS + w;
    int s = row & (S_ - 1);
    const float* e1 = wte    + (size_t)ids[row] * D_;
    const float* e2 = wte_rf + (size_t)rfi[row] * D_;
    const float* e3 = wpe    + (size_t)s * D_;
    float* hr = h + (size_t)row * D_;
    float v[24];
    float sum = 0.f;
    #pragma unroll
    for (int i = 0; i < 24; i++) {
        int c = lane + (i << 5);
        float x = e1[c] + e2[c] + e3[c];
        hr[c] = x;
        v[i] = x; sum += x;
    }
    sum = warp_sum(sum);
    float mu = sum * (1.0f / D_);
    float q = 0.f;
    #pragma unroll
    for (int i = 0; i < 24; i++) { v[i] -= mu; q += v[i] * v[i]; }
    q = warp_sum(q);
    float inv = rsqrtf(q * (1.0f / D_) + 1e-5f);
    size_t base = (size_t)row * D_;
    #pragma unroll
    for (int i = 0; i < 24; i++) {
        int c = lane + (i << 5);
        float r = v[i] * inv * g[c] + b[c];
        __half hi, lo; split_h(r, hi, lo);
        yh[base + c] = hi; yl[base + c] = lo;
    }
}

// ln_sum: v = x + t0 + t1 + t2 + gbias; optionally write h; LN(v) -> (yh,yl)/y.
template<bool HF>
__global__ void ln_sum_kernel(const float* __restrict__ x, const float* __restrict__ t,
                              const float* __restrict__ gb,
                              const float* __restrict__ g, const float* __restrict__ b,
                              float* __restrict__ hout, float* __restrict__ y,
                              __half* __restrict__ yh, __half* __restrict__ yl) {
    int w = threadIdx.x >> 5, lane = threadIdx.x & 31;
    int row = blockIdx.x * LNROWS + w;
    size_t base = (size_t)row * D_;
    const float* t0 = t + base;
    const float* t1 = t + (size_t)NT_ * D_ + base;
    const float* t2 = t + (size_t)2 * NT_ * D_ + base;
    const float* xr = x + base;
    float v[24];
    float sum = 0.f;
    #pragma unroll
    for (int i = 0; i < 24; i++) {
        int c = lane + (i << 5);
        float val = xr[c] + t0[c] + t1[c] + t2[c] + gb[c];
        if (hout) hout[base + c] = val;
        v[i] = val; sum += val;
    }
    sum = warp_sum(sum);
    float mu = sum * (1.0f / D_);
    float q = 0.f;
    #pragma unroll
    for (int i = 0; i < 24; i++) { v[i] -= mu; q += v[i] * v[i]; }
    q = warp_sum(q);
    float inv = rsqrtf(q * (1.0f / D_) + 1e-5f);
    #pragma unroll
    for (int i = 0; i < 24; i++) {
        int c = lane + (i << 5);
        float r = v[i] * inv * g[c] + b[c];
        if (HF) {
            __half hi, lo; split_h(r, hi, lo);
            yh[base + c] = hi; yl[base + c] = lo;
        } else {
            y[base + c] = r;
        }
    }
}

// ---------------- mma.sync GEMM (fp16 2-pass, K-chunk 64) ---------------------
// EPI 2: Ch/Cl = split(gelu(acc+bias)).  EPI 3: head-major Q(hi/lo) K V.
// EPI 4: split-K partial: Cf[z] = raw acc, z = blockIdx.z.
template<int EPI>
__global__ void __launch_bounds__(256, 2)
gemm_mma(const __half* __restrict__ Ah, const __half* __restrict__ Al,
         const __half* __restrict__ Bh,
         const float* __restrict__ bias, const float* __restrict__ resid,
         float* __restrict__ Cf, __half* __restrict__ Ch, __half* __restrict__ Cl,
         __half* __restrict__ Qh_, __half* __restrict__ Ql_,
         __half* __restrict__ Kh_, __half* __restrict__ Vh_,
         int M, int N, int K, int Ktot) {
    extern __shared__ char smem[];
    uint32_t sbase = smem_u32(smem);
    int tid = threadIdx.x;
    int wid = tid >> 5, lane = tid & 31;
    int wm = wid >> 2, wn = wid & 3;
    int m0 = blockIdx.y << 7, n0 = blockIdx.x << 7;
    int ldb = Ktot * 2;
    int kz = (EPI == 4) ? blockIdx.z : 0;
    size_t koff0 = (size_t)kz * K;
    if (EPI == 4) Cf += (size_t)kz * ((size_t)M * N);

    const char* srcs[3];
    srcs[0] = (const char*)(Ah + (size_t)m0 * Ktot + koff0);
    srcs[1] = (const char*)(Al + (size_t)m0 * Ktot + koff0);
    srcs[2] = (const char*)(Bh + (size_t)n0 * Ktot + koff0);

    float acc[4][4][4] = {};
    int nk = K >> 6;

#define PREFETCH(c, s)                                                        \
    {                                                                         \
        size_t ko = (size_t)(c) << 7;                                         \
        uint32_t stb = sbase + (s) * STAGEBYTES;                              \
        _Pragma("unroll")                                                     \
        for (int j = 0; j < 12; j++) {                                        \
            int q = tid + j * 256;                                            \
            int mat = q >> 10, w = q & 1023, row = w >> 3, cc = w & 7;        \
            uint32_t dst = stb + mat * MATBYTES + row * TSTRIDE + cc * 16;    \
            const char* sp = srcs[mat] + (size_t)row * ldb + ko + cc * 16;    \
            CP16(dst, sp);                                                    \
        }                                                                     \
        CP_COMMIT();                                                          \
    }

    PREFETCH(0, 0);

    int aRow = wm * 64 + (lane & 7) + ((lane >> 3) & 1) * 8;
    uint32_t aKoff = ((lane >> 4) & 1) * 16;
    int lb = lane & 15;
    int bRow = wn * 32 + (lb & 7);
    uint32_t bKoff = ((lb >> 3) & 1) * 16;

    for (int c = 0; c < nk; c++) {
        int s = c & 1;
        if (c + 1 < nk) PREFETCH(c + 1, s ^ 1);
        if (c + 1 < nk) { CP_WAIT(1); } else { CP_WAIT(0); }
        __syncthreads();

        uint32_t stb = sbase + s * STAGEBYTES;
        #pragma unroll
        for (int kk = 0; kk < 4; kk++) {
            uint32_t bh[4][2];
            #pragma unroll
            for (int nj = 0; nj < 4; nj++) {
                uint32_t addr = stb + 2 * MATBYTES + (bRow + nj * 8) * TSTRIDE + kk * 32 + bKoff;
                LDSM_X2(bh[nj][0], bh[nj][1], addr);
            }
            uint32_t af[4][4];
            #pragma unroll
            for (int mi = 0; mi < 4; mi++) {
                uint32_t addr = stb + (aRow + mi * 16) * TSTRIDE + kk * 32 + aKoff;
                LDSM_X4(af[mi][0], af[mi][1], af[mi][2], af[mi][3], addr);
            }
            #pragma unroll
            for (int mi = 0; mi < 4; mi++)
                #pragma unroll
                for (int nj = 0; nj < 4; nj++)
                    MMA16816(acc[mi][nj], af[mi][0], af[mi][1], af[mi][2], af[mi][3],
                             bh[nj][0], bh[nj][1]);
            #pragma unroll
            for (int mi = 0; mi < 4; mi++) {
                uint32_t addr = stb + MATBYTES + (aRow + mi * 16) * TSTRIDE + kk * 32 + aKoff;
                LDSM_X4(af[mi][0], af[mi][1], af[mi][2], af[mi][3], addr);
            }
            #pragma unroll
            for (int mi = 0; mi < 4; mi++)
                #pragma unroll
                for (int nj = 0; nj < 4; nj++)
                    MMA16816(acc[mi][nj], af[mi][0], af[mi][1], af[mi][2], af[mi][3],
                             bh[nj][0], bh[nj][1]);
        }
        __syncthreads();
    }

    int rbase = m0 + wm * 64 + (lane >> 2);
    int cbase = n0 + wn * 32 + (lane & 3) * 2;
    #pragma unroll
    for (int mi = 0; mi < 4; mi++) {
        #pragma unroll
        for (int nj = 0; nj < 4; nj++) {
            int r = rbase + mi * 16;
            int col = cbase + nj * 8;
            float b0 = (EPI == 4) ? 0.f : bias[col];
            float b1 = (EPI == 4) ? 0.f : bias[col + 1];
            float v00 = acc[mi][nj][0] + b0, v01 = acc[mi][nj][1] + b1;
            float v10 = acc[mi][nj][2] + b0, v11 = acc[mi][nj][3] + b1;
            size_t i0 = (size_t)r * N + col;
            size_t i1 = (size_t)(r + 8) * N + col;
            if (EPI == 4) {
                *(float2*)&Cf[i0] = make_float2(v00, v01);
                *(float2*)&Cf[i1] = make_float2(v10, v11);
            } else if (EPI == 2) {
                v00 = gelu_f(v00); v01 = gelu_f(v01);
                v10 = gelu_f(v10); v11 = gelu_f(v11);
                uint32_t hp, lp;
                pack_split_h(v00, v01, hp, lp);
                *(uint32_t*)&Ch[i0] = hp; *(uint32_t*)&Cl[i0] = lp;
                pack_split_h(v10, v11, hp, lp);
                *(uint32_t*)&Ch[i1] = hp; *(uint32_t*)&Cl[i1] = lp;
            } else {
                int which = col / D_;
                int hh = (col % D_) / DH_;
                int dd = col % DH_;
                int bi = r >> 10, si = r & 1023;
                size_t j0 = (((size_t)(bi * H_ + hh)) * S_ + si) * DH_ + dd;
                size_t j1 = j0 + 8 * DH_;
                if (which == 0) {
                    uint32_t hp, lp;
                    pack_split_h(v00, v01, hp, lp);
                    *(uint32_t*)&Qh_[j0] = hp; *(uint32_t*)&Ql_[j0] = lp;
                    pack_split_h(v10, v11, hp, lp);
                    *(uint32_t*)&Qh_[j1] = hp; *(uint32_t*)&Ql_[j1] = lp;
                } else {
                    __half* d_ = which == 1 ? Kh_ : Vh_;
                    *(uint32_t*)&d_[j0] = pack2h(v00, v01);
                    *(uint32_t*)&d_[j1] = pack2h(v10, v11);
                }
            }
        }
    }
#undef PREFETCH
}

// ---------------- fused flash attention (64-row Q, single KV buffer) ----------
__global__ void __launch_bounds__(128)
flash_kernel(const __half* __restrict__ qh, const __half* __restrict__ ql,
             const __half* __restrict__ kh, const __half* __restrict__ vh,
             __half* __restrict__ oh, __half* __restrict__ ol) {
    extern __shared__ char fsm[];
    uint32_t sb = smem_u32(fsm);
    int bh = blockIdx.y;
    int q0 = (gridDim.x - 1 - blockIdx.x) << 6;   // long CTAs first
    int tid = threadIdx.x, wid = tid >> 5, lane = tid & 31;

    {   // Q tile load (64 rows x 128B), hi+lo
        const char* srcH = (const char*)(qh + ((size_t)bh * S_ + q0) * DH_);
        const char* srcL = (const char*)(ql + ((size_t)bh * S_ + q0) * DH_);
        #pragma unroll
        for (int i = tid; i < 512; i += 128) {
            int r = i >> 3, c = (i & 7) << 4;
            CP16(sb + QOFF_H + r * FSTR + c, srcH + r * 128 + c);
            CP16(sb + QOFF_L + r * FSTR + c, srcL + r * 128 + c);
        }
        CP_COMMIT();
    }

    float m0 = -1e30f, m1 = -1e30f, l0 = 0.f, l1 = 0.f;
    float oacc[8][4];
    #pragma unroll
    for (int d = 0; d < 8; d++)
        oacc[d][0] = oacc[d][1] = oacc[d][2] = oacc[d][3] = 0.f;

    int rA = q0 + wid * 16 + (lane >> 2);
    int nj = (q0 >> 7) + 1;

    uint32_t aAddrBase = sb + (wid * 16 + (lane & 15)) * FSTR + (((lane >> 4) & 1) << 4);
    uint32_t bRowOff = (uint32_t)((lane & 7) * FSTR) + (((lane >> 3) & 1) << 4);

    for (int j = 0; j < nj; j++) {
        __syncthreads();
        {   // K/V tile load (128 rows x 128B)
            const char* kH = (const char*)(kh + ((size_t)bh * S_ + (j << 7)) * DH_);
            const char* vH = (const char*)(vh + ((size_t)bh * S_ + (j << 7)) * DH_);
            #pragma unroll
            for (int i = tid; i < 1024; i += 128) {
                int r = i >> 3, c = (i & 7) << 4;
                uint32_t so = r * FSTR + c;
                size_t go = (size_t)r * 128 + c;
                CP16(sb + KOFF + so, kH + go);
                CP16(sb + VOFF + so, vH + go);
            }
            CP_COMMIT();
            CP_WAIT(0);
        }
        __syncthreads();

        float sf[16][4];
        #pragma unroll
        for (int nt = 0; nt < 16; nt++)
            sf[nt][0] = sf[nt][1] = sf[nt][2] = sf[nt][3] = 0.f;

        #pragma unroll
        for (int kc = 0; kc < 4; kc++) {
            uint32_t qa = aAddrBase + kc * 32;
            uint32_t q_h0,q_h1,q_h2,q_h3, q_l0,q_l1,q_l2,q_l3;
            LDSM_X4(q_h0,q_h1,q_h2,q_h3, qa + QOFF_H);
            LDSM_X4(q_l0,q_l1,q_l2,q_l3, qa + QOFF_L);
            #pragma unroll
            for (int nt = 0; nt < 16; nt++) {
                uint32_t ka = sb + KOFF + nt * 8 * FSTR + bRowOff + kc * 32;
                uint32_t k_h0,k_h1;
                LDSM_X2(k_h0,k_h1, ka);
                MMA16816(sf[nt], q_h0,q_h1,q_h2,q_h3, k_h0,k_h1);
                MMA16816(sf[nt], q_l0,q_l1,q_l2,q_l3, k_h0,k_h1);
            }
        }

        int cb = (j << 7) + (lane & 3) * 2;
        float mx0 = -1e30f, mx1 = -1e30f;
        #pragma unroll
        for (int nt = 0; nt < 16; nt++) {
            int c0 = cb + nt * 8;
            sf[nt][0] = (c0     <= rA)     ? sf[nt][0] * 0.125f : -1e30f;
            sf[nt][1] = (c0 + 1 <= rA)     ? sf[nt][1] * 0.125f : -1e30f;
            sf[nt][2] = (c0     <= rA + 8) ? sf[nt][2] * 0.125f : -1e30f;
            sf[nt][3] = (c0 + 1 <= rA + 8) ? sf[nt][3] * 0.125f : -1e30f;
            mx0 = fmaxf(mx0, fmaxf(sf[nt][0], sf[nt][1]));
            mx1 = fmaxf(mx1, fmaxf(sf[nt][2], sf[nt][3]));
        }
        mx0 = fmaxf(mx0, __shfl_xor_sync(0xffffffffu, mx0, 1));
        mx0 = fmaxf(mx0, __shfl_xor_sync(0xffffffffu, mx0, 2));
        mx1 = fmaxf(mx1, __shfl_xor_sync(0xffffffffu, mx1, 1));
        mx1 = fmaxf(mx1, __shfl_xor_sync(0xffffffffu, mx1, 2));
        float mn0 = fmaxf(m0, mx0), mn1 = fmaxf(m1, mx1);
        float sc0 = expf(m0 - mn0), sc1 = expf(m1 - mn1);
        m0 = mn0; m1 = mn1;
        l0 *= sc0; l1 *= sc1;
        #pragma unroll
        for (int d = 0; d < 8; d++) {
            oacc[d][0] *= sc0; oacc[d][1] *= sc0;
            oacc[d][2] *= sc1; oacc[d][3] *= sc1;
        }
        float s0 = 0.f, s1 = 0.f;
        uint32_t ph[16][2], pl[16][2];
        #pragma unroll
        for (int nt = 0; nt < 16; nt++) {
            float p0 = expf(sf[nt][0] - m0), p1 = expf(sf[nt][1] - m0);
            float p2 = expf(sf[nt][2] - m1), p3 = expf(sf[nt][3] - m1);
            s0 += p0 + p1; s1 += p2 + p3;
            pack_split_h(p0, p1, ph[nt][0], pl[nt][0]);
            pack_split_h(p2, p3, ph[nt][1], pl[nt][1]);
        }
        s0 += __shfl_xor_sync(0xffffffffu, s0, 1);
        s0 += __shfl_xor_sync(0xffffffffu, s0, 2);
        s1 += __shfl_xor_sync(0xffffffffu, s1, 1);
        s1 += __shfl_xor_sync(0xffffffffu, s1, 2);
        l0 += s0; l1 += s1;

        #pragma unroll
        for (int kc = 0; kc < 8; kc++) {
            uint32_t va = sb + VOFF + (kc * 16 + (lane & 15)) * FSTR;
            #pragma unroll
            for (int dt = 0; dt < 8; dt++) {
                uint32_t v_h0,v_h1;
                LDSM_X2_T(v_h0,v_h1, va + dt * 16);
                MMA16816(oacc[dt], ph[2*kc][0], ph[2*kc][1], ph[2*kc+1][0], ph[2*kc+1][1], v_h0, v_h1);
                MMA16816(oacc[dt], pl[2*kc][0], pl[2*kc][1], pl[2*kc+1][0], pl[2*kc+1][1], v_h0, v_h1);
            }
        }
    }

    float inv0 = 1.f / l0, inv1 = 1.f / l1;
    int bb = bh / H_, hH = bh % H_;
    size_t baseA = ((size_t)bb * S_ + rA) * D_ + hH * DH_;
    size_t baseB = baseA + 8 * D_;
    #pragma unroll
    for (int dt = 0; dt < 8; dt++) {
        int c = dt * 8 + (lane & 3) * 2;
        uint32_t hp, lp;
        pack_split_h(oacc[dt][0] * inv0, oacc[dt][1] * inv0, hp, lp);
        *(uint32_t*)&oh[baseA + c] = hp;
        *(uint32_t*)&ol[baseA + c] = lp;
        pack_split_h(oacc[dt][2] * inv1, oacc[dt][3] * inv1, hp, lp);
        *(uint32_t*)&oh[baseB + c] = hp;
        *(uint32_t*)&ol[baseB + c] = lp;
    }
}

// ---------------- host orchestration -----------------------------------------
extern "C" void kernel_launch(void* const* d_in, const int* in_sizes, int n_in,
                              void* d_out, int out_size) {
    const int*   ids    = (const int*)d_in[0];
    const int*   rfi    = (const int*)d_in[1];
    const float* wte    = (const float*)d_in[2];
    const float* wte_rf = (const float*)d_in[3];
    const float* wpe    = (const float*)d_in[4];
    const float* ln1_g  = (const float*)d_in[5];
    const float* ln1_b  = (const float*)d_in[6];
    const float* attn_w = (const float*)d_in[7];
    const float* attn_b = (const float*)d_in[8];
    const float* proj_w = (const float*)d_in[9];
    const float* proj_b = (const float*)d_in[10];
    const float* ln2_g  = (const float*)d_in[11];
    const float* ln2_b  = (const float*)d_in[12];
    const float* fc_w   = (const float*)d_in[13];
    const float* fc_b   = (const float*)d_in[14];
    const float* fc2_w  = (const float*)d_in[15];
    const float* fc2_b  = (const float*)d_in[16];
    const float* lnf_g  = (const float*)d_in[17];
    const float* lnf_b  = (const float*)d_in[18];
    float* out = (float*)d_out;

    float *h, *tp;
    __half *ah, *al, *mh, *ml, *oh, *ol;
    __half *qh, *ql, *kh, *vh;
    __half *tah, *tph, *tfh, *t2h;
    cudaGetSymbolAddress((void**)&h,   g_h);
    cudaGetSymbolAddress((void**)&tp,  g_t);
    cudaGetSymbolAddress((void**)&ah,  g_ah);  cudaGetSymbolAddress((void**)&al,  g_al);
    cudaGetSymbolAddress((void**)&mh,  g_mh);  cudaGetSymbolAddress((void**)&ml,  g_ml);
    cudaGetSymbolAddress((void**)&oh,  g_oh);  cudaGetSymbolAddress((void**)&ol,  g_ol);
    cudaGetSymbolAddress((void**)&qh,  g_qh);  cudaGetSymbolAddress((void**)&ql,  g_ql);
    cudaGetSymbolAddress((void**)&kh,  g_kh);  cudaGetSymbolAddress((void**)&vh,  g_vh);
    cudaGetSymbolAddress((void**)&tah, t_attn_h);
    cudaGetSymbolAddress((void**)&tph, t_proj_h);
    cudaGetSymbolAddress((void**)&tfh, t_fc_h);
    cudaGetSymbolAddress((void**)&t2h, t_fc2_h);

    cudaFuncSetAttribute(gemm_mma<2>, cudaFuncAttributeMaxDynamicSharedMemorySize, SMEM_GEMM);
    cudaFuncSetAttribute(gemm_mma<3>, cudaFuncAttributeMaxDynamicSharedMemorySize, SMEM_GEMM);
    cudaFuncSetAttribute(gemm_mma<4>, cudaFuncAttributeMaxDynamicSharedMemorySize, SMEM_GEMM);
    cudaFuncSetAttribute(flash_kernel, cudaFuncAttributeMaxDynamicSharedMemorySize, SMEM_FLASH);

    wsplit_all_kernel<<<TILES_PER_LAYER * L_, dim3(32, 8)>>>(
        attn_w, proj_w, fc_w, fc2_w, tah, tph, tfh, t2h);
    embed_ln_kernel<<<NT_/LNROWS, 256>>>(ids, rfi, wte, wte_rf, wpe, ln1_g, ln1_b, h, ah, al);

    for (int l = 0; l < L_; l++) {
        gemm_mma<3><<<dim3(D3_/128, NT_/128), 256, SMEM_GEMM>>>(
            ah, al, tah + (size_t)l * D3_ * D_,
            attn_b + l * D3_, nullptr, nullptr, nullptr, nullptr,
            qh, ql, kh, vh, NT_, D3_, D_, D_);
        flash_kernel<<<dim3(S_/64, B_*H_), 128, SMEM_FLASH>>>(qh, ql, kh, vh, oh, ol);
        // proj split-K=3 -> tmp partials
        gemm_mma<4><<<dim3(D_/128, NT_/128, SPLITK), 256, SMEM_GEMM>>>(
            oh, ol, tph + (size_t)l * D_ * D_,
            nullptr, nullptr, tp, nullptr, nullptr,
            nullptr, nullptr, nullptr, nullptr, NT_, D_, D_/SPLITK, D_);
        // h = h + t0 + t1 + t2 + proj_b;  ah/al = split(ln2(h))
        ln_sum_kernel<true><<<NT_/LNROWS, 256>>>(
            h, tp, proj_b + l * D_, ln2_g + l * D_, ln2_b + l * D_, h, nullptr, ah, al);
        gemm_mma<2><<<dim3(DF_/128, NT_/128), 256, SMEM_GEMM>>>(
            ah, al, tfh + (size_t)l * DF_ * D_,
            fc_b + l * DF_, nullptr, nullptr, mh, ml,
            nullptr, nullptr, nullptr, nullptr, NT_, DF_, D_, D_);
        // fc2 split-K=3 -> tmp partials
        gemm_mma<4><<<dim3(D_/128, NT_/128, SPLITK), 256, SMEM_GEMM>>>(
            mh, ml, t2h + (size_t)l * D_ * DF_,
            nullptr, nullptr, tp, nullptr, nullptr,
            nullptr, nullptr, nullptr, nullptr, NT_, D_, DF_/SPLITK, DF_);
        if (l < L_ - 1) {
            ln_sum_kernel<true><<<NT_/LNROWS, 256>>>(
                h, tp, fc2_b + l * D_, ln1_g + (l + 1) * D_, ln1_b + (l + 1) * D_,
                h, nullptr, ah, al);
        } else {
            ln_sum_kernel<false><<<NT_/LNROWS, 256>>>(
                h, tp, fc2_b + l * D_, lnf_g, lnf_b, nullptr, out, nullptr, nullptr);
        }
    }
}

// round 14
// speedup vs baseline: 1.2104x; 1.0723x over previous
#include <cuda_runtime.h>
#include <cuda_fp16.h>
#include <math.h>
#include <stdint.h>

#define B_  4
#define S_  1024
#define D_  768
#define H_  12
#define L_  6
#define DF_ 3072
#define DH_ 64
#define NT_ (B_*S_)        // 4096
#define D3_ (3*D_)         // 2304
#define SPLITK 3

// ---------------- scratch (static device globals) ----------------------------
static __device__ float g_h[NT_*D_];
static __device__ float g_t[(size_t)SPLITK*NT_*D_];     // split-K partials
static __device__ __half g_ah[NT_*D_],  g_al[NT_*D_];
static __device__ __half g_mh[NT_*DF_], g_ml[NT_*DF_];
static __device__ __half g_oh[NT_*D_],  g_ol[NT_*D_];
static __device__ __half g_qh[NT_*D_],  g_ql[NT_*D_];
static __device__ __half g_kh[NT_*D_];
static __device__ __half g_vh[NT_*D_];
static __device__ __half t_attn_h[(size_t)L_*D3_*D_];
static __device__ __half t_proj_h[(size_t)L_*D_*D_];
static __device__ __half t_fc_h[(size_t)L_*DF_*D_];
static __device__ __half t_fc2_h[(size_t)L_*D_*DF_];

// ---------------- helpers ----------------------------------------------------
__device__ __forceinline__ uint32_t smem_u32(const void* p) {
    uint32_t a;
    asm("{ .reg .u64 t; cvta.to.shared.u64 t, %1; cvt.u32.u64 %0, t; }" : "=r"(a) : "l"(p));
    return a;
}
__device__ __forceinline__ float gelu_f(float x) {
    const float c = 0.7978845608028654f;
    return 0.5f * x * (1.0f + tanhf(c * (x + 0.044715f * x * x * x)));
}
__device__ __forceinline__ void split_h(float v, __half& hi, __half& lo) {
    hi = __float2half_rn(v);
    lo = __float2half_rn(v - __half2float(hi));
}
__device__ __forceinline__ uint32_t pack2h(float x, float y) {
    __half2 p; p.x = __float2half_rn(x); p.y = __float2half_rn(y);
    return *(uint32_t*)&p;
}
__device__ __forceinline__ void pack_split_h(float x, float y, uint32_t& hp, uint32_t& lp) {
    __half hx, lx, hy, ly;
    split_h(x, hx, lx); split_h(y, hy, ly);
    __half2 h2; h2.x = hx; h2.y = hy;
    __half2 l2; l2.x = lx; l2.y = ly;
    hp = *(uint32_t*)&h2; lp = *(uint32_t*)&l2;
}
__device__ __forceinline__ float warp_sum(float v) {
    #pragma unroll
    for (int o = 16; o > 0; o >>= 1) v += __shfl_xor_sync(0xffffffffu, v, o);
    return v;
}

#define CP16(dst, src) \
    asm volatile("cp.async.cg.shared.global [%0], [%1], 16;" :: "r"(dst), "l"(src))
#define CP_COMMIT() asm volatile("cp.async.commit_group;")
#define CP_WAIT(n)  asm volatile("cp.async.wait_group %0;" :: "n"(n))

#define LDSM_X4(r0, r1, r2, r3, a) \
    asm volatile("ldmatrix.sync.aligned.m8n8.x4.shared.b16 {%0,%1,%2,%3}, [%4];" \
                 : "=r"(r0), "=r"(r1), "=r"(r2), "=r"(r3) : "r"(a))
#define LDSM_X2(r0, r1, a) \
    asm volatile("ldmatrix.sync.aligned.m8n8.x2.shared.b16 {%0,%1}, [%2];" \
                 : "=r"(r0), "=r"(r1) : "r"(a))
#define LDSM_X2_T(r0, r1, a) \
    asm volatile("ldmatrix.sync.aligned.m8n8.x2.trans.shared.b16 {%0,%1}, [%2];" \
                 : "=r"(r0), "=r"(r1) : "r"(a))
#define MMA16816(d, a0, a1, a2, a3, b0, b1) \
    asm volatile("mma.sync.aligned.m16n8k16.row.col.f32.f16.f16.f32 " \
                 "{%0,%1,%2,%3},{%4,%5,%6,%7},{%8,%9},{%0,%1,%2,%3};" \
                 : "+f"((d)[0]), "+f"((d)[1]), "+f"((d)[2]), "+f"((d)[3]) \
                 : "r"(a0), "r"(a1), "r"(a2), "r"(a3), "r"(b0), "r"(b1))

// gemm smem: 128 rows x 64 fp16 (128B) padded to 144B; 3 matrices per stage
#define TSTRIDE 144
#define MATBYTES 18432
#define STAGEBYTES 55296
#define SMEM_GEMM (2*STAGEBYTES)

// flash smem: rows of 64 fp16 (128B) padded to 144B
#define FSTR 144
#define QOFF_H 0
#define QOFF_L 9216
#define KOFF   18432
#define VOFF   36864
#define SMEM_FLASH 55296

// ---------------- fused weight transpose + fp16 convert ----------------------
#define TILES_PER_LAYER 6912
__global__ void wsplit_all_kernel(const float* __restrict__ attn_w, const float* __restrict__ proj_w,
                                  const float* __restrict__ fc_w,   const float* __restrict__ fc2_w,
                                  __half* __restrict__ tah, __half* __restrict__ tph,
                                  __half* __restrict__ tfh, __half* __restrict__ t2h) {
    __shared__ float t[32][33];
    int bid = blockIdx.x;
    int l = bid / TILES_PER_LAYER;
    int r = bid % TILES_PER_LAYER;
    const float* W; __half* Oh; int K, N, tile;
    if (r < 1728)      { W = attn_w; Oh = tah; K = D_;  N = D3_; tile = r; }
    else if (r < 2304) { W = proj_w; Oh = tph; K = D_;  N = D_;  tile = r - 1728; }
    else if (r < 4608) { W = fc_w;   Oh = tfh; K = D_;  N = DF_; tile = r - 2304; }
    else               { W = fc2_w;  Oh = t2h; K = DF_; N = D_;  tile = r - 4608; }
    int nx = N >> 5;
    int n0 = (tile % nx) << 5, k0 = (tile / nx) << 5;
    const float* Wl = W + (size_t)l * K * N;
    __half* OhL = Oh + (size_t)l * K * N;
    int tx = threadIdx.x, ty = threadIdx.y;    // (32,8)
    for (int i = ty; i < 32; i += 8)
        t[i][tx] = Wl[(size_t)(k0 + i) * N + n0 + tx];
    __syncthreads();
    for (int i = ty; i < 32; i += 8)
        OhL[(size_t)(n0 + i) * K + k0 + tx] = __float2half_rn(t[tx][i]);
}

// ---------------- warp-per-row layernorms -------------------------------------
#define LNROWS 8
__global__ void embed_ln_kernel(const int* __restrict__ ids, const int* __restrict__ rfi,
                                const float* __restrict__ wte, const float* __restrict__ wte_rf,
                                const float* __restrict__ wpe,
                                const float* __restrict__ g, const float* __restrict__ b,
                                float* __restrict__ h,
                                __half* __restrict__ yh, __half* __restrict__ yl) {
    int w = threadIdx.x >> 5, lane = threadIdx.x & 31;
    int row = blockIdx.x * LNROWS + w;
    int s = row & (S_ - 1);
    const float* e1 = wte    + (size_t)ids[row] * D_;
    const float* e2 = wte_rf + (size_t)rfi[row] * D_;
    const float* e3 = wpe    + (size_t)s * D_;
    float* hr = h + (size_t)row * D_;
    float v[24];
    float sum = 0.f;
    #pragma unroll
    for (int i = 0; i < 24; i++) {
        int c = lane + (i << 5);
        float x = e1[c] + e2[c] + e3[c];
        hr[c] = x;
        v[i] = x; sum += x;
    }
    sum = warp_sum(sum);
    float mu = sum * (1.0f / D_);
    float q = 0.f;
    #pragma unroll
    for (int i = 0; i < 24; i++) { v[i] -= mu; q += v[i] * v[i]; }
    q = warp_sum(q);
    float inv = rsqrtf(q * (1.0f / D_) + 1e-5f);
    size_t base = (size_t)row * D_;
    #pragma unroll
    for (int i = 0; i < 24; i++) {
        int c = lane + (i << 5);
        float r = v[i] * inv * g[c] + b[c];
        __half hi, lo; split_h(r, hi, lo);
        yh[base + c] = hi; yl[base + c] = lo;
    }
}

// ln_sum: v = x + t0 + t1 + t2 + gbias; optionally write h; LN(v) -> (yh,yl)/y.
template<bool HF>
__global__ void ln_sum_kernel(const float* __restrict__ x, const float* __restrict__ t,
                              const float* __restrict__ gb,
                              const float* __restrict__ g, const float* __restrict__ b,
                              float* __restrict__ hout, float* __restrict__ y,
                              __half* __restrict__ yh, __half* __restrict__ yl) {
    int w = threadIdx.x >> 5, lane = threadIdx.x & 31;
    int row = blockIdx.x * LNROWS + w;
    size_t base = (size_t)row * D_;
    const float* t0 = t + base;
    const float* t1 = t + (size_t)NT_ * D_ + base;
    const float* t2 = t + (size_t)2 * NT_ * D_ + base;
    const float* xr = x + base;
    float v[24];
    float sum = 0.f;
    #pragma unroll
    for (int i = 0; i < 24; i++) {
        int c = lane + (i << 5);
        float val = xr[c] + t0[c] + t1[c] + t2[c] + gb[c];
        if (hout) hout[base + c] = val;
        v[i] = val; sum += val;
    }
    sum = warp_sum(sum);
    float mu = sum * (1.0f / D_);
    float q = 0.f;
    #pragma unroll
    for (int i = 0; i < 24; i++) { v[i] -= mu; q += v[i] * v[i]; }
    q = warp_sum(q);
    float inv = rsqrtf(q * (1.0f / D_) + 1e-5f);
    #pragma unroll
    for (int i = 0; i < 24; i++) {
        int c = lane + (i << 5);
        float r = v[i] * inv * g[c] + b[c];
        if (HF) {
            __half hi, lo; split_h(r, hi, lo);
            yh[base + c] = hi; yl[base + c] = lo;
        } else {
            y[base + c] = r;
        }
    }
}

// ---------------- mma.sync GEMM (fp16, K-chunk 64) ----------------------------
// PASSES=2: acc = Ah*Bh + Al*Bh.  PASSES=1: acc = Ah*Bh (QKV only).
// EPI 2: Ch/Cl = split(gelu(acc+bias)).  EPI 3: head-major Q(hi/lo) K V.
// EPI 4: split-K partial: Cf[z] = raw acc, z = blockIdx.z.
template<int EPI, int PASSES>
__global__ void __launch_bounds__(256, 2)
gemm_mma(const __half* __restrict__ Ah, const __half* __restrict__ Al,
         const __half* __restrict__ Bh,
         const float* __restrict__ bias, const float* __restrict__ resid,
         float* __restrict__ Cf, __half* __restrict__ Ch, __half* __restrict__ Cl,
         __half* __restrict__ Qh_, __half* __restrict__ Ql_,
         __half* __restrict__ Kh_, __half* __restrict__ Vh_,
         int M, int N, int K, int Ktot) {
    extern __shared__ char smem[];
    uint32_t sbase = smem_u32(smem);
    int tid = threadIdx.x;
    int wid = tid >> 5, lane = tid & 31;
    int wm = wid >> 2, wn = wid & 3;
    int m0 = blockIdx.y << 7, n0 = blockIdx.x << 7;
    int ldb = Ktot * 2;
    int kz = (EPI == 4) ? blockIdx.z : 0;
    size_t koff0 = (size_t)kz * K;
    if (EPI == 4) Cf += (size_t)kz * ((size_t)M * N);

    const char* srcs[3];
    srcs[0] = (const char*)(Ah + (size_t)m0 * Ktot + koff0);
    srcs[1] = (const char*)(Al + (size_t)m0 * Ktot + koff0);
    srcs[2] = (const char*)(Bh + (size_t)n0 * Ktot + koff0);

    float acc[4][4][4] = {};
    int nk = K >> 6;

    // PASSES==1: load A-hi into mat slot 0 and B into slot 2 only (skip Al).
#define PREFETCH(c, s)                                                        \
    {                                                                         \
        size_t ko = (size_t)(c) << 7;                                         \
        uint32_t stb = sbase + (s) * STAGEBYTES;                              \
        _Pragma("unroll")                                                     \
        for (int j = 0; j < (PASSES == 2 ? 12 : 8); j++) {                    \
            int q = tid + j * 256;                                            \
            int mat = q >> 10, w = q & 1023, row = w >> 3, cc = w & 7;        \
            if (PASSES == 1 && mat == 1) mat = 2;                             \
            uint32_t dst = stb + mat * MATBYTES + row * TSTRIDE + cc * 16;    \
            const char* sp = srcs[mat] + (size_t)row * ldb + ko + cc * 16;    \
            CP16(dst, sp);                                                    \
        }                                                                     \
        CP_COMMIT();                                                          \
    }

    PREFETCH(0, 0);

    int aRow = wm * 64 + (lane & 7) + ((lane >> 3) & 1) * 8;
    uint32_t aKoff = ((lane >> 4) & 1) * 16;
    int lb = lane & 15;
    int bRow = wn * 32 + (lb & 7);
    uint32_t bKoff = ((lb >> 3) & 1) * 16;

    for (int c = 0; c < nk; c++) {
        int s = c & 1;
        if (c + 1 < nk) PREFETCH(c + 1, s ^ 1);
        if (c + 1 < nk) { CP_WAIT(1); } else { CP_WAIT(0); }
        __syncthreads();

        uint32_t stb = sbase + s * STAGEBYTES;
        #pragma unroll
        for (int kk = 0; kk < 4; kk++) {
            uint32_t bh[4][2];
            #pragma unroll
            for (int nj = 0; nj < 4; nj++) {
                uint32_t addr = stb + 2 * MATBYTES + (bRow + nj * 8) * TSTRIDE + kk * 32 + bKoff;
                LDSM_X2(bh[nj][0], bh[nj][1], addr);
            }
            uint32_t af[4][4];
            #pragma unroll
            for (int mi = 0; mi < 4; mi++) {
                uint32_t addr = stb + (aRow + mi * 16) * TSTRIDE + kk * 32 + aKoff;
                LDSM_X4(af[mi][0], af[mi][1], af[mi][2], af[mi][3], addr);
            }
            #pragma unroll
            for (int mi = 0; mi < 4; mi++)
                #pragma unroll
                for (int nj = 0; nj < 4; nj++)
                    MMA16816(acc[mi][nj], af[mi][0], af[mi][1], af[mi][2], af[mi][3],
                             bh[nj][0], bh[nj][1]);
            if (PASSES == 2) {
                #pragma unroll
                for (int mi = 0; mi < 4; mi++) {
                    uint32_t addr = stb + MATBYTES + (aRow + mi * 16) * TSTRIDE + kk * 32 + aKoff;
                    LDSM_X4(af[mi][0], af[mi][1], af[mi][2], af[mi][3], addr);
                }
                #pragma unroll
                for (int mi = 0; mi < 4; mi++)
                    #pragma unroll
                    for (int nj = 0; nj < 4; nj++)
                        MMA16816(acc[mi][nj], af[mi][0], af[mi][1], af[mi][2], af[mi][3],
                                 bh[nj][0], bh[nj][1]);
            }
        }
        __syncthreads();
    }

    int rbase = m0 + wm * 64 + (lane >> 2);
    int cbase = n0 + wn * 32 + (lane & 3) * 2;
    #pragma unroll
    for (int mi = 0; mi < 4; mi++) {
        #pragma unroll
        for (int nj = 0; nj < 4; nj++) {
            int r = rbase + mi * 16;
            int col = cbase + nj * 8;
            float b0 = (EPI == 4) ? 0.f : bias[col];
            float b1 = (EPI == 4) ? 0.f : bias[col + 1];
            float v00 = acc[mi][nj][0] + b0, v01 = acc[mi][nj][1] + b1;
            float v10 = acc[mi][nj][2] + b0, v11 = acc[mi][nj][3] + b1;
            size_t i0 = (size_t)r * N + col;
            size_t i1 = (size_t)(r + 8) * N + col;
            if (EPI == 4) {
                *(float2*)&Cf[i0] = make_float2(v00, v01);
                *(float2*)&Cf[i1] = make_float2(v10, v11);
            } else if (EPI == 2) {
                v00 = gelu_f(v00); v01 = gelu_f(v01);
                v10 = gelu_f(v10); v11 = gelu_f(v11);
                uint32_t hp, lp;
                pack_split_h(v00, v01, hp, lp);
                *(uint32_t*)&Ch[i0] = hp; *(uint32_t*)&Cl[i0] = lp;
                pack_split_h(v10, v11, hp, lp);
                *(uint32_t*)&Ch[i1] = hp; *(uint32_t*)&Cl[i1] = lp;
            } else {
                int which = col / D_;
                int hh = (col % D_) / DH_;
                int dd = col % DH_;
                int bi = r >> 10, si = r & 1023;
                size_t j0 = (((size_t)(bi * H_ + hh)) * S_ + si) * DH_ + dd;
                size_t j1 = j0 + 8 * DH_;
                if (which == 0) {
                    uint32_t hp, lp;
                    pack_split_h(v00, v01, hp, lp);
                    *(uint32_t*)&Qh_[j0] = hp; *(uint32_t*)&Ql_[j0] = lp;
                    pack_split_h(v10, v11, hp, lp);
                    *(uint32_t*)&Qh_[j1] = hp; *(uint32_t*)&Ql_[j1] = lp;
                } else {
                    __half* d_ = which == 1 ? Kh_ : Vh_;
                    *(uint32_t*)&d_[j0] = pack2h(v00, v01);
                    *(uint32_t*)&d_[j1] = pack2h(v10, v11);
                }
            }
        }
    }
#undef PREFETCH
}

// ---------------- fused flash attention (64-row Q, single KV buffer) ----------
__global__ void __launch_bounds__(128)
flash_kernel(const __half* __restrict__ qh, const __half* __restrict__ ql,
             const __half* __restrict__ kh, const __half* __restrict__ vh,
             __half* __restrict__ oh, __half* __restrict__ ol) {
    extern __shared__ char fsm[];
    uint32_t sb = smem_u32(fsm);
    int bh = blockIdx.y;
    int q0 = (gridDim.x - 1 - blockIdx.x) << 6;   // long CTAs first
    int tid = threadIdx.x, wid = tid >> 5, lane = tid & 31;

    {   // Q tile load (64 rows x 128B), hi+lo
        const char* srcH = (const char*)(qh + ((size_t)bh * S_ + q0) * DH_);
        const char* srcL = (const char*)(ql + ((size_t)bh * S_ + q0) * DH_);
        #pragma unroll
        for (int i = tid; i < 512; i += 128) {
            int r = i >> 3, c = (i & 7) << 4;
            CP16(sb + QOFF_H + r * FSTR + c, srcH + r * 128 + c);
            CP16(sb + QOFF_L + r * FSTR + c, srcL + r * 128 + c);
        }
        CP_COMMIT();
    }

    float m0 = -1e30f, m1 = -1e30f, l0 = 0.f, l1 = 0.f;
    float oacc[8][4];
    #pragma unroll
    for (int d = 0; d < 8; d++)
        oacc[d][0] = oacc[d][1] = oacc[d][2] = oacc[d][3] = 0.f;

    int rA = q0 + wid * 16 + (lane >> 2);
    int nj = (q0 >> 7) + 1;

    uint32_t aAddrBase = sb + (wid * 16 + (lane & 15)) * FSTR + (((lane >> 4) & 1) << 4);
    uint32_t bRowOff = (uint32_t)((lane & 7) * FSTR) + (((lane >> 3) & 1) << 4);

    for (int j = 0; j < nj; j++) {
        __syncthreads();
        {   // K/V tile load (128 rows x 128B)
            const char* kH = (const char*)(kh + ((size_t)bh * S_ + (j << 7)) * DH_);
            const char* vH = (const char*)(vh + ((size_t)bh * S_ + (j << 7)) * DH_);
            #pragma unroll
            for (int i = tid; i < 1024; i += 128) {
                int r = i >> 3, c = (i & 7) << 4;
                uint32_t so = r * FSTR + c;
                size_t go = (size_t)r * 128 + c;
                CP16(sb + KOFF + so, kH + go);
                CP16(sb + VOFF + so, vH + go);
            }
            CP_COMMIT();
            CP_WAIT(0);
        }
        __syncthreads();

        float sf[16][4];
        #pragma unroll
        for (int nt = 0; nt < 16; nt++)
            sf[nt][0] = sf[nt][1] = sf[nt][2] = sf[nt][3] = 0.f;

        #pragma unroll
        for (int kc = 0; kc < 4; kc++) {
            uint32_t qa = aAddrBase + kc * 32;
            uint32_t q_h0,q_h1,q_h2,q_h3, q_l0,q_l1,q_l2,q_l3;
            LDSM_X4(q_h0,q_h1,q_h2,q_h3, qa + QOFF_H);
            LDSM_X4(q_l0,q_l1,q_l2,q_l3, qa + QOFF_L);
            #pragma unroll
            for (int nt = 0; nt < 16; nt++) {
                uint32_t ka = sb + KOFF + nt * 8 * FSTR + bRowOff + kc * 32;
                uint32_t k_h0,k_h1;
                LDSM_X2(k_h0,k_h1, ka);
                MMA16816(sf[nt], q_h0,q_h1,q_h2,q_h3, k_h0,k_h1);
                MMA16816(sf[nt], q_l0,q_l1,q_l2,q_l3, k_h0,k_h1);
            }
        }

        int cb = (j << 7) + (lane & 3) * 2;
        float mx0 = -1e30f, mx1 = -1e30f;
        #pragma unroll
        for (int nt = 0; nt < 16; nt++) {
            int c0 = cb + nt * 8;
            sf[nt][0] = (c0     <= rA)     ? sf[nt][0] * 0.125f : -1e30f;
            sf[nt][1] = (c0 + 1 <= rA)     ? sf[nt][1] * 0.125f : -1e30f;
            sf[nt][2] = (c0     <= rA + 8) ? sf[nt][2] * 0.125f : -1e30f;
            sf[nt][3] = (c0 + 1 <= rA + 8) ? sf[nt][3] * 0.125f : -1e30f;
            mx0 = fmaxf(mx0, fmaxf(sf[nt][0], sf[nt][1]));
            mx1 = fmaxf(mx1, fmaxf(sf[nt][2], sf[nt][3]));
        }
        mx0 = fmaxf(mx0, __shfl_xor_sync(0xffffffffu, mx0, 1));
        mx0 = fmaxf(mx0, __shfl_xor_sync(0xffffffffu, mx0, 2));
        mx1 = fmaxf(mx1, __shfl_xor_sync(0xffffffffu, mx1, 1));
        mx1 = fmaxf(mx1, __shfl_xor_sync(0xffffffffu, mx1, 2));
        float mn0 = fmaxf(m0, mx0), mn1 = fmaxf(m1, mx1);
        float sc0 = expf(m0 - mn0), sc1 = expf(m1 - mn1);
        m0 = mn0; m1 = mn1;
        l0 *= sc0; l1 *= sc1;
        #pragma unroll
        for (int d = 0; d < 8; d++) {
            oacc[d][0] *= sc0; oacc[d][1] *= sc0;
            oacc[d][2] *= sc1; oacc[d][3] *= sc1;
        }
        float s0 = 0.f, s1 = 0.f;
        uint32_t ph[16][2], pl[16][2];
        #pragma unroll
        for (int nt = 0; nt < 16; nt++) {
            float p0 = expf(sf[nt][0] - m0), p1 = expf(sf[nt][1] - m0);
            float p2 = expf(sf[nt][2] - m1), p3 = expf(sf[nt][3] - m1);
            s0 += p0 + p1; s1 += p2 + p3;
            pack_split_h(p0, p1, ph[nt][0], pl[nt][0]);
            pack_split_h(p2, p3, ph[nt][1], pl[nt][1]);
        }
        s0 += __shfl_xor_sync(0xffffffffu, s0, 1);
        s0 += __shfl_xor_sync(0xffffffffu, s0, 2);
        s1 += __shfl_xor_sync(0xffffffffu, s1, 1);
        s1 += __shfl_xor_sync(0xffffffffu, s1, 2);
        l0 += s0; l1 += s1;

        #pragma unroll
        for (int kc = 0; kc < 8; kc++) {
            uint32_t va = sb + VOFF + (kc * 16 + (lane & 15)) * FSTR;
            #pragma unroll
            for (int dt = 0; dt < 8; dt++) {
                uint32_t v_h0,v_h1;
                LDSM_X2_T(v_h0,v_h1, va + dt * 16);
                MMA16816(oacc[dt], ph[2*kc][0], ph[2*kc][1], ph[2*kc+1][0], ph[2*kc+1][1], v_h0, v_h1);
                MMA16816(oacc[dt], pl[2*kc][0], pl[2*kc][1], pl[2*kc+1][0], pl[2*kc+1][1], v_h0, v_h1);
            }
        }
    }

    float inv0 = 1.f / l0, inv1 = 1.f / l1;
    int bb = bh / H_, hH = bh % H_;
    size_t baseA = ((size_t)bb * S_ + rA) * D_ + hH * DH_;
    size_t baseB = baseA + 8 * D_;
    #pragma unroll
    for (int dt = 0; dt < 8; dt++) {
        int c = dt * 8 + (lane & 3) * 2;
        uint32_t hp, lp;
        pack_split_h(oacc[dt][0] * inv0, oacc[dt][1] * inv0, hp, lp);
        *(uint32_t*)&oh[baseA + c] = hp;
        *(uint32_t*)&ol[baseA + c] = lp;
        pack_split_h(oacc[dt][2] * inv1, oacc[dt][3] * inv1, hp, lp);
        *(uint32_t*)&oh[baseB + c] = hp;
        *(uint32_t*)&ol[baseB + c] = lp;
    }
}

// ---------------- host orchestration -----------------------------------------
extern "C" void kernel_launch(void* const* d_in, const int* in_sizes, int n_in,
                              void* d_out, int out_size) {
    const int*   ids    = (const int*)d_in[0];
    const int*   rfi    = (const int*)d_in[1];
    const float* wte    = (const float*)d_in[2];
    const float* wte_rf = (const float*)d_in[3];
    const float* wpe    = (const float*)d_in[4];
    const float* ln1_g  = (const float*)d_in[5];
    const float* ln1_b  = (const float*)d_in[6];
    const float* attn_w = (const float*)d_in[7];
    const float* attn_b = (const float*)d_in[8];
    const float* proj_w = (const float*)d_in[9];
    const float* proj_b = (const float*)d_in[10];
    const float* ln2_g  = (const float*)d_in[11];
    const float* ln2_b  = (const float*)d_in[12];
    const float* fc_w   = (const float*)d_in[13];
    const float* fc_b   = (const float*)d_in[14];
    const float* fc2_w  = (const float*)d_in[15];
    const float* fc2_b  = (const float*)d_in[16];
    const float* lnf_g  = (const float*)d_in[17];
    const float* lnf_b  = (const float*)d_in[18];
    float* out = (float*)d_out;

    float *h, *tp;
    __half *ah, *al, *mh, *ml, *oh, *ol;
    __half *qh, *ql, *kh, *vh;
    __half *tah, *tph, *tfh, *t2h;
    cudaGetSymbolAddress((void**)&h,   g_h);
    cudaGetSymbolAddress((void**)&tp,  g_t);
    cudaGetSymbolAddress((void**)&ah,  g_ah);  cudaGetSymbolAddress((void**)&al,  g_al);
    cudaGetSymbolAddress((void**)&mh,  g_mh);  cudaGetSymbolAddress((void**)&ml,  g_ml);
    cudaGetSymbolAddress((void**)&oh,  g_oh);  cudaGetSymbolAddress((void**)&ol,  g_ol);
    cudaGetSymbolAddress((void**)&qh,  g_qh);  cudaGetSymbolAddress((void**)&ql,  g_ql);
    cudaGetSymbolAddress((void**)&kh,  g_kh);  cudaGetSymbolAddress((void**)&vh,  g_vh);
    cudaGetSymbolAddress((void**)&tah, t_attn_h);
    cudaGetSymbolAddress((void**)&tph, t_proj_h);
    cudaGetSymbolAddress((void**)&tfh, t_fc_h);
    cudaGetSymbolAddress((void**)&t2h, t_fc2_h);

    cudaFuncSetAttribute((const void*)gemm_mma<2,2>, cudaFuncAttributeMaxDynamicSharedMemorySize, SMEM_GEMM);
    cudaFuncSetAttribute((const void*)gemm_mma<3,1>, cudaFuncAttributeMaxDynamicSharedMemorySize, SMEM_GEMM);
    cudaFuncSetAttribute((const void*)gemm_mma<4,2>, cudaFuncAttributeMaxDynamicSharedMemorySize, SMEM_GEMM);
    cudaFuncSetAttribute(flash_kernel, cudaFuncAttributeMaxDynamicSharedMemorySize, SMEM_FLASH);

    wsplit_all_kernel<<<TILES_PER_LAYER * L_, dim3(32, 8)>>>(
        attn_w, proj_w, fc_w, fc2_w, tah, tph, tfh, t2h);
    embed_ln_kernel<<<NT_/LNROWS, 256>>>(ids, rfi, wte, wte_rf, wpe, ln1_g, ln1_b, h, ah, al);

    for (int l = 0; l < L_; l++) {
        // QKV: single-pass (Ah*Bh) — K,V round to fp16 anyway; Q keeps hi/lo.
        gemm_mma<3,1><<<dim3(D3_/128, NT_/128), 256, SMEM_GEMM>>>(
            ah, al, tah + (size_t)l * D3_ * D_,
            attn_b + l * D3_, nullptr, nullptr, nullptr, nullptr,
            qh, ql, kh, vh, NT_, D3_, D_, D_);
        flash_kernel<<<dim3(S_/64, B_*H_), 128, SMEM_FLASH>>>(qh, ql, kh, vh, oh, ol);
        gemm_mma<4,2><<<dim3(D_/128, NT_/128, SPLITK), 256, SMEM_GEMM>>>(
            oh, ol, tph + (size_t)l * D_ * D_,
            nullptr, nullptr, tp, nullptr, nullptr,
            nullptr, nullptr, nullptr, nullptr, NT_, D_, D_/SPLITK, D_);
        ln_sum_kernel<true><<<NT_/LNROWS, 256>>>(
            h, tp, proj_b + l * D_, ln2_g + l * D_, ln2_b + l * D_, h, nullptr, ah, al);
        gemm_mma<2,2><<<dim3(DF_/128, NT_/128), 256, SMEM_GEMM>>>(
            ah, al, tfh + (size_t)l * DF_ * D_,
            fc_b + l * DF_, nullptr, nullptr, mh, ml,
            nullptr, nullptr, nullptr, nullptr, NT_, DF_, D_, D_);
        gemm_mma<4,2><<<dim3(D_/128, NT_/128, SPLITK), 256, SMEM_GEMM>>>(
            mh, ml, t2h + (size_t)l * D_ * DF_,
            nullptr, nullptr, tp, nullptr, nullptr,
            nullptr, nullptr, nullptr, nullptr, NT_, D_, DF_/SPLITK, DF_);
        if (l < L_ - 1) {
            ln_sum_kernel<true><<<NT_/LNROWS, 256>>>(
                h, tp, fc2_b + l * D_, ln1_g + (l + 1) * D_, ln1_b + (l + 1) * D_,
                h, nullptr, ah, al);
        } else {
            ln_sum_kernel<false><<<NT_/LNROWS, 256>>>(
                h, tp, fc2_b + l * D_, lnf_g, lnf_b, nullptr, out, nullptr, nullptr);
        }
    }
}

// round 15
// speedup vs baseline: 1.4167x; 1.1704x over previous
#include <cuda_runtime.h>
#include <cuda_fp16.h>
#include <math.h>
#include <stdint.h>

#define B_  4
#define S_  1024
#define D_  768
#define H_  12
#define L_  6
#define DF_ 3072
#define DH_ 64
#define NT_ (B_*S_)        // 4096
#define D3_ (3*D_)         // 2304
#define SPLITK 3

// ---------------- scratch (static device globals) ----------------------------
static __device__ float g_h[NT_*D_];
static __device__ float g_t[(size_t)SPLITK*NT_*D_];     // split-K partials
static __device__ __half g_ah[NT_*D_],  g_al[NT_*D_];
static __device__ __half g_mh[NT_*DF_];
static __device__ __half g_oh[NT_*D_];
static __device__ __half g_qh[NT_*D_],  g_ql[NT_*D_];
static __device__ __half g_kh[NT_*D_];
static __device__ __half g_vh[NT_*D_];
static __device__ __half t_attn_h[(size_t)L_*D3_*D_];
static __device__ __half t_proj_h[(size_t)L_*D_*D_];
static __device__ __half t_fc_h[(size_t)L_*DF_*D_];
static __device__ __half t_fc2_h[(size_t)L_*D_*DF_];

// ---------------- helpers ----------------------------------------------------
__device__ __forceinline__ uint32_t smem_u32(const void* p) {
    uint32_t a;
    asm("{ .reg .u64 t; cvta.to.shared.u64 t, %1; cvt.u32.u64 %0, t; }" : "=r"(a) : "l"(p));
    return a;
}
__device__ __forceinline__ float gelu_f(float x) {
    const float c = 0.7978845608028654f;
    return 0.5f * x * (1.0f + tanhf(c * (x + 0.044715f * x * x * x)));
}
__device__ __forceinline__ void split_h(float v, __half& hi, __half& lo) {
    hi = __float2half_rn(v);
    lo = __float2half_rn(v - __half2float(hi));
}
__device__ __forceinline__ uint32_t pack2h(float x, float y) {
    __half2 p; p.x = __float2half_rn(x); p.y = __float2half_rn(y);
    return *(uint32_t*)&p;
}
__device__ __forceinline__ void pack_split_h(float x, float y, uint32_t& hp, uint32_t& lp) {
    __half hx, lx, hy, ly;
    split_h(x, hx, lx); split_h(y, hy, ly);
    __half2 h2; h2.x = hx; h2.y = hy;
    __half2 l2; l2.x = lx; l2.y = ly;
    hp = *(uint32_t*)&h2; lp = *(uint32_t*)&l2;
}
__device__ __forceinline__ float warp_sum(float v) {
    #pragma unroll
    for (int o = 16; o > 0; o >>= 1) v += __shfl_xor_sync(0xffffffffu, v, o);
    return v;
}

#define CP16(dst, src) \
    asm volatile("cp.async.cg.shared.global [%0], [%1], 16;" :: "r"(dst), "l"(src))
#define CP_COMMIT() asm volatile("cp.async.commit_group;")
#define CP_WAIT(n)  asm volatile("cp.async.wait_group %0;" :: "n"(n))

#define LDSM_X4(r0, r1, r2, r3, a) \
    asm volatile("ldmatrix.sync.aligned.m8n8.x4.shared.b16 {%0,%1,%2,%3}, [%4];" \
                 : "=r"(r0), "=r"(r1), "=r"(r2), "=r"(r3) : "r"(a))
#define LDSM_X2(r0, r1, a) \
    asm volatile("ldmatrix.sync.aligned.m8n8.x2.shared.b16 {%0,%1}, [%2];" \
                 : "=r"(r0), "=r"(r1) : "r"(a))
#define LDSM_X2_T(r0, r1, a) \
    asm volatile("ldmatrix.sync.aligned.m8n8.x2.trans.shared.b16 {%0,%1}, [%2];" \
                 : "=r"(r0), "=r"(r1) : "r"(a))
#define MMA16816(d, a0, a1, a2, a3, b0, b1) \
    asm volatile("mma.sync.aligned.m16n8k16.row.col.f32.f16.f16.f32 " \
                 "{%0,%1,%2,%3},{%4,%5,%6,%7},{%8,%9},{%0,%1,%2,%3};" \
                 : "+f"((d)[0]), "+f"((d)[1]), "+f"((d)[2]), "+f"((d)[3]) \
                 : "r"(a0), "r"(a1), "r"(a2), "r"(a3), "r"(b0), "r"(b1))

// gemm smem: 128 rows x 64 fp16 (128B) padded to 144B; 3 matrices per stage
#define TSTRIDE 144
#define MATBYTES 18432
#define STAGEBYTES 55296
#define SMEM_GEMM (2*STAGEBYTES)

// flash smem: rows of 64 fp16 (128B) padded to 144B
#define FSTR 144
#define QOFF_H 0
#define QOFF_L 9216
#define KOFF   18432
#define VOFF   36864
#define SMEM_FLASH 55296

// ---------------- fused weight transpose + fp16 convert ----------------------
#define TILES_PER_LAYER 6912
__global__ void wsplit_all_kernel(const float* __restrict__ attn_w, const float* __restrict__ proj_w,
                                  const float* __restrict__ fc_w,   const float* __restrict__ fc2_w,
                                  __half* __restrict__ tah, __half* __restrict__ tph,
                                  __half* __restrict__ tfh, __half* __restrict__ t2h) {
    __shared__ float t[32][33];
    int bid = blockIdx.x;
    int l = bid / TILES_PER_LAYER;
    int r = bid % TILES_PER_LAYER;
    const float* W; __half* Oh; int K, N, tile;
    if (r < 1728)      { W = attn_w; Oh = tah; K = D_;  N = D3_; tile = r; }
    else if (r < 2304) { W = proj_w; Oh = tph; K = D_;  N = D_;  tile = r - 1728; }
    else if (r < 4608) { W = fc_w;   Oh = tfh; K = D_;  N = DF_; tile = r - 2304; }
    else               { W = fc2_w;  Oh = t2h; K = DF_; N = D_;  tile = r - 4608; }
    int nx = N >> 5;
    int n0 = (tile % nx) << 5, k0 = (tile / nx) << 5;
    const float* Wl = W + (size_t)l * K * N;
    __half* OhL = Oh + (size_t)l * K * N;
    int tx = threadIdx.x, ty = threadIdx.y;    // (32,8)
    for (int i = ty; i < 32; i += 8)
        t[i][tx] = Wl[(size_t)(k0 + i) * N + n0 + tx];
    __syncthreads();
    for (int i = ty; i < 32; i += 8)
        OhL[(size_t)(n0 + i) * K + k0 + tx] = __float2half_rn(t[tx][i]);
}

// ---------------- warp-per-row layernorms -------------------------------------
#define LNROWS 8
__global__ void embed_ln_kernel(const int* __restrict__ ids, const int* __restrict__ rfi,
                                const float* __restrict__ wte, const float* __restrict__ wte_rf,
                                const float* __restrict__ wpe,
                                const float* __restrict__ g, const float* __restrict__ b,
                                float* __restrict__ h,
                                __half* __restrict__ yh, __half* __restrict__ yl) {
    int w = threadIdx.x >> 5, lane = threadIdx.x & 31;
    int row = blockIdx.x * LNROWS + w;
    int s = row & (S_ - 1);
    const float* e1 = wte    + (size_t)ids[row] * D_;
    const float* e2 = wte_rf + (size_t)rfi[row] * D_;
    const float* e3 = wpe    + (size_t)s * D_;
    float* hr = h + (size_t)row * D_;
    float v[24];
    float sum = 0.f;
    #pragma unroll
    for (int i = 0; i < 24; i++) {
        int c = lane + (i << 5);
        float x = e1[c] + e2[c] + e3[c];
        hr[c] = x;
        v[i] = x; sum += x;
    }
    sum = warp_sum(sum);
    float mu = sum * (1.0f / D_);
    float q = 0.f;
    #pragma unroll
    for (int i = 0; i < 24; i++) { v[i] -= mu; q += v[i] * v[i]; }
    q = warp_sum(q);
    float inv = rsqrtf(q * (1.0f / D_) + 1e-5f);
    size_t base = (size_t)row * D_;
    #pragma unroll
    for (int i = 0; i < 24; i++) {
        int c = lane + (i << 5);
        float r = v[i] * inv * g[c] + b[c];
        __half hi, lo; split_h(r, hi, lo);
        yh[base + c] = hi; yl[base + c] = lo;
    }
}

// ln_sum: v = x + t0 + t1 + t2 + gbias; optionally write h; LN(v) -> (yh,yl)/y.
template<bool HF>
__global__ void ln_sum_kernel(const float* __restrict__ x, const float* __restrict__ t,
                              const float* __restrict__ gb,
                              const float* __restrict__ g, const float* __restrict__ b,
                              float* __restrict__ hout, float* __restrict__ y,
                              __half* __restrict__ yh, __half* __restrict__ yl) {
    int w = threadIdx.x >> 5, lane = threadIdx.x & 31;
    int row = blockIdx.x * LNROWS + w;
    size_t base = (size_t)row * D_;
    const float* t0 = t + base;
    const float* t1 = t + (size_t)NT_ * D_ + base;
    const float* t2 = t + (size_t)2 * NT_ * D_ + base;
    const float* xr = x + base;
    float v[24];
    float sum = 0.f;
    #pragma unroll
    for (int i = 0; i < 24; i++) {
        int c = lane + (i << 5);
        float val = xr[c] + t0[c] + t1[c] + t2[c] + gb[c];
        if (hout) hout[base + c] = val;
        v[i] = val; sum += val;
    }
    sum = warp_sum(sum);
    float mu = sum * (1.0f / D_);
    float q = 0.f;
    #pragma unroll
    for (int i = 0; i < 24; i++) { v[i] -= mu; q += v[i] * v[i]; }
    q = warp_sum(q);
    float inv = rsqrtf(q * (1.0f / D_) + 1e-5f);
    #pragma unroll
    for (int i = 0; i < 24; i++) {
        int c = lane + (i << 5);
        float r = v[i] * inv * g[c] + b[c];
        if (HF) {
            __half hi, lo; split_h(r, hi, lo);
            yh[base + c] = hi; yl[base + c] = lo;
        } else {
            y[base + c] = r;
        }
    }
}

// ---------------- mma.sync GEMM (fp16, K-chunk 64) ----------------------------
// PASSES=2: acc = Ah*Bh + Al*Bh.  PASSES=1: acc = Ah*Bh.
// EPI 2: Ch = fp16(gelu(acc+bias)).  EPI 3: head-major Q(hi/lo) K V.
// EPI 4: split-K partial: Cf[z] = raw acc, z = blockIdx.z.
template<int EPI, int PASSES>
__global__ void __launch_bounds__(256, 2)
gemm_mma(const __half* __restrict__ Ah, const __half* __restrict__ Al,
         const __half* __restrict__ Bh,
         const float* __restrict__ bias, const float* __restrict__ resid,
         float* __restrict__ Cf, __half* __restrict__ Ch, __half* __restrict__ Cl,
         __half* __restrict__ Qh_, __half* __restrict__ Ql_,
         __half* __restrict__ Kh_, __half* __restrict__ Vh_,
         int M, int N, int K, int Ktot) {
    extern __shared__ char smem[];
    uint32_t sbase = smem_u32(smem);
    int tid = threadIdx.x;
    int wid = tid >> 5, lane = tid & 31;
    int wm = wid >> 2, wn = wid & 3;
    int m0 = blockIdx.y << 7, n0 = blockIdx.x << 7;
    int ldb = Ktot * 2;
    int kz = (EPI == 4) ? blockIdx.z : 0;
    size_t koff0 = (size_t)kz * K;
    if (EPI == 4) Cf += (size_t)kz * ((size_t)M * N);

    const char* srcs[3];
    srcs[0] = (const char*)(Ah + (size_t)m0 * Ktot + koff0);
    srcs[1] = (const char*)(Al + (size_t)m0 * Ktot + koff0);
    srcs[2] = (const char*)(Bh + (size_t)n0 * Ktot + koff0);

    float acc[4][4][4] = {};
    int nk = K >> 6;

#define PREFETCH(c, s)                                                        \
    {                                                                         \
        size_t ko = (size_t)(c) << 7;                                         \
        uint32_t stb = sbase + (s) * STAGEBYTES;                              \
        _Pragma("unroll")                                                     \
        for (int j = 0; j < (PASSES == 2 ? 12 : 8); j++) {                    \
            int q = tid + j * 256;                                            \
            int mat = q >> 10, w = q & 1023, row = w >> 3, cc = w & 7;        \
            if (PASSES == 1 && mat == 1) mat = 2;                             \
            uint32_t dst = stb + mat * MATBYTES + row * TSTRIDE + cc * 16;    \
            const char* sp = srcs[mat] + (size_t)row * ldb + ko + cc * 16;    \
            CP16(dst, sp);                                                    \
        }                                                                     \
        CP_COMMIT();                                                          \
    }

    PREFETCH(0, 0);

    int aRow = wm * 64 + (lane & 7) + ((lane >> 3) & 1) * 8;
    uint32_t aKoff = ((lane >> 4) & 1) * 16;
    int lb = lane & 15;
    int bRow = wn * 32 + (lb & 7);
    uint32_t bKoff = ((lb >> 3) & 1) * 16;

    for (int c = 0; c < nk; c++) {
        int s = c & 1;
        if (c + 1 < nk) PREFETCH(c + 1, s ^ 1);
        if (c + 1 < nk) { CP_WAIT(1); } else { CP_WAIT(0); }
        __syncthreads();

        uint32_t stb = sbase + s * STAGEBYTES;
        #pragma unroll
        for (int kk = 0; kk < 4; kk++) {
            uint32_t bh[4][2];
            #pragma unroll
            for (int nj = 0; nj < 4; nj++) {
                uint32_t addr = stb + 2 * MATBYTES + (bRow + nj * 8) * TSTRIDE + kk * 32 + bKoff;
                LDSM_X2(bh[nj][0], bh[nj][1], addr);
            }
            uint32_t af[4][4];
            #pragma unroll
            for (int mi = 0; mi < 4; mi++) {
                uint32_t addr = stb + (aRow + mi * 16) * TSTRIDE + kk * 32 + aKoff;
                LDSM_X4(af[mi][0], af[mi][1], af[mi][2], af[mi][3], addr);
            }
            #pragma unroll
            for (int mi = 0; mi < 4; mi++)
                #pragma unroll
                for (int nj = 0; nj < 4; nj++)
                    MMA16816(acc[mi][nj], af[mi][0], af[mi][1], af[mi][2], af[mi][3],
                             bh[nj][0], bh[nj][1]);
            if (PASSES == 2) {
                #pragma unroll
                for (int mi = 0; mi < 4; mi++) {
                    uint32_t addr = stb + MATBYTES + (aRow + mi * 16) * TSTRIDE + kk * 32 + aKoff;
                    LDSM_X4(af[mi][0], af[mi][1], af[mi][2], af[mi][3], addr);
                }
                #pragma unroll
                for (int mi = 0; mi < 4; mi++)
                    #pragma unroll
                    for (int nj = 0; nj < 4; nj++)
                        MMA16816(acc[mi][nj], af[mi][0], af[mi][1], af[mi][2], af[mi][3],
                                 bh[nj][0], bh[nj][1]);
            }
        }
        __syncthreads();
    }

    int rbase = m0 + wm * 64 + (lane >> 2);
    int cbase = n0 + wn * 32 + (lane & 3) * 2;
    #pragma unroll
    for (int mi = 0; mi < 4; mi++) {
        #pragma unroll
        for (int nj = 0; nj < 4; nj++) {
            int r = rbase + mi * 16;
            int col = cbase + nj * 8;
            float b0 = (EPI == 4) ? 0.f : bias[col];
            float b1 = (EPI == 4) ? 0.f : bias[col + 1];
            float v00 = acc[mi][nj][0] + b0, v01 = acc[mi][nj][1] + b1;
            float v10 = acc[mi][nj][2] + b0, v11 = acc[mi][nj][3] + b1;
            size_t i0 = (size_t)r * N + col;
            size_t i1 = (size_t)(r + 8) * N + col;
            if (EPI == 4) {
                *(float2*)&Cf[i0] = make_float2(v00, v01);
                *(float2*)&Cf[i1] = make_float2(v10, v11);
            } else if (EPI == 2) {
                v00 = gelu_f(v00); v01 = gelu_f(v01);
                v10 = gelu_f(v10); v11 = gelu_f(v11);
                *(uint32_t*)&Ch[i0] = pack2h(v00, v01);
                *(uint32_t*)&Ch[i1] = pack2h(v10, v11);
            } else {
                int which = col / D_;
                int hh = (col % D_) / DH_;
                int dd = col % DH_;
                int bi = r >> 10, si = r & 1023;
                size_t j0 = (((size_t)(bi * H_ + hh)) * S_ + si) * DH_ + dd;
                size_t j1 = j0 + 8 * DH_;
                if (which == 0) {
                    uint32_t hp, lp;
                    pack_split_h(v00, v01, hp, lp);
                    *(uint32_t*)&Qh_[j0] = hp; *(uint32_t*)&Ql_[j0] = lp;
                    pack_split_h(v10, v11, hp, lp);
                    *(uint32_t*)&Qh_[j1] = hp; *(uint32_t*)&Ql_[j1] = lp;
                } else {
                    __half* d_ = which == 1 ? Kh_ : Vh_;
                    *(uint32_t*)&d_[j0] = pack2h(v00, v01);
                    *(uint32_t*)&d_[j1] = pack2h(v10, v11);
                }
            }
        }
    }
#undef PREFETCH
}

// ---------------- fused flash attention (64-row Q, single KV buffer) ----------
// Output: oh only (fp16) — proj GEMM is single-pass now.
__global__ void __launch_bounds__(128)
flash_kernel(const __half* __restrict__ qh, const __half* __restrict__ ql,
             const __half* __restrict__ kh, const __half* __restrict__ vh,
             __half* __restrict__ oh) {
    extern __shared__ char fsm[];
    uint32_t sb = smem_u32(fsm);
    int bh = blockIdx.y;
    int q0 = (gridDim.x - 1 - blockIdx.x) << 6;   // long CTAs first
    int tid = threadIdx.x, wid = tid >> 5, lane = tid & 31;

    {   // Q tile load (64 rows x 128B), hi+lo
        const char* srcH = (const char*)(qh + ((size_t)bh * S_ + q0) * DH_);
        const char* srcL = (const char*)(ql + ((size_t)bh * S_ + q0) * DH_);
        #pragma unroll
        for (int i = tid; i < 512; i += 128) {
            int r = i >> 3, c = (i & 7) << 4;
            CP16(sb + QOFF_H + r * FSTR + c, srcH + r * 128 + c);
            CP16(sb + QOFF_L + r * FSTR + c, srcL + r * 128 + c);
        }
        CP_COMMIT();
    }

    float m0 = -1e30f, m1 = -1e30f, l0 = 0.f, l1 = 0.f;
    float oacc[8][4];
    #pragma unroll
    for (int d = 0; d < 8; d++)
        oacc[d][0] = oacc[d][1] = oacc[d][2] = oacc[d][3] = 0.f;

    int rA = q0 + wid * 16 + (lane >> 2);
    int nj = (q0 >> 7) + 1;

    uint32_t aAddrBase = sb + (wid * 16 + (lane & 15)) * FSTR + (((lane >> 4) & 1) << 4);
    uint32_t bRowOff = (uint32_t)((lane & 7) * FSTR) + (((lane >> 3) & 1) << 4);

    for (int j = 0; j < nj; j++) {
        __syncthreads();
        {   // K/V tile load (128 rows x 128B)
            const char* kH = (const char*)(kh + ((size_t)bh * S_ + (j << 7)) * DH_);
            const char* vH = (const char*)(vh + ((size_t)bh * S_ + (j << 7)) * DH_);
            #pragma unroll
            for (int i = tid; i < 1024; i += 128) {
                int r = i >> 3, c = (i & 7) << 4;
                uint32_t so = r * FSTR + c;
                size_t go = (size_t)r * 128 + c;
                CP16(sb + KOFF + so, kH + go);
                CP16(sb + VOFF + so, vH + go);
            }
            CP_COMMIT();
            CP_WAIT(0);
        }
        __syncthreads();

        float sf[16][4];
        #pragma unroll
        for (int nt = 0; nt < 16; nt++)
            sf[nt][0] = sf[nt][1] = sf[nt][2] = sf[nt][3] = 0.f;

        #pragma unroll
        for (int kc = 0; kc < 4; kc++) {
            uint32_t qa = aAddrBase + kc * 32;
            uint32_t q_h0,q_h1,q_h2,q_h3, q_l0,q_l1,q_l2,q_l3;
            LDSM_X4(q_h0,q_h1,q_h2,q_h3, qa + QOFF_H);
            LDSM_X4(q_l0,q_l1,q_l2,q_l3, qa + QOFF_L);
            #pragma unroll
            for (int nt = 0; nt < 16; nt++) {
                uint32_t ka = sb + KOFF + nt * 8 * FSTR + bRowOff + kc * 32;
                uint32_t k_h0,k_h1;
                LDSM_X2(k_h0,k_h1, ka);
                MMA16816(sf[nt], q_h0,q_h1,q_h2,q_h3, k_h0,k_h1);
                MMA16816(sf[nt], q_l0,q_l1,q_l2,q_l3, k_h0,k_h1);
            }
        }

        int cb = (j << 7) + (lane & 3) * 2;
        float mx0 = -1e30f, mx1 = -1e30f;
        #pragma unroll
        for (int nt = 0; nt < 16; nt++) {
            int c0 = cb + nt * 8;
            sf[nt][0] = (c0     <= rA)     ? sf[nt][0] * 0.125f : -1e30f;
            sf[nt][1] = (c0 + 1 <= rA)     ? sf[nt][1] * 0.125f : -1e30f;
            sf[nt][2] = (c0     <= rA + 8) ? sf[nt][2] * 0.125f : -1e30f;
            sf[nt][3] = (c0 + 1 <= rA + 8) ? sf[nt][3] * 0.125f : -1e30f;
            mx0 = fmaxf(mx0, fmaxf(sf[nt][0], sf[nt][1]));
            mx1 = fmaxf(mx1, fmaxf(sf[nt][2], sf[nt][3]));
        }
        mx0 = fmaxf(mx0, __shfl_xor_sync(0xffffffffu, mx0, 1));
        mx0 = fmaxf(mx0, __shfl_xor_sync(0xffffffffu, mx0, 2));
        mx1 = fmaxf(mx1, __shfl_xor_sync(0xffffffffu, mx1, 1));
        mx1 = fmaxf(mx1, __shfl_xor_sync(0xffffffffu, mx1, 2));
        float mn0 = fmaxf(m0, mx0), mn1 = fmaxf(m1, mx1);
        float sc0 = expf(m0 - mn0), sc1 = expf(m1 - mn1);
        m0 = mn0; m1 = mn1;
        l0 *= sc0; l1 *= sc1;
        #pragma unroll
        for (int d = 0; d < 8; d++) {
            oacc[d][0] *= sc0; oacc[d][1] *= sc0;
            oacc[d][2] *= sc1; oacc[d][3] *= sc1;
        }
        float s0 = 0.f, s1 = 0.f;
        uint32_t ph[16][2], pl[16][2];
        #pragma unroll
        for (int nt = 0; nt < 16; nt++) {
            float p0 = expf(sf[nt][0] - m0), p1 = expf(sf[nt][1] - m0);
            float p2 = expf(sf[nt][2] - m1), p3 = expf(sf[nt][3] - m1);
            s0 += p0 + p1; s1 += p2 + p3;
            pack_split_h(p0, p1, ph[nt][0], pl[nt][0]);
            pack_split_h(p2, p3, ph[nt][1], pl[nt][1]);
        }
        s0 += __shfl_xor_sync(0xffffffffu, s0, 1);
        s0 += __shfl_xor_sync(0xffffffffu, s0, 2);
        s1 += __shfl_xor_sync(0xffffffffu, s1, 1);
        s1 += __shfl_xor_sync(0xffffffffu, s1, 2);
        l0 += s0; l1 += s1;

        #pragma unroll
        for (int kc = 0; kc < 8; kc++) {
            uint32_t va = sb + VOFF + (kc * 16 + (lane & 15)) * FSTR;
            #pragma unroll
            for (int dt = 0; dt < 8; dt++) {
                uint32_t v_h0,v_h1;
                LDSM_X2_T(v_h0,v_h1, va + dt * 16);
                MMA16816(oacc[dt], ph[2*kc][0], ph[2*kc][1], ph[2*kc+1][0], ph[2*kc+1][1], v_h0, v_h1);
                MMA16816(oacc[dt], pl[2*kc][0], pl[2*kc][1], pl[2*kc+1][0], pl[2*kc+1][1], v_h0, v_h1);
            }
        }
    }

    float inv0 = 1.f / l0, inv1 = 1.f / l1;
    int bb = bh / H_, hH = bh % H_;
    size_t baseA = ((size_t)bb * S_ + rA) * D_ + hH * DH_;
    size_t baseB = baseA + 8 * D_;
    #pragma unroll
    for (int dt = 0; dt < 8; dt++) {
        int c = dt * 8 + (lane & 3) * 2;
        *(uint32_t*)&oh[baseA + c] = pack2h(oacc[dt][0] * inv0, oacc[dt][1] * inv0);
        *(uint32_t*)&oh[baseB + c] = pack2h(oacc[dt][2] * inv1, oacc[dt][3] * inv1);
    }
}

// ---------------- host orchestration -----------------------------------------
extern "C" void kernel_launch(void* const* d_in, const int* in_sizes, int n_in,
                              void* d_out, int out_size) {
    const int*   ids    = (const int*)d_in[0];
    const int*   rfi    = (const int*)d_in[1];
    const float* wte    = (const float*)d_in[2];
    const float* wte_rf = (const float*)d_in[3];
    const float* wpe    = (const float*)d_in[4];
    const float* ln1_g  = (const float*)d_in[5];
    const float* ln1_b  = (const float*)d_in[6];
    const float* attn_w = (const float*)d_in[7];
    const float* attn_b = (const float*)d_in[8];
    const float* proj_w = (const float*)d_in[9];
    const float* proj_b = (const float*)d_in[10];
    const float* ln2_g  = (const float*)d_in[11];
    const float* ln2_b  = (const float*)d_in[12];
    const float* fc_w   = (const float*)d_in[13];
    const float* fc_b   = (const float*)d_in[14];
    const float* fc2_w  = (const float*)d_in[15];
    const float* fc2_b  = (const float*)d_in[16];
    const float* lnf_g  = (const float*)d_in[17];
    const float* lnf_b  = (const float*)d_in[18];
    float* out = (float*)d_out;

    float *h, *tp;
    __half *ah, *al, *mh, *oh;
    __half *qh, *ql, *kh, *vh;
    __half *tah, *tph, *tfh, *t2h;
    cudaGetSymbolAddress((void**)&h,   g_h);
    cudaGetSymbolAddress((void**)&tp,  g_t);
    cudaGetSymbolAddress((void**)&ah,  g_ah);  cudaGetSymbolAddress((void**)&al,  g_al);
    cudaGetSymbolAddress((void**)&mh,  g_mh);
    cudaGetSymbolAddress((void**)&oh,  g_oh);
    cudaGetSymbolAddress((void**)&qh,  g_qh);  cudaGetSymbolAddress((void**)&ql,  g_ql);
    cudaGetSymbolAddress((void**)&kh,  g_kh);  cudaGetSymbolAddress((void**)&vh,  g_vh);
    cudaGetSymbolAddress((void**)&tah, t_attn_h);
    cudaGetSymbolAddress((void**)&tph, t_proj_h);
    cudaGetSymbolAddress((void**)&tfh, t_fc_h);
    cudaGetSymbolAddress((void**)&t2h, t_fc2_h);

    cudaFuncSetAttribute((const void*)gemm_mma<2,2>, cudaFuncAttributeMaxDynamicSharedMemorySize, SMEM_GEMM);
    cudaFuncSetAttribute((const void*)gemm_mma<3,1>, cudaFuncAttributeMaxDynamicSharedMemorySize, SMEM_GEMM);
    cudaFuncSetAttribute((const void*)gemm_mma<4,1>, cudaFuncAttributeMaxDynamicSharedMemorySize, SMEM_GEMM);
    cudaFuncSetAttribute(flash_kernel, cudaFuncAttributeMaxDynamicSharedMemorySize, SMEM_FLASH);

    wsplit_all_kernel<<<TILES_PER_LAYER * L_, dim3(32, 8)>>>(
        attn_w, proj_w, fc_w, fc2_w, tah, tph, tfh, t2h);
    embed_ln_kernel<<<NT_/LNROWS, 256>>>(ids, rfi, wte, wte_rf, wpe, ln1_g, ln1_b, h, ah, al);

    for (int l = 0; l < L_; l++) {
        // QKV: single-pass (Ah*Bh)
        gemm_mma<3,1><<<dim3(D3_/128, NT_/128), 256, SMEM_GEMM>>>(
            ah, al, tah + (size_t)l * D3_ * D_,
            attn_b + l * D3_, nullptr, nullptr, nullptr, nullptr,
            qh, ql, kh, vh, NT_, D3_, D_, D_);
        flash_kernel<<<dim3(S_/64, B_*H_), 128, SMEM_FLASH>>>(qh, ql, kh, vh, oh);
        // proj: single-pass split-K=3 -> tmp partials
        gemm_mma<4,1><<<dim3(D_/128, NT_/128, SPLITK), 256, SMEM_GEMM>>>(
            oh, nullptr, tph + (size_t)l * D_ * D_,
            nullptr, nullptr, tp, nullptr, nullptr,
            nullptr, nullptr, nullptr, nullptr, NT_, D_, D_/SPLITK, D_);
        ln_sum_kernel<true><<<NT_/LNROWS, 256>>>(
            h, tp, proj_b + l * D_, ln2_g + l * D_, ln2_b + l * D_, h, nullptr, ah, al);
        // fc: 2-pass (Ah+Al), writes mh only
        gemm_mma<2,2><<<dim3(DF_/128, NT_/128), 256, SMEM_GEMM>>>(
            ah, al, tfh + (size_t)l * DF_ * D_,
            fc_b + l * DF_, nullptr, nullptr, mh, nullptr,
            nullptr, nullptr, nullptr, nullptr, NT_, DF_, D_, D_);
        // fc2: single-pass split-K=3 -> tmp partials
        gemm_mma<4,1><<<dim3(D_/128, NT_/128, SPLITK), 256, SMEM_GEMM>>>(
            mh, nullptr, t2h + (size_t)l * D_ * DF_,
            nullptr, nullptr, tp, nullptr, nullptr,
            nullptr, nullptr, nullptr, nullptr, NT_, D_, DF_/SPLITK, DF_);
        if (l < L_ - 1) {
            ln_sum_kernel<true><<<NT_/LNROWS, 256>>>(
                h, tp, fc2_b + l * D_, ln1_g + (l + 1) * D_, ln1_b + (l + 1) * D_,
                h, nullptr, ah, al);
        } else {
            ln_sum_kernel<false><<<NT_/LNROWS, 256>>>(
                h, tp, fc2_b + l * D_, lnf_g, lnf_b, nullptr, out, nullptr, nullptr);
        }
    }
}

// round 16
// speedup vs baseline: 1.6305x; 1.1509x over previous
#include <cuda_runtime.h>
#include <cuda_fp16.h>
#include <math.h>
#include <stdint.h>

#define B_  4
#define S_  1024
#define D_  768
#define H_  12
#define L_  6
#define DF_ 3072
#define DH_ 64
#define NT_ (B_*S_)        // 4096
#define D3_ (3*D_)         // 2304
#define SPLITK 3

// ---------------- scratch (static device globals) ----------------------------
static __device__ float g_h[NT_*D_];
static __device__ float g_t[(size_t)SPLITK*NT_*D_];     // split-K partials
static __device__ __half g_ah[NT_*D_];
static __device__ __half g_mh[NT_*DF_];
static __device__ __half g_oh[NT_*D_];
static __device__ __half g_qh[NT_*D_],  g_ql[NT_*D_];
static __device__ __half g_kh[NT_*D_];
static __device__ __half g_vh[NT_*D_];
static __device__ __half t_attn_h[(size_t)L_*D3_*D_];
static __device__ __half t_proj_h[(size_t)L_*D_*D_];
static __device__ __half t_fc_h[(size_t)L_*DF_*D_];
static __device__ __half t_fc2_h[(size_t)L_*D_*DF_];

// ---------------- helpers ----------------------------------------------------
__device__ __forceinline__ uint32_t smem_u32(const void* p) {
    uint32_t a;
    asm("{ .reg .u64 t; cvta.to.shared.u64 t, %1; cvt.u32.u64 %0, t; }" : "=r"(a) : "l"(p));
    return a;
}
__device__ __forceinline__ float gelu_f(float x) {
    const float c = 0.7978845608028654f;
    return 0.5f * x * (1.0f + tanhf(c * (x + 0.044715f * x * x * x)));
}
__device__ __forceinline__ void split_h(float v, __half& hi, __half& lo) {
    hi = __float2half_rn(v);
    lo = __float2half_rn(v - __half2float(hi));
}
__device__ __forceinline__ uint32_t pack2h(float x, float y) {
    __half2 p; p.x = __float2half_rn(x); p.y = __float2half_rn(y);
    return *(uint32_t*)&p;
}
__device__ __forceinline__ void pack_split_h(float x, float y, uint32_t& hp, uint32_t& lp) {
    __half hx, lx, hy, ly;
    split_h(x, hx, lx); split_h(y, hy, ly);
    __half2 h2; h2.x = hx; h2.y = hy;
    __half2 l2; l2.x = lx; l2.y = ly;
    hp = *(uint32_t*)&h2; lp = *(uint32_t*)&l2;
}
__device__ __forceinline__ float warp_sum(float v) {
    #pragma unroll
    for (int o = 16; o > 0; o >>= 1) v += __shfl_xor_sync(0xffffffffu, v, o);
    return v;
}

#define CP16(dst, src) \
    asm volatile("cp.async.cg.shared.global [%0], [%1], 16;" :: "r"(dst), "l"(src))
#define CP_COMMIT() asm volatile("cp.async.commit_group;")
#define CP_WAIT(n)  asm volatile("cp.async.wait_group %0;" :: "n"(n))

#define LDSM_X4(r0, r1, r2, r3, a) \
    asm volatile("ldmatrix.sync.aligned.m8n8.x4.shared.b16 {%0,%1,%2,%3}, [%4];" \
                 : "=r"(r0), "=r"(r1), "=r"(r2), "=r"(r3) : "r"(a))
#define LDSM_X2(r0, r1, a) \
    asm volatile("ldmatrix.sync.aligned.m8n8.x2.shared.b16 {%0,%1}, [%2];" \
                 : "=r"(r0), "=r"(r1) : "r"(a))
#define LDSM_X2_T(r0, r1, a) \
    asm volatile("ldmatrix.sync.aligned.m8n8.x2.trans.shared.b16 {%0,%1}, [%2];" \
                 : "=r"(r0), "=r"(r1) : "r"(a))
#define MMA16816(d, a0, a1, a2, a3, b0, b1) \
    asm volatile("mma.sync.aligned.m16n8k16.row.col.f32.f16.f16.f32 " \
                 "{%0,%1,%2,%3},{%4,%5,%6,%7},{%8,%9},{%0,%1,%2,%3};" \
                 : "+f"((d)[0]), "+f"((d)[1]), "+f"((d)[2]), "+f"((d)[3]) \
                 : "r"(a0), "r"(a1), "r"(a2), "r"(a3), "r"(b0), "r"(b1))

// gemm smem: 128 rows x 64 fp16 (128B) padded to 144B; up to 3 matrices/stage
#define TSTRIDE 144
#define MATBYTES 18432
#define STAGEBYTES 55296
#define SMEM_GEMM (2*STAGEBYTES)

// flash smem: rows of 64 fp16 (128B) padded to 144B
#define FSTR 144
#define QOFF_H 0
#define QOFF_L 9216
#define KOFF   18432
#define VOFF   36864
#define SMEM_FLASH 55296

// ---------------- fused weight transpose + fp16 convert ----------------------
#define TILES_PER_LAYER 6912
__global__ void wsplit_all_kernel(const float* __restrict__ attn_w, const float* __restrict__ proj_w,
                                  const float* __restrict__ fc_w,   const float* __restrict__ fc2_w,
                                  __half* __restrict__ tah, __half* __restrict__ tph,
                                  __half* __restrict__ tfh, __half* __restrict__ t2h) {
    __shared__ float t[32][33];
    int bid = blockIdx.x;
    int l = bid / TILES_PER_LAYER;
    int r = bid % TILES_PER_LAYER;
    const float* W; __half* Oh; int K, N, tile;
    if (r < 1728)      { W = attn_w; Oh = tah; K = D_;  N = D3_; tile = r; }
    else if (r < 2304) { W = proj_w; Oh = tph; K = D_;  N = D_;  tile = r - 1728; }
    else if (r < 4608) { W = fc_w;   Oh = tfh; K = D_;  N = DF_; tile = r - 2304; }
    else               { W = fc2_w;  Oh = t2h; K = DF_; N = D_;  tile = r - 4608; }
    int nx = N >> 5;
    int n0 = (tile % nx) << 5, k0 = (tile / nx) << 5;
    const float* Wl = W + (size_t)l * K * N;
    __half* OhL = Oh + (size_t)l * K * N;
    int tx = threadIdx.x, ty = threadIdx.y;    // (32,8)
    for (int i = ty; i < 32; i += 8)
        t[i][tx] = Wl[(size_t)(k0 + i) * N + n0 + tx];
    __syncthreads();
    for (int i = ty; i < 32; i += 8)
        OhL[(size_t)(n0 + i) * K + k0 + tx] = __float2half_rn(t[tx][i]);
}

// ---------------- warp-per-row layernorms (hi-only output) --------------------
#define LNROWS 8
__global__ void embed_ln_kernel(const int* __restrict__ ids, const int* __restrict__ rfi,
                                const float* __restrict__ wte, const float* __restrict__ wte_rf,
                                const float* __restrict__ wpe,
                                const float* __restrict__ g, const float* __restrict__ b,
                                float* __restrict__ h,
                                __half* __restrict__ yh) {
    int w = threadIdx.x >> 5, lane = threadIdx.x & 31;
    int row = blockIdx.x * LNROWS + w;
    int s = row & (S_ - 1);
    const float* e1 = wte    + (size_t)ids[row] * D_;
    const float* e2 = wte_rf + (size_t)rfi[row] * D_;
    const float* e3 = wpe    + (size_t)s * D_;
    float* hr = h + (size_t)row * D_;
    float v[24];
    float sum = 0.f;
    #pragma unroll
    for (int i = 0; i < 24; i++) {
        int c = lane + (i << 5);
        float x = e1[c] + e2[c] + e3[c];
        hr[c] = x;
        v[i] = x; sum += x;
    }
    sum = warp_sum(sum);
    float mu = sum * (1.0f / D_);
    float q = 0.f;
    #pragma unroll
    for (int i = 0; i < 24; i++) { v[i] -= mu; q += v[i] * v[i]; }
    q = warp_sum(q);
    float inv = rsqrtf(q * (1.0f / D_) + 1e-5f);
    size_t base = (size_t)row * D_;
    #pragma unroll
    for (int i = 0; i < 24; i++) {
        int c = lane + (i << 5);
        yh[base + c] = __float2half_rn(v[i] * inv * g[c] + b[c]);
    }
}

// ln_sum: v = x + t0 + t1 + t2 + gbias; optionally write h; LN(v) -> yh or y.
template<bool HF>
__global__ void ln_sum_kernel(const float* __restrict__ x, const float* __restrict__ t,
                              const float* __restrict__ gb,
                              const float* __restrict__ g, const float* __restrict__ b,
                              float* __restrict__ hout, float* __restrict__ y,
                              __half* __restrict__ yh) {
    int w = threadIdx.x >> 5, lane = threadIdx.x & 31;
    int row = blockIdx.x * LNROWS + w;
    size_t base = (size_t)row * D_;
    const float* t0 = t + base;
    const float* t1 = t + (size_t)NT_ * D_ + base;
    const float* t2 = t + (size_t)2 * NT_ * D_ + base;
    const float* xr = x + base;
    float v[24];
    float sum = 0.f;
    #pragma unroll
    for (int i = 0; i < 24; i++) {
        int c = lane + (i << 5);
        float val = xr[c] + t0[c] + t1[c] + t2[c] + gb[c];
        if (hout) hout[base + c] = val;
        v[i] = val; sum += val;
    }
    sum = warp_sum(sum);
    float mu = sum * (1.0f / D_);
    float q = 0.f;
    #pragma unroll
    for (int i = 0; i < 24; i++) { v[i] -= mu; q += v[i] * v[i]; }
    q = warp_sum(q);
    float inv = rsqrtf(q * (1.0f / D_) + 1e-5f);
    #pragma unroll
    for (int i = 0; i < 24; i++) {
        int c = lane + (i << 5);
        float r = v[i] * inv * g[c] + b[c];
        if (HF) yh[base + c] = __float2half_rn(r);
        else    y[base + c] = r;
    }
}

// ---------------- mma.sync GEMM (fp16 single-pass, K-chunk 64) -----------------
// acc = Ah*Bh.  EPI 2: Ch = fp16(gelu(acc+bias)).  EPI 3: head-major QKV.
// EPI 4: split-K partial: Cf[z] = raw acc, z = blockIdx.z.
template<int EPI>
__global__ void __launch_bounds__(256, 2)
gemm_mma(const __half* __restrict__ Ah, const __half* __restrict__ Bh,
         const float* __restrict__ bias,
         float* __restrict__ Cf, __half* __restrict__ Ch,
         __half* __restrict__ Qh_, __half* __restrict__ Ql_,
         __half* __restrict__ Kh_, __half* __restrict__ Vh_,
         int M, int N, int K, int Ktot) {
    extern __shared__ char smem[];
    uint32_t sbase = smem_u32(smem);
    int tid = threadIdx.x;
    int wid = tid >> 5, lane = tid & 31;
    int wm = wid >> 2, wn = wid & 3;
    int m0 = blockIdx.y << 7, n0 = blockIdx.x << 7;
    int ldb = Ktot * 2;
    int kz = (EPI == 4) ? blockIdx.z : 0;
    size_t koff0 = (size_t)kz * K;
    if (EPI == 4) Cf += (size_t)kz * ((size_t)M * N);

    const char* srcA = (const char*)(Ah + (size_t)m0 * Ktot + koff0);
    const char* srcB = (const char*)(Bh + (size_t)n0 * Ktot + koff0);

    float acc[4][4][4] = {};
    int nk = K >> 6;

#define PREFETCH(c, s)                                                        \
    {                                                                         \
        size_t ko = (size_t)(c) << 7;                                         \
        uint32_t stb = sbase + (s) * STAGEBYTES;                              \
        _Pragma("unroll")                                                     \
        for (int j = 0; j < 8; j++) {                                         \
            int q = tid + j * 256;                                            \
            int mat = q >> 10, w = q & 1023, row = w >> 3, cc = w & 7;        \
            const char* sp = (mat == 0 ? srcA : srcB) + (size_t)row * ldb + ko + cc * 16; \
            uint32_t dst = stb + (mat == 0 ? 0 : 2 * MATBYTES) + row * TSTRIDE + cc * 16; \
            CP16(dst, sp);                                                    \
        }                                                                     \
        CP_COMMIT();                                                          \
    }

    PREFETCH(0, 0);

    int aRow = wm * 64 + (lane & 7) + ((lane >> 3) & 1) * 8;
    uint32_t aKoff = ((lane >> 4) & 1) * 16;
    int lb = lane & 15;
    int bRow = wn * 32 + (lb & 7);
    uint32_t bKoff = ((lb >> 3) & 1) * 16;

    for (int c = 0; c < nk; c++) {
        int s = c & 1;
        if (c + 1 < nk) PREFETCH(c + 1, s ^ 1);
        if (c + 1 < nk) { CP_WAIT(1); } else { CP_WAIT(0); }
        __syncthreads();

        uint32_t stb = sbase + s * STAGEBYTES;
        #pragma unroll
        for (int kk = 0; kk < 4; kk++) {
            uint32_t bh[4][2];
            #pragma unroll
            for (int nj = 0; nj < 4; nj++) {
                uint32_t addr = stb + 2 * MATBYTES + (bRow + nj * 8) * TSTRIDE + kk * 32 + bKoff;
                LDSM_X2(bh[nj][0], bh[nj][1], addr);
            }
            uint32_t af[4][4];
            #pragma unroll
            for (int mi = 0; mi < 4; mi++) {
                uint32_t addr = stb + (aRow + mi * 16) * TSTRIDE + kk * 32 + aKoff;
                LDSM_X4(af[mi][0], af[mi][1], af[mi][2], af[mi][3], addr);
            }
            #pragma unroll
            for (int mi = 0; mi < 4; mi++)
                #pragma unroll
                for (int nj = 0; nj < 4; nj++)
                    MMA16816(acc[mi][nj], af[mi][0], af[mi][1], af[mi][2], af[mi][3],
                             bh[nj][0], bh[nj][1]);
        }
        __syncthreads();
    }

    int rbase = m0 + wm * 64 + (lane >> 2);
    int cbase = n0 + wn * 32 + (lane & 3) * 2;
    #pragma unroll
    for (int mi = 0; mi < 4; mi++) {
        #pragma unroll
        for (int nj = 0; nj < 4; nj++) {
            int r = rbase + mi * 16;
            int col = cbase + nj * 8;
            float b0 = (EPI == 4) ? 0.f : bias[col];
            float b1 = (EPI == 4) ? 0.f : bias[col + 1];
            float v00 = acc[mi][nj][0] + b0, v01 = acc[mi][nj][1] + b1;
            float v10 = acc[mi][nj][2] + b0, v11 = acc[mi][nj][3] + b1;
            size_t i0 = (size_t)r * N + col;
            size_t i1 = (size_t)(r + 8) * N + col;
            if (EPI == 4) {
                *(float2*)&Cf[i0] = make_float2(v00, v01);
                *(float2*)&Cf[i1] = make_float2(v10, v11);
            } else if (EPI == 2) {
                v00 = gelu_f(v00); v01 = gelu_f(v01);
                v10 = gelu_f(v10); v11 = gelu_f(v11);
                *(uint32_t*)&Ch[i0] = pack2h(v00, v01);
                *(uint32_t*)&Ch[i1] = pack2h(v10, v11);
            } else {
                int which = col / D_;
                int hh = (col % D_) / DH_;
                int dd = col % DH_;
                int bi = r >> 10, si = r & 1023;
                size_t j0 = (((size_t)(bi * H_ + hh)) * S_ + si) * DH_ + dd;
                size_t j1 = j0 + 8 * DH_;
                if (which == 0) {
                    uint32_t hp, lp;
                    pack_split_h(v00, v01, hp, lp);
                    *(uint32_t*)&Qh_[j0] = hp; *(uint32_t*)&Ql_[j0] = lp;
                    pack_split_h(v10, v11, hp, lp);
                    *(uint32_t*)&Qh_[j1] = hp; *(uint32_t*)&Ql_[j1] = lp;
                } else {
                    __half* d_ = which == 1 ? Kh_ : Vh_;
                    *(uint32_t*)&d_[j0] = pack2h(v00, v01);
                    *(uint32_t*)&d_[j1] = pack2h(v10, v11);
                }
            }
        }
    }
#undef PREFETCH
}

// ---------------- fused flash attention (64-row Q, single KV buffer) ----------
__global__ void __launch_bounds__(128)
flash_kernel(const __half* __restrict__ qh, const __half* __restrict__ ql,
             const __half* __restrict__ kh, const __half* __restrict__ vh,
             __half* __restrict__ oh) {
    extern __shared__ char fsm[];
    uint32_t sb = smem_u32(fsm);
    int bh = blockIdx.y;
    int q0 = (gridDim.x - 1 - blockIdx.x) << 6;   // long CTAs first
    int tid = threadIdx.x, wid = tid >> 5, lane = tid & 31;

    {   // Q tile load (64 rows x 128B), hi+lo
        const char* srcH = (const char*)(qh + ((size_t)bh * S_ + q0) * DH_);
        const char* srcL = (const char*)(ql + ((size_t)bh * S_ + q0) * DH_);
        #pragma unroll
        for (int i = tid; i < 512; i += 128) {
            int r = i >> 3, c = (i & 7) << 4;
            CP16(sb + QOFF_H + r * FSTR + c, srcH + r * 128 + c);
            CP16(sb + QOFF_L + r * FSTR + c, srcL + r * 128 + c);
        }
        CP_COMMIT();
    }

    float m0 = -1e30f, m1 = -1e30f, l0 = 0.f, l1 = 0.f;
    float oacc[8][4];
    #pragma unroll
    for (int d = 0; d < 8; d++)
        oacc[d][0] = oacc[d][1] = oacc[d][2] = oacc[d][3] = 0.f;

    int rA = q0 + wid * 16 + (lane >> 2);
    int nj = (q0 >> 7) + 1;

    uint32_t aAddrBase = sb + (wid * 16 + (lane & 15)) * FSTR + (((lane >> 4) & 1) << 4);
    uint32_t bRowOff = (uint32_t)((lane & 7) * FSTR) + (((lane >> 3) & 1) << 4);

    for (int j = 0; j < nj; j++) {
        __syncthreads();
        {   // K/V tile load (128 rows x 128B)
            const char* kH = (const char*)(kh + ((size_t)bh * S_ + (j << 7)) * DH_);
            const char* vH = (const char*)(vh + ((size_t)bh * S_ + (j << 7)) * DH_);
            #pragma unroll
            for (int i = tid; i < 1024; i += 128) {
                int r = i >> 3, c = (i & 7) << 4;
                uint32_t so = r * FSTR + c;
                size_t go = (size_t)r * 128 + c;
                CP16(sb + KOFF + so, kH + go);
                CP16(sb + VOFF + so, vH + go);
            }
            CP_COMMIT();
            CP_WAIT(0);
        }
        __syncthreads();

        float sf[16][4];
        #pragma unroll
        for (int nt = 0; nt < 16; nt++)
            sf[nt][0] = sf[nt][1] = sf[nt][2] = sf[nt][3] = 0.f;

        #pragma unroll
        for (int kc = 0; kc < 4; kc++) {
            uint32_t qa = aAddrBase + kc * 32;
            uint32_t q_h0,q_h1,q_h2,q_h3, q_l0,q_l1,q_l2,q_l3;
            LDSM_X4(q_h0,q_h1,q_h2,q_h3, qa + QOFF_H);
            LDSM_X4(q_l0,q_l1,q_l2,q_l3, qa + QOFF_L);
            #pragma unroll
            for (int nt = 0; nt < 16; nt++) {
                uint32_t ka = sb + KOFF + nt * 8 * FSTR + bRowOff + kc * 32;
                uint32_t k_h0,k_h1;
                LDSM_X2(k_h0,k_h1, ka);
                MMA16816(sf[nt], q_h0,q_h1,q_h2,q_h3, k_h0,k_h1);
                MMA16816(sf[nt], q_l0,q_l1,q_l2,q_l3, k_h0,k_h1);
            }
        }

        int cb = (j << 7) + (lane & 3) * 2;
        float mx0 = -1e30f, mx1 = -1e30f;
        #pragma unroll
        for (int nt = 0; nt < 16; nt++) {
            int c0 = cb + nt * 8;
            sf[nt][0] = (c0     <= rA)     ? sf[nt][0] * 0.125f : -1e30f;
            sf[nt][1] = (c0 + 1 <= rA)     ? sf[nt][1] * 0.125f : -1e30f;
            sf[nt][2] = (c0     <= rA + 8) ? sf[nt][2] * 0.125f : -1e30f;
            sf[nt][3] = (c0 + 1 <= rA + 8) ? sf[nt][3] * 0.125f : -1e30f;
            mx0 = fmaxf(mx0, fmaxf(sf[nt][0], sf[nt][1]));
            mx1 = fmaxf(mx1, fmaxf(sf[nt][2], sf[nt][3]));
        }
        mx0 = fmaxf(mx0, __shfl_xor_sync(0xffffffffu, mx0, 1));
        mx0 = fmaxf(mx0, __shfl_xor_sync(0xffffffffu, mx0, 2));
        mx1 = fmaxf(mx1, __shfl_xor_sync(0xffffffffu, mx1, 1));
        mx1 = fmaxf(mx1, __shfl_xor_sync(0xffffffffu, mx1, 2));
        float mn0 = fmaxf(m0, mx0), mn1 = fmaxf(m1, mx1);
        float sc0 = expf(m0 - mn0), sc1 = expf(m1 - mn1);
        m0 = mn0; m1 = mn1;
        l0 *= sc0; l1 *= sc1;
        #pragma unroll
        for (int d = 0; d < 8; d++) {
            oacc[d][0] *= sc0; oacc[d][1] *= sc0;
            oacc[d][2] *= sc1; oacc[d][3] *= sc1;
        }
        float s0 = 0.f, s1 = 0.f;
        uint32_t ph[16][2], pl[16][2];
        #pragma unroll
        for (int nt = 0; nt < 16; nt++) {
            float p0 = expf(sf[nt][0] - m0), p1 = expf(sf[nt][1] - m0);
            float p2 = expf(sf[nt][2] - m1), p3 = expf(sf[nt][3] - m1);
            s0 += p0 + p1; s1 += p2 + p3;
            pack_split_h(p0, p1, ph[nt][0], pl[nt][0]);
            pack_split_h(p2, p3, ph[nt][1], pl[nt][1]);
        }
        s0 += __shfl_xor_sync(0xffffffffu, s0, 1);
        s0 += __shfl_xor_sync(0xffffffffu, s0, 2);
        s1 += __shfl_xor_sync(0xffffffffu, s1, 1);
        s1 += __shfl_xor_sync(0xffffffffu, s1, 2);
        l0 += s0; l1 += s1;

        #pragma unroll
        for (int kc = 0; kc < 8; kc++) {
            uint32_t va = sb + VOFF + (kc * 16 + (lane & 15)) * FSTR;
            #pragma unroll
            for (int dt = 0; dt < 8; dt++) {
                uint32_t v_h0,v_h1;
                LDSM_X2_T(v_h0,v_h1, va + dt * 16);
                MMA16816(oacc[dt], ph[2*kc][0], ph[2*kc][1], ph[2*kc+1][0], ph[2*kc+1][1], v_h0, v_h1);
                MMA16816(oacc[dt], pl[2*kc][0], pl[2*kc][1], pl[2*kc+1][0], pl[2*kc+1][1], v_h0, v_h1);
            }
        }
    }

    float inv0 = 1.f / l0, inv1 = 1.f / l1;
    int bb = bh / H_, hH = bh % H_;
    size_t baseA = ((size_t)bb * S_ + rA) * D_ + hH * DH_;
    size_t baseB = baseA + 8 * D_;
    #pragma unroll
    for (int dt = 0; dt < 8; dt++) {
        int c = dt * 8 + (lane & 3) * 2;
        *(uint32_t*)&oh[baseA + c] = pack2h(oacc[dt][0] * inv0, oacc[dt][1] * inv0);
        *(uint32_t*)&oh[baseB + c] = pack2h(oacc[dt][2] * inv1, oacc[dt][3] * inv1);
    }
}

// ---------------- host orchestration -----------------------------------------
extern "C" void kernel_launch(void* const* d_in, const int* in_sizes, int n_in,
                              void* d_out, int out_size) {
    const int*   ids    = (const int*)d_in[0];
    const int*   rfi    = (const int*)d_in[1];
    const float* wte    = (const float*)d_in[2];
    const float* wte_rf = (const float*)d_in[3];
    const float* wpe    = (const float*)d_in[4];
    const float* ln1_g  = (const float*)d_in[5];
    const float* ln1_b  = (const float*)d_in[6];
    const float* attn_w = (const float*)d_in[7];
    const float* attn_b = (const float*)d_in[8];
    const float* proj_w = (const float*)d_in[9];
    const float* proj_b = (const float*)d_in[10];
    const float* ln2_g  = (const float*)d_in[11];
    const float* ln2_b  = (const float*)d_in[12];
    const float* fc_w   = (const float*)d_in[13];
    const float* fc_b   = (const float*)d_in[14];
    const float* fc2_w  = (const float*)d_in[15];
    const float* fc2_b  = (const float*)d_in[16];
    const float* lnf_g  = (const float*)d_in[17];
    const float* lnf_b  = (const float*)d_in[18];
    float* out = (float*)d_out;

    float *h, *tp;
    __half *ah, *mh, *oh;
    __half *qh, *ql, *kh, *vh;
    __half *tah, *tph, *tfh, *t2h;
    cudaGetSymbolAddress((void**)&h,   g_h);
    cudaGetSymbolAddress((void**)&tp,  g_t);
    cudaGetSymbolAddress((void**)&ah,  g_ah);
    cudaGetSymbolAddress((void**)&mh,  g_mh);
    cudaGetSymbolAddress((void**)&oh,  g_oh);
    cudaGetSymbolAddress((void**)&qh,  g_qh);  cudaGetSymbolAddress((void**)&ql,  g_ql);
    cudaGetSymbolAddress((void**)&kh,  g_kh);  cudaGetSymbolAddress((void**)&vh,  g_vh);
    cudaGetSymbolAddress((void**)&tah, t_attn_h);
    cudaGetSymbolAddress((void**)&tph, t_proj_h);
    cudaGetSymbolAddress((void**)&tfh, t_fc_h);
    cudaGetSymbolAddress((void**)&t2h, t_fc2_h);

    cudaFuncSetAttribute((const void*)gemm_mma<2>, cudaFuncAttributeMaxDynamicSharedMemorySize, SMEM_GEMM);
    cudaFuncSetAttribute((const void*)gemm_mma<3>, cudaFuncAttributeMaxDynamicSharedMemorySize, SMEM_GEMM);
    cudaFuncSetAttribute((const void*)gemm_mma<4>, cudaFuncAttributeMaxDynamicSharedMemorySize, SMEM_GEMM);
    cudaFuncSetAttribute(flash_kernel, cudaFuncAttributeMaxDynamicSharedMemorySize, SMEM_FLASH);

    wsplit_all_kernel<<<TILES_PER_LAYER * L_, dim3(32, 8)>>>(
        attn_w, proj_w, fc_w, fc2_w, tah, tph, tfh, t2h);
    embed_ln_kernel<<<NT_/LNROWS, 256>>>(ids, rfi, wte, wte_rf, wpe, ln1_g, ln1_b, h, ah);

    for (int l = 0; l < L_; l++) {
        // QKV: single-pass
        gemm_mma<3><<<dim3(D3_/128, NT_/128), 256, SMEM_GEMM>>>(
            ah, tah + (size_t)l * D3_ * D_,
            attn_b + l * D3_, nullptr, nullptr,
            qh, ql, kh, vh, NT_, D3_, D_, D_);
        flash_kernel<<<dim3(S_/64, B_*H_), 128, SMEM_FLASH>>>(qh, ql, kh, vh, oh);
        // proj: single-pass split-K=3 -> tmp partials
        gemm_mma<4><<<dim3(D_/128, NT_/128, SPLITK), 256, SMEM_GEMM>>>(
            oh, tph + (size_t)l * D_ * D_,
            nullptr, tp, nullptr,
            nullptr, nullptr, nullptr, nullptr, NT_, D_, D_/SPLITK, D_);
        ln_sum_kernel<true><<<NT_/LNROWS, 256>>>(
            h, tp, proj_b + l * D_, ln2_g + l * D_, ln2_b + l * D_, h, nullptr, ah);
        // fc: single-pass, writes mh
        gemm_mma<2><<<dim3(DF_/128, NT_/128), 256, SMEM_GEMM>>>(
            ah, tfh + (size_t)l * DF_ * D_,
            fc_b + l * DF_, nullptr, mh,
            nullptr, nullptr, nullptr, nullptr, NT_, DF_, D_, D_);
        // fc2: single-pass split-K=3 -> tmp partials
        gemm_mma<4><<<dim3(D_/128, NT_/128, SPLITK), 256, SMEM_GEMM>>>(
            mh, t2h + (size_t)l * D_ * DF_,
            nullptr, tp, nullptr,
            nullptr, nullptr, nullptr, nullptr, NT_, D_, DF_/SPLITK, DF_);
        if (l < L_ - 1) {
            ln_sum_kernel<true><<<NT_/LNROWS, 256>>>(
                h, tp, fc2_b + l * D_, ln1_g + (l + 1) * D_, ln1_b + (l + 1) * D_,
                h, nullptr, ah);
        } else {
            ln_sum_kernel<false><<<NT_/LNROWS, 256>>>(
                h, tp, fc2_b + l * D_, lnf_g, lnf_b, nullptr, out, nullptr);
        }
    }
}

// round 17
// speedup vs baseline: 1.7499x; 1.0732x over previous
#include <cuda_runtime.h>
#include <cuda_fp16.h>
#include <math.h>
#include <stdint.h>

#define B_  4
#define S_  1024
#define D_  768
#define H_  12
#define L_  6
#define DF_ 3072
#define DH_ 64
#define NT_ (B_*S_)        // 4096
#define D3_ (3*D_)         // 2304
#define SPLITK 3

// ---------------- scratch (static device globals) ----------------------------
static __device__ float g_h[NT_*D_];
static __device__ float g_t[(size_t)SPLITK*NT_*D_];     // split-K partials
static __device__ __half g_ah[NT_*D_];
static __device__ __half g_mh[NT_*DF_];
static __device__ __half g_oh[NT_*D_];
static __device__ __half g_qh[NT_*D_];
static __device__ __half g_kh[NT_*D_];
static __device__ __half g_vh[NT_*D_];
static __device__ __half t_attn_h[(size_t)L_*D3_*D_];
static __device__ __half t_proj_h[(size_t)L_*D_*D_];
static __device__ __half t_fc_h[(size_t)L_*DF_*D_];
static __device__ __half t_fc2_h[(size_t)L_*D_*DF_];

// ---------------- helpers ----------------------------------------------------
__device__ __forceinline__ uint32_t smem_u32(const void* p) {
    uint32_t a;
    asm("{ .reg .u64 t; cvta.to.shared.u64 t, %1; cvt.u32.u64 %0, t; }" : "=r"(a) : "l"(p));
    return a;
}
__device__ __forceinline__ float gelu_f(float x) {
    const float c = 0.7978845608028654f;
    return 0.5f * x * (1.0f + tanhf(c * (x + 0.044715f * x * x * x)));
}
__device__ __forceinline__ uint32_t pack2h(float x, float y) {
    __half2 p; p.x = __float2half_rn(x); p.y = __float2half_rn(y);
    return *(uint32_t*)&p;
}
__device__ __forceinline__ float warp_sum(float v) {
    #pragma unroll
    for (int o = 16; o > 0; o >>= 1) v += __shfl_xor_sync(0xffffffffu, v, o);
    return v;
}

#define CP16(dst, src) \
    asm volatile("cp.async.cg.shared.global [%0], [%1], 16;" :: "r"(dst), "l"(src))
#define CP_COMMIT() asm volatile("cp.async.commit_group;")
#define CP_WAIT(n)  asm volatile("cp.async.wait_group %0;" :: "n"(n))

#define LDSM_X4(r0, r1, r2, r3, a) \
    asm volatile("ldmatrix.sync.aligned.m8n8.x4.shared.b16 {%0,%1,%2,%3}, [%4];" \
                 : "=r"(r0), "=r"(r1), "=r"(r2), "=r"(r3) : "r"(a))
#define LDSM_X2(r0, r1, a) \
    asm volatile("ldmatrix.sync.aligned.m8n8.x2.shared.b16 {%0,%1}, [%2];" \
                 : "=r"(r0), "=r"(r1) : "r"(a))
#define LDSM_X2_T(r0, r1, a) \
    asm volatile("ldmatrix.sync.aligned.m8n8.x2.trans.shared.b16 {%0,%1}, [%2];" \
                 : "=r"(r0), "=r"(r1) : "r"(a))
#define MMA16816(d, a0, a1, a2, a3, b0, b1) \
    asm volatile("mma.sync.aligned.m16n8k16.row.col.f32.f16.f16.f32 " \
                 "{%0,%1,%2,%3},{%4,%5,%6,%7},{%8,%9},{%0,%1,%2,%3};" \
                 : "+f"((d)[0]), "+f"((d)[1]), "+f"((d)[2]), "+f"((d)[3]) \
                 : "r"(a0), "r"(a1), "r"(a2), "r"(a3), "r"(b0), "r"(b1))

// gemm smem: 128 rows x 64 fp16 (128B) padded to 144B; 2 matrices per stage
#define TSTRIDE 144
#define MATBYTES 18432
#define STAGEBYTES 36864
#define SMEM_GEMM (2*STAGEBYTES)

// flash smem: Q(64 rows) + K,V(128 rows), 144B stride
#define FSTR 144
#define QOFF 0
#define KOFF 9216
#define VOFF 27648
#define SMEM_FLASH 46080

// ---------------- fused weight transpose + fp16 convert ----------------------
#define TILES_PER_LAYER 6912
__global__ void wsplit_all_kernel(const float* __restrict__ attn_w, const float* __restrict__ proj_w,
                                  const float* __restrict__ fc_w,   const float* __restrict__ fc2_w,
                                  __half* __restrict__ tah, __half* __restrict__ tph,
                                  __half* __restrict__ tfh, __half* __restrict__ t2h) {
    __shared__ float t[32][33];
    int bid = blockIdx.x;
    int l = bid / TILES_PER_LAYER;
    int r = bid % TILES_PER_LAYER;
    const float* W; __half* Oh; int K, N, tile;
    if (r < 1728)      { W = attn_w; Oh = tah; K = D_;  N = D3_; tile = r; }
    else if (r < 2304) { W = proj_w; Oh = tph; K = D_;  N = D_;  tile = r - 1728; }
    else if (r < 4608) { W = fc_w;   Oh = tfh; K = D_;  N = DF_; tile = r - 2304; }
    else               { W = fc2_w;  Oh = t2h; K = DF_; N = D_;  tile = r - 4608; }
    int nx = N >> 5;
    int n0 = (tile % nx) << 5, k0 = (tile / nx) << 5;
    const float* Wl = W + (size_t)l * K * N;
    __half* OhL = Oh + (size_t)l * K * N;
    int tx = threadIdx.x, ty = threadIdx.y;    // (32,8)
    for (int i = ty; i < 32; i += 8)
        t[i][tx] = Wl[(size_t)(k0 + i) * N + n0 + tx];
    __syncthreads();
    for (int i = ty; i < 32; i += 8)
        OhL[(size_t)(n0 + i) * K + k0 + tx] = __float2half_rn(t[tx][i]);
}

// ---------------- warp-per-row layernorms (hi-only output) --------------------
#define LNROWS 8
__global__ void embed_ln_kernel(const int* __restrict__ ids, const int* __restrict__ rfi,
                                const float* __restrict__ wte, const float* __restrict__ wte_rf,
                                const float* __restrict__ wpe,
                                const float* __restrict__ g, const float* __restrict__ b,
                                float* __restrict__ h,
                                __half* __restrict__ yh) {
    int w = threadIdx.x >> 5, lane = threadIdx.x & 31;
    int row = blockIdx.x * LNROWS + w;
    int s = row & (S_ - 1);
    const float* e1 = wte    + (size_t)ids[row] * D_;
    const float* e2 = wte_rf + (size_t)rfi[row] * D_;
    const float* e3 = wpe    + (size_t)s * D_;
    float* hr = h + (size_t)row * D_;
    float v[24];
    float sum = 0.f;
    #pragma unroll
    for (int i = 0; i < 24; i++) {
        int c = lane + (i << 5);
        float x = e1[c] + e2[c] + e3[c];
        hr[c] = x;
        v[i] = x; sum += x;
    }
    sum = warp_sum(sum);
    float mu = sum * (1.0f / D_);
    float q = 0.f;
    #pragma unroll
    for (int i = 0; i < 24; i++) { v[i] -= mu; q += v[i] * v[i]; }
    q = warp_sum(q);
    float inv = rsqrtf(q * (1.0f / D_) + 1e-5f);
    size_t base = (size_t)row * D_;
    #pragma unroll
    for (int i = 0; i < 24; i++) {
        int c = lane + (i << 5);
        yh[base + c] = __float2half_rn(v[i] * inv * g[c] + b[c]);
    }
}

// ln_sum: v = x + t0 + t1 + t2 + gbias; optionally write h; LN(v) -> yh or y.
template<bool HF>
__global__ void ln_sum_kernel(const float* __restrict__ x, const float* __restrict__ t,
                              const float* __restrict__ gb,
                              const float* __restrict__ g, const float* __restrict__ b,
                              float* __restrict__ hout, float* __restrict__ y,
                              __half* __restrict__ yh) {
    int w = threadIdx.x >> 5, lane = threadIdx.x & 31;
    int row = blockIdx.x * LNROWS + w;
    size_t base = (size_t)row * D_;
    const float* t0 = t + base;
    const float* t1 = t + (size_t)NT_ * D_ + base;
    const float* t2 = t + (size_t)2 * NT_ * D_ + base;
    const float* xr = x + base;
    float v[24];
    float sum = 0.f;
    #pragma unroll
    for (int i = 0; i < 24; i++) {
        int c = lane + (i << 5);
        float val = xr[c] + t0[c] + t1[c] + t2[c] + gb[c];
        if (hout) hout[base + c] = val;
        v[i] = val; sum += val;
    }
    sum = warp_sum(sum);
    float mu = sum * (1.0f / D_);
    float q = 0.f;
    #pragma unroll
    for (int i = 0; i < 24; i++) { v[i] -= mu; q += v[i] * v[i]; }
    q = warp_sum(q);
    float inv = rsqrtf(q * (1.0f / D_) + 1e-5f);
    #pragma unroll
    for (int i = 0; i < 24; i++) {
        int c = lane + (i << 5);
        float r = v[i] * inv * g[c] + b[c];
        if (HF) yh[base + c] = __float2half_rn(r);
        else    y[base + c] = r;
    }
}

// ---------------- mma.sync GEMM (fp16 single-pass, K-chunk 64) -----------------
// acc = Ah*Bh.  EPI 2: Ch = fp16(gelu(acc+bias)).  EPI 3: head-major QKV (fp16).
// EPI 4: split-K partial: Cf[z] = raw acc, z = blockIdx.z.
template<int EPI>
__global__ void __launch_bounds__(256, 2)
gemm_mma(const __half* __restrict__ Ah, const __half* __restrict__ Bh,
         const float* __restrict__ bias,
         float* __restrict__ Cf, __half* __restrict__ Ch,
         __half* __restrict__ Qh_, __half* __restrict__ Kh_, __half* __restrict__ Vh_,
         int M, int N, int K, int Ktot) {
    extern __shared__ char smem[];
    uint32_t sbase = smem_u32(smem);
    int tid = threadIdx.x;
    int wid = tid >> 5, lane = tid & 31;
    int wm = wid >> 2, wn = wid & 3;
    int m0 = blockIdx.y << 7, n0 = blockIdx.x << 7;
    int ldb = Ktot * 2;
    int kz = (EPI == 4) ? blockIdx.z : 0;
    size_t koff0 = (size_t)kz * K;
    if (EPI == 4) Cf += (size_t)kz * ((size_t)M * N);

    const char* srcA = (const char*)(Ah + (size_t)m0 * Ktot + koff0);
    const char* srcB = (const char*)(Bh + (size_t)n0 * Ktot + koff0);

    float acc[4][4][4] = {};
    int nk = K >> 6;

#define PREFETCH(c, s)                                                        \
    {                                                                         \
        size_t ko = (size_t)(c) << 7;                                         \
        uint32_t stb = sbase + (s) * STAGEBYTES;                              \
        _Pragma("unroll")                                                     \
        for (int j = 0; j < 8; j++) {                                         \
            int q = tid + j * 256;                                            \
            int mat = q >> 10, w = q & 1023, row = w >> 3, cc = w & 7;        \
            const char* sp = (mat == 0 ? srcA : srcB) + (size_t)row * ldb + ko + cc * 16; \
            uint32_t dst = stb + (mat == 0 ? 0 : MATBYTES) + row * TSTRIDE + cc * 16; \
            CP16(dst, sp);                                                    \
        }                                                                     \
        CP_COMMIT();                                                          \
    }

    PREFETCH(0, 0);

    int aRow = wm * 64 + (lane & 7) + ((lane >> 3) & 1) * 8;
    uint32_t aKoff = ((lane >> 4) & 1) * 16;
    int lb = lane & 15;
    int bRow = wn * 32 + (lb & 7);
    uint32_t bKoff = ((lb >> 3) & 1) * 16;

    for (int c = 0; c < nk; c++) {
        int s = c & 1;
        if (c + 1 < nk) PREFETCH(c + 1, s ^ 1);
        if (c + 1 < nk) { CP_WAIT(1); } else { CP_WAIT(0); }
        __syncthreads();

        uint32_t stb = sbase + s * STAGEBYTES;
        #pragma unroll
        for (int kk = 0; kk < 4; kk++) {
            uint32_t bh[4][2];
            #pragma unroll
            for (int nj = 0; nj < 4; nj++) {
                uint32_t addr = stb + MATBYTES + (bRow + nj * 8) * TSTRIDE + kk * 32 + bKoff;
                LDSM_X2(bh[nj][0], bh[nj][1], addr);
            }
            uint32_t af[4][4];
            #pragma unroll
            for (int mi = 0; mi < 4; mi++) {
                uint32_t addr = stb + (aRow + mi * 16) * TSTRIDE + kk * 32 + aKoff;
                LDSM_X4(af[mi][0], af[mi][1], af[mi][2], af[mi][3], addr);
            }
            #pragma unroll
            for (int mi = 0; mi < 4; mi++)
                #pragma unroll
                for (int nj = 0; nj < 4; nj++)
                    MMA16816(acc[mi][nj], af[mi][0], af[mi][1], af[mi][2], af[mi][3],
                             bh[nj][0], bh[nj][1]);
        }
        __syncthreads();
    }

    int rbase = m0 + wm * 64 + (lane >> 2);
    int cbase = n0 + wn * 32 + (lane & 3) * 2;
    #pragma unroll
    for (int mi = 0; mi < 4; mi++) {
        #pragma unroll
        for (int nj = 0; nj < 4; nj++) {
            int r = rbase + mi * 16;
            int col = cbase + nj * 8;
            float b0 = (EPI == 4) ? 0.f : bias[col];
            float b1 = (EPI == 4) ? 0.f : bias[col + 1];
            float v00 = acc[mi][nj][0] + b0, v01 = acc[mi][nj][1] + b1;
            float v10 = acc[mi][nj][2] + b0, v11 = acc[mi][nj][3] + b1;
            size_t i0 = (size_t)r * N + col;
            size_t i1 = (size_t)(r + 8) * N + col;
            if (EPI == 4) {
                *(float2*)&Cf[i0] = make_float2(v00, v01);
                *(float2*)&Cf[i1] = make_float2(v10, v11);
            } else if (EPI == 2) {
                v00 = gelu_f(v00); v01 = gelu_f(v01);
                v10 = gelu_f(v10); v11 = gelu_f(v11);
                *(uint32_t*)&Ch[i0] = pack2h(v00, v01);
                *(uint32_t*)&Ch[i1] = pack2h(v10, v11);
            } else {
                int which = col / D_;
                int hh = (col % D_) / DH_;
                int dd = col % DH_;
                int bi = r >> 10, si = r & 1023;
                size_t j0 = (((size_t)(bi * H_ + hh)) * S_ + si) * DH_ + dd;
                size_t j1 = j0 + 8 * DH_;
                __half* d_ = which == 0 ? Qh_ : (which == 1 ? Kh_ : Vh_);
                *(uint32_t*)&d_[j0] = pack2h(v00, v01);
                *(uint32_t*)&d_[j1] = pack2h(v10, v11);
            }
        }
    }
#undef PREFETCH
}

// ---------------- fused flash attention (64-row Q fp16, single KV buffer) -----
__global__ void __launch_bounds__(128)
flash_kernel(const __half* __restrict__ qh, const __half* __restrict__ kh,
             const __half* __restrict__ vh, __half* __restrict__ oh) {
    extern __shared__ char fsm[];
    uint32_t sb = smem_u32(fsm);
    int bh = blockIdx.y;
    int q0 = (gridDim.x - 1 - blockIdx.x) << 6;   // long CTAs first
    int tid = threadIdx.x, wid = tid >> 5, lane = tid & 31;

    {   // Q tile load (64 rows x 128B)
        const char* srcH = (const char*)(qh + ((size_t)bh * S_ + q0) * DH_);
        #pragma unroll
        for (int i = tid; i < 512; i += 128) {
            int r = i >> 3, c = (i & 7) << 4;
            CP16(sb + QOFF + r * FSTR + c, srcH + r * 128 + c);
        }
        CP_COMMIT();
    }

    float m0 = -1e30f, m1 = -1e30f, l0 = 0.f, l1 = 0.f;
    float oacc[8][4];
    #pragma unroll
    for (int d = 0; d < 8; d++)
        oacc[d][0] = oacc[d][1] = oacc[d][2] = oacc[d][3] = 0.f;

    int rA = q0 + wid * 16 + (lane >> 2);
    int nj = (q0 >> 7) + 1;

    uint32_t aAddrBase = sb + QOFF + (wid * 16 + (lane & 15)) * FSTR + (((lane >> 4) & 1) << 4);
    uint32_t bRowOff = (uint32_t)((lane & 7) * FSTR) + (((lane >> 3) & 1) << 4);

    for (int j = 0; j < nj; j++) {
        __syncthreads();
        {   // K/V tile load (128 rows x 128B)
            const char* kH = (const char*)(kh + ((size_t)bh * S_ + (j << 7)) * DH_);
            const char* vH = (const char*)(vh + ((size_t)bh * S_ + (j << 7)) * DH_);
            #pragma unroll
            for (int i = tid; i < 1024; i += 128) {
                int r = i >> 3, c = (i & 7) << 4;
                uint32_t so = r * FSTR + c;
                size_t go = (size_t)r * 128 + c;
                CP16(sb + KOFF + so, kH + go);
                CP16(sb + VOFF + so, vH + go);
            }
            CP_COMMIT();
            CP_WAIT(0);
        }
        __syncthreads();

        float sf[16][4];
        #pragma unroll
        for (int nt = 0; nt < 16; nt++)
            sf[nt][0] = sf[nt][1] = sf[nt][2] = sf[nt][3] = 0.f;

        #pragma unroll
        for (int kc = 0; kc < 4; kc++) {
            uint32_t qa = aAddrBase + kc * 32;
            uint32_t q_h0,q_h1,q_h2,q_h3;
            LDSM_X4(q_h0,q_h1,q_h2,q_h3, qa);
            #pragma unroll
            for (int nt = 0; nt < 16; nt++) {
                uint32_t ka = sb + KOFF + nt * 8 * FSTR + bRowOff + kc * 32;
                uint32_t k_h0,k_h1;
                LDSM_X2(k_h0,k_h1, ka);
                MMA16816(sf[nt], q_h0,q_h1,q_h2,q_h3, k_h0,k_h1);
            }
        }

        int cb = (j << 7) + (lane & 3) * 2;
        float mx0 = -1e30f, mx1 = -1e30f;
        #pragma unroll
        for (int nt = 0; nt < 16; nt++) {
            int c0 = cb + nt * 8;
            sf[nt][0] = (c0     <= rA)     ? sf[nt][0] * 0.125f : -1e30f;
            sf[nt][1] = (c0 + 1 <= rA)     ? sf[nt][1] * 0.125f : -1e30f;
            sf[nt][2] = (c0     <= rA + 8) ? sf[nt][2] * 0.125f : -1e30f;
            sf[nt][3] = (c0 + 1 <= rA + 8) ? sf[nt][3] * 0.125f : -1e30f;
            mx0 = fmaxf(mx0, fmaxf(sf[nt][0], sf[nt][1]));
            mx1 = fmaxf(mx1, fmaxf(sf[nt][2], sf[nt][3]));
        }
        mx0 = fmaxf(mx0, __shfl_xor_sync(0xffffffffu, mx0, 1));
        mx0 = fmaxf(mx0, __shfl_xor_sync(0xffffffffu, mx0, 2));
        mx1 = fmaxf(mx1, __shfl_xor_sync(0xffffffffu, mx1, 1));
        mx1 = fmaxf(mx1, __shfl_xor_sync(0xffffffffu, mx1, 2));
        float mn0 = fmaxf(m0, mx0), mn1 = fmaxf(m1, mx1);
        float sc0 = expf(m0 - mn0), sc1 = expf(m1 - mn1);
        m0 = mn0; m1 = mn1;
        l0 *= sc0; l1 *= sc1;
        #pragma unroll
        for (int d = 0; d < 8; d++) {
            oacc[d][0] *= sc0; oacc[d][1] *= sc0;
            oacc[d][2] *= sc1; oacc[d][3] *= sc1;
        }
        float s0 = 0.f, s1 = 0.f;
        uint32_t ph[16][2];
        #pragma unroll
        for (int nt = 0; nt < 16; nt++) {
            float p0 = expf(sf[nt][0] - m0), p1 = expf(sf[nt][1] - m0);
            float p2 = expf(sf[nt][2] - m1), p3 = expf(sf[nt][3] - m1);
            s0 += p0 + p1; s1 += p2 + p3;
            ph[nt][0] = pack2h(p0, p1);
            ph[nt][1] = pack2h(p2, p3);
        }
        s0 += __shfl_xor_sync(0xffffffffu, s0, 1);
        s0 += __shfl_xor_sync(0xffffffffu, s0, 2);
        s1 += __shfl_xor_sync(0xffffffffu, s1, 1);
        s1 += __shfl_xor_sync(0xffffffffu, s1, 2);
        l0 += s0; l1 += s1;

        #pragma unroll
        for (int kc = 0; kc < 8; kc++) {
            uint32_t va = sb + VOFF + (kc * 16 + (lane & 15)) * FSTR;
            #pragma unroll
            for (int dt = 0; dt < 8; dt++) {
                uint32_t v_h0,v_h1;
                LDSM_X2_T(v_h0,v_h1, va + dt * 16);
                MMA16816(oacc[dt], ph[2*kc][0], ph[2*kc][1], ph[2*kc+1][0], ph[2*kc+1][1], v_h0, v_h1);
            }
        }
    }

    float inv0 = 1.f / l0, inv1 = 1.f / l1;
    int bb = bh / H_, hH = bh % H_;
    size_t baseA = ((size_t)bb * S_ + rA) * D_ + hH * DH_;
    size_t baseB = baseA + 8 * D_;
    #pragma unroll
    for (int dt = 0; dt < 8; dt++) {
        int c = dt * 8 + (lane & 3) * 2;
        *(uint32_t*)&oh[baseA + c] = pack2h(oacc[dt][0] * inv0, oacc[dt][1] * inv0);
        *(uint32_t*)&oh[baseB + c] = pack2h(oacc[dt][2] * inv1, oacc[dt][3] * inv1);
    }
}

// ---------------- host orchestration -----------------------------------------
extern "C" void kernel_launch(void* const* d_in, const int* in_sizes, int n_in,
                              void* d_out, int out_size) {
    const int*   ids    = (const int*)d_in[0];
    const int*   rfi    = (const int*)d_in[1];
    const float* wte    = (const float*)d_in[2];
    const float* wte_rf = (const float*)d_in[3];
    const float* wpe    = (const float*)d_in[4];
    const float* ln1_g  = (const float*)d_in[5];
    const float* ln1_b  = (const float*)d_in[6];
    const float* attn_w = (const float*)d_in[7];
    const float* attn_b = (const float*)d_in[8];
    const float* proj_w = (const float*)d_in[9];
    const float* proj_b = (const float*)d_in[10];
    const float* ln2_g  = (const float*)d_in[11];
    const float* ln2_b  = (const float*)d_in[12];
    const float* fc_w   = (const float*)d_in[13];
    const float* fc_b   = (const float*)d_in[14];
    const float* fc2_w  = (const float*)d_in[15];
    const float* fc2_b  = (const float*)d_in[16];
    const float* lnf_g  = (const float*)d_in[17];
    const float* lnf_b  = (const float*)d_in[18];
    float* out = (float*)d_out;

    float *h, *tp;
    __half *ah, *mh, *oh;
    __half *qh, *kh, *vh;
    __half *tah, *tph, *tfh, *t2h;
    cudaGetSymbolAddress((void**)&h,   g_h);
    cudaGetSymbolAddress((void**)&tp,  g_t);
    cudaGetSymbolAddress((void**)&ah,  g_ah);
    cudaGetSymbolAddress((void**)&mh,  g_mh);
    cudaGetSymbolAddress((void**)&oh,  g_oh);
    cudaGetSymbolAddress((void**)&qh,  g_qh);
    cudaGetSymbolAddress((void**)&kh,  g_kh);
    cudaGetSymbolAddress((void**)&vh,  g_vh);
    cudaGetSymbolAddress((void**)&tah, t_attn_h);
    cudaGetSymbolAddress((void**)&tph, t_proj_h);
    cudaGetSymbolAddress((void**)&tfh, t_fc_h);
    cudaGetSymbolAddress((void**)&t2h, t_fc2_h);

    cudaFuncSetAttribute((const void*)gemm_mma<2>, cudaFuncAttributeMaxDynamicSharedMemorySize, SMEM_GEMM);
    cudaFuncSetAttribute((const void*)gemm_mma<3>, cudaFuncAttributeMaxDynamicSharedMemorySize, SMEM_GEMM);
    cudaFuncSetAttribute((const void*)gemm_mma<4>, cudaFuncAttributeMaxDynamicSharedMemorySize, SMEM_GEMM);
    cudaFuncSetAttribute(flash_kernel, cudaFuncAttributeMaxDynamicSharedMemorySize, SMEM_FLASH);

    wsplit_all_kernel<<<TILES_PER_LAYER * L_, dim3(32, 8)>>>(
        attn_w, proj_w, fc_w, fc2_w, tah, tph, tfh, t2h);
    embed_ln_kernel<<<NT_/LNROWS, 256>>>(ids, rfi, wte, wte_rf, wpe, ln1_g, ln1_b, h, ah);

    for (int l = 0; l < L_; l++) {
        gemm_mma<3><<<dim3(D3_/128, NT_/128), 256, SMEM_GEMM>>>(
            ah, tah + (size_t)l * D3_ * D_,
            attn_b + l * D3_, nullptr, nullptr,
            qh, kh, vh, NT_, D3_, D_, D_);
        flash_kernel<<<dim3(S_/64, B_*H_), 128, SMEM_FLASH>>>(qh, kh, vh, oh);
        gemm_mma<4><<<dim3(D_/128, NT_/128, SPLITK), 256, SMEM_GEMM>>>(
            oh, tph + (size_t)l * D_ * D_,
            nullptr, tp, nullptr,
            nullptr, nullptr, nullptr, NT_, D_, D_/SPLITK, D_);
        ln_sum_kernel<true><<<NT_/LNROWS, 256>>>(
            h, tp, proj_b + l * D_, ln2_g + l * D_, ln2_b + l * D_, h, nullptr, ah);
        gemm_mma<2><<<dim3(DF_/128, NT_/128), 256, SMEM_GEMM>>>(
            ah, tfh + (size_t)l * DF_ * D_,
            fc_b + l * DF_, nullptr, mh,
            nullptr, nullptr, nullptr, NT_, DF_, D_, D_);
        gemm_mma<4><<<dim3(D_/128, NT_/128, SPLITK), 256, SMEM_GEMM>>>(
            mh, t2h + (size_t)l * D_ * DF_,
            nullptr, tp, nullptr,
            nullptr, nullptr, nullptr, NT_, D_, DF_/SPLITK, DF_);
        if (l < L_ - 1) {
            ln_sum_kernel<true><<<NT_/LNROWS, 256>>>(
                h, tp, fc2_b + l * D_, ln1_g + (l + 1) * D_, ln1_b + (l + 1) * D_,
                h, nullptr, ah);
        } else {
            ln_sum_kernel<false><<<NT_/LNROWS, 256>>>(
                h, tp, fc2_b + l * D_, lnf_g, lnf_b, nullptr, out, nullptr);
        }
    }
}